// round 1
// baseline (speedup 1.0000x reference)
#include <cuda_runtime.h>
#include <math.h>

#define D_  1024
#define H_  16
#define DH_ 64
#define P_  16
#define C_  512
#define B_  4
#define S_  4096
#define FF_ 4096
#define NC_ 8
#define BC_ (B_*C_)      /* 2048 */
#define PC_ (P_+C_)      /* 528  */
#define BH_ (B_*H_)      /* 64   */

// ------------------------- scratch (device globals) -------------------------
__device__ float g_h1[BC_*D_];
__device__ float g_qm[BC_*D_];
__device__ float g_km[BC_*D_];
__device__ float g_vm[BC_*D_];
__device__ float g_mc[BC_*D_];          // mem_ctx
__device__ float g_pr[BC_*D_];          // pred, then pred - vm
__device__ float g_grad[B_*D_*D_];
__device__ float g_Mst[B_*D_*D_];       // memory matrix M
__device__ float g_Sst[B_*D_*D_];       // momentum S
__device__ float g_h2[BC_*D_];
__device__ float g_qh[BC_*D_];
__device__ float g_kh[BC_*D_];
__device__ float g_vh[BC_*D_];
__device__ float g_sc[BH_*C_*PC_];      // attention scores / probs
__device__ float g_at[BC_*D_];          // attention output (pre-Wo)
__device__ float g_ao[BC_*D_];
__device__ float g_gt[BC_*D_];          // gate
__device__ float g_o [BC_*D_];
__device__ float g_h3[BC_*D_];
__device__ float g_f1[BC_*FF_];
__device__ float g_f2[BC_*FF_];

// ------------------------- generic SGEMM 128x128x8 --------------------------
// C[M,N] = epilogue(alpha * op(A)[M,K] @ B[K,N])
// TA=false: A is MxK row-major (lda = K). TA=true: A physically KxM (lda = M-ish, passed).
// EPI: 0 = alpha*acc ; 1 = acc+bias ; 2 = sigmoid(acc+bias) ; 3 = C += acc + bias
template<int EPI, bool TA>
__global__ __launch_bounds__(256) void sgemm_k(
    const float* __restrict__ A, const float* __restrict__ Bm,
    float* __restrict__ Cm, const float* __restrict__ bias,
    int M, int N, int K, int lda,
    long sA, long sB, long sC, float alpha)
{
    int bz = blockIdx.z;
    A  += (long)bz * sA;
    Bm += (long)bz * sB;
    Cm += (long)bz * sC;

    __shared__ float As[8][128];
    __shared__ float Bs[8][128];

    int tid = threadIdx.x;
    int n0 = blockIdx.x * 128, m0 = blockIdx.y * 128;
    int ty = tid >> 4, tx = tid & 15;
    int mb = ty * 8, nb = tx * 8;

    float acc[8][8];
#pragma unroll
    for (int i = 0; i < 8; i++)
#pragma unroll
        for (int j = 0; j < 8; j++) acc[i][j] = 0.f;

    for (int k0 = 0; k0 < K; k0 += 8) {
        if (TA) {
            int k = tid >> 5, m4 = (tid & 31) << 2;
            float4 v = *(const float4*)&A[(long)(k0 + k) * lda + m0 + m4];
            *(float4*)&As[k][m4] = v;
        } else {
            int m = tid >> 1, kq = (tid & 1) << 2;
            float4 v = *(const float4*)&A[(long)(m0 + m) * lda + k0 + kq];
            As[kq + 0][m] = v.x; As[kq + 1][m] = v.y;
            As[kq + 2][m] = v.z; As[kq + 3][m] = v.w;
        }
        {
            int k = tid >> 5, n4 = (tid & 31) << 2;
            float4 v = *(const float4*)&Bm[(long)(k0 + k) * N + n0 + n4];
            *(float4*)&Bs[k][n4] = v;
        }
        __syncthreads();
#pragma unroll
        for (int k = 0; k < 8; k++) {
            float a[8], b[8];
#pragma unroll
            for (int i = 0; i < 8; i++) a[i] = As[k][mb + i];
#pragma unroll
            for (int j = 0; j < 8; j++) b[j] = Bs[k][nb + j];
#pragma unroll
            for (int i = 0; i < 8; i++)
#pragma unroll
                for (int j = 0; j < 8; j++)
                    acc[i][j] = fmaf(a[i], b[j], acc[i][j]);
        }
        __syncthreads();
    }

#pragma unroll
    for (int i = 0; i < 8; i++) {
        int r = m0 + mb + i;
        float* crow = &Cm[(long)r * N + n0 + nb];
#pragma unroll
        for (int j = 0; j < 8; j++) {
            float v = acc[i][j] * alpha;
            int c = n0 + nb + j;
            if (EPI == 1)      v = v + bias[c];
            else if (EPI == 2) v = 1.f / (1.f + expf(-(v + bias[c])));
            else if (EPI == 3) v = v + bias[c] + crow[j];
            crow[j] = v;
        }
    }
}

// ------------------------------- LayerNorm ----------------------------------
// MODE 0: src rows mapped from x chunk; MODE 1: x chunk + residual; MODE 2: direct rows
template<int MODE>
__global__ __launch_bounds__(256) void ln_k(
    const float* __restrict__ src, const float* __restrict__ res,
    const float* __restrict__ gam, const float* __restrict__ bet,
    float* __restrict__ out, int c0)
{
    int r = blockIdx.x;
    const float* p;
    if (MODE == 2) p = src + (long)r * D_;
    else { int b = r / C_, i = r % C_; p = src + ((long)b * S_ + c0 + i) * D_; }

    int tid = threadIdx.x;
    float v[4], s = 0.f, sq = 0.f;
#pragma unroll
    for (int k = 0; k < 4; k++) {
        int c = tid + k * 256;
        float xv = p[c];
        if (MODE == 1) xv += res[(long)r * D_ + c];
        v[k] = xv; s += xv; sq += xv * xv;
    }
    __shared__ float shs[8], shq[8];
#pragma unroll
    for (int o = 16; o; o >>= 1) {
        s  += __shfl_xor_sync(0xffffffffu, s,  o);
        sq += __shfl_xor_sync(0xffffffffu, sq, o);
    }
    if ((tid & 31) == 0) { shs[tid >> 5] = s; shq[tid >> 5] = sq; }
    __syncthreads();
    s = 0.f; sq = 0.f;
#pragma unroll
    for (int i = 0; i < 8; i++) { s += shs[i]; sq += shq[i]; }
    float m  = s * (1.f / D_);
    float var = sq * (1.f / D_) - m * m;
    float rs = rsqrtf(var + 1e-5f);
#pragma unroll
    for (int k = 0; k < 4; k++) {
        int c = tid + k * 256;
        out[(long)r * D_ + c] = (v[k] - m) * rs * gam[c] + bet[c];
    }
}

// row L2 normalize: km *= rsqrt(sum(km^2)+1e-6)
__global__ __launch_bounds__(256) void rownorm_k(float* __restrict__ km)
{
    int r = blockIdx.x, tid = threadIdx.x;
    float* p = km + (long)r * D_;
    float v[4], sq = 0.f;
#pragma unroll
    for (int k = 0; k < 4; k++) { int c = tid + k * 256; v[k] = p[c]; sq += v[k] * v[k]; }
    __shared__ float shq[8];
#pragma unroll
    for (int o = 16; o; o >>= 1) sq += __shfl_xor_sync(0xffffffffu, sq, o);
    if ((tid & 31) == 0) shq[tid >> 5] = sq;
    __syncthreads();
    sq = 0.f;
#pragma unroll
    for (int i = 0; i < 8; i++) sq += shq[i];
    float rs = rsqrtf(sq + 1e-6f);
#pragma unroll
    for (int k = 0; k < 4; k++) { int c = tid + k * 256; p[c] = v[k] * rs; }
}

// -------------------------------- attention ---------------------------------
// scores[bh, i, j] = 0.125 * q . k + mask ; grid (9 jtiles, 8 itiles, BH)
__global__ __launch_bounds__(256) void attn_scores_k(
    const float* __restrict__ qh, const float* __restrict__ kh,
    const float* __restrict__ pk, float* __restrict__ sc)
{
    int bh = blockIdx.z; int b = bh >> 4, h = bh & 15;
    int i0 = blockIdx.y * 64, j0 = blockIdx.x * 64;
    __shared__ float Qs[64][16];
    __shared__ float Ks[64][16];
    int tid = threadIdx.x;
    int ty = tid >> 4, tx = tid & 15;
    float acc[4][4] = {};
    for (int k0 = 0; k0 < DH_; k0 += 16) {
        for (int t = tid; t < 1024; t += 256) {
            int r = t >> 4, c = t & 15;
            Qs[r][c] = qh[(((long)b * C_ + i0 + r) * H_ + h) * DH_ + k0 + c];
            int j = j0 + r;
            float kv = 0.f;
            if (j < PC_) {
                kv = (j < P_) ? pk[((long)j * H_ + h) * DH_ + k0 + c]
                              : kh[(((long)b * C_ + (j - P_)) * H_ + h) * DH_ + k0 + c];
            }
            Ks[r][c] = kv;
        }
        __syncthreads();
#pragma unroll
        for (int kk = 0; kk < 16; kk++) {
            float qr[4], kr[4];
#pragma unroll
            for (int i = 0; i < 4; i++) qr[i] = Qs[ty * 4 + i][kk];
#pragma unroll
            for (int j = 0; j < 4; j++) kr[j] = Ks[tx * 4 + j][kk];
#pragma unroll
            for (int i = 0; i < 4; i++)
#pragma unroll
                for (int j = 0; j < 4; j++) acc[i][j] += qr[i] * kr[j];
        }
        __syncthreads();
    }
#pragma unroll
    for (int i = 0; i < 4; i++) {
        int gi = i0 + ty * 4 + i;
#pragma unroll
        for (int j = 0; j < 4; j++) {
            int gj = j0 + tx * 4 + j;
            if (gj < PC_) {
                float m = (gj < P_ || (gj - P_) <= gi) ? 0.f : -1e9f;
                sc[((long)bh * C_ + gi) * PC_ + gj] = acc[i][j] * 0.125f + m;
            }
        }
    }
}

__global__ __launch_bounds__(256) void softmax_k(float* __restrict__ sc)
{
    float* row = sc + (long)blockIdx.x * PC_;
    int tid = threadIdx.x;
    __shared__ float sh[8];
    float mx = -1e30f;
    for (int c = tid; c < PC_; c += 256) mx = fmaxf(mx, row[c]);
#pragma unroll
    for (int o = 16; o; o >>= 1) mx = fmaxf(mx, __shfl_xor_sync(0xffffffffu, mx, o));
    if ((tid & 31) == 0) sh[tid >> 5] = mx;
    __syncthreads();
    mx = sh[0];
#pragma unroll
    for (int i = 1; i < 8; i++) mx = fmaxf(mx, sh[i]);
    float s = 0.f;
    for (int c = tid; c < PC_; c += 256) { float e = expf(row[c] - mx); row[c] = e; s += e; }
    __syncthreads();
#pragma unroll
    for (int o = 16; o; o >>= 1) s += __shfl_xor_sync(0xffffffffu, s, o);
    if ((tid & 31) == 0) sh[tid >> 5] = s;
    __syncthreads();
    s = 0.f;
#pragma unroll
    for (int i = 0; i < 8; i++) s += sh[i];
    float inv = 1.f / s;
    for (int c = tid; c < PC_; c += 256) row[c] *= inv;
}

// out[b,i,h,:] = probs @ V ; grid (8 itiles, BH)
__global__ __launch_bounds__(256) void attn_av_k(
    const float* __restrict__ sc, const float* __restrict__ vh,
    const float* __restrict__ pv, float* __restrict__ outp)
{
    int bh = blockIdx.y; int b = bh >> 4, h = bh & 15;
    int i0 = blockIdx.x * 64;
    __shared__ float As[64][16];
    __shared__ float Vs[16][64];
    int tid = threadIdx.x;
    int ty = tid >> 4, tx = tid & 15;
    float acc[4][4] = {};
    for (int k0 = 0; k0 < PC_; k0 += 16) {
        for (int t = tid; t < 1024; t += 256) {
            int r = t >> 4, c = t & 15;
            As[r][c] = sc[((long)bh * C_ + i0 + r) * PC_ + k0 + c];
        }
        for (int t = tid; t < 1024; t += 256) {
            int kk = t >> 6, d = t & 63;
            int j = k0 + kk;
            Vs[kk][d] = (j < P_) ? pv[((long)j * H_ + h) * DH_ + d]
                                 : vh[(((long)b * C_ + (j - P_)) * H_ + h) * DH_ + d];
        }
        __syncthreads();
#pragma unroll
        for (int kk = 0; kk < 16; kk++) {
            float ar[4], vr[4];
#pragma unroll
            for (int i = 0; i < 4; i++) ar[i] = As[ty * 4 + i][kk];
#pragma unroll
            for (int j = 0; j < 4; j++) vr[j] = Vs[kk][tx * 4 + j];
#pragma unroll
            for (int i = 0; i < 4; i++)
#pragma unroll
                for (int j = 0; j < 4; j++) acc[i][j] += ar[i] * vr[j];
        }
        __syncthreads();
    }
#pragma unroll
    for (int i = 0; i < 4; i++) {
        int gi = i0 + ty * 4 + i;
#pragma unroll
        for (int j = 0; j < 4; j++) {
            outp[((long)b * C_ + gi) * D_ + h * DH_ + tx * 4 + j] = acc[i][j];
        }
    }
}

// ------------------------------- elementwise --------------------------------
__global__ void zero2_k(float* __restrict__ a, float* __restrict__ b)
{
    long i = (long)blockIdx.x * 256 + threadIdx.x;
    a[i] = 0.f; b[i] = 0.f;
}

__global__ void sub_k(float* __restrict__ p, const float* __restrict__ v)
{
    long i = (long)blockIdx.x * 256 + threadIdx.x;
    p[i] -= v[i];
}

__global__ void update_k(float* __restrict__ M, float* __restrict__ S,
                         const float* __restrict__ grad,
                         const float* __restrict__ lr,
                         const float* __restrict__ mom,
                         const float* __restrict__ fg)
{
    long i = (long)blockIdx.x * 256 + threadIdx.x;
    float th = 1.f / (1.f + expf(-lr[0]));
    float et = 1.f / (1.f + expf(-mom[0]));
    float al = 1.f / (1.f + expf(-fg[0]));
    float s = et * S[i] - th * grad[i];
    S[i] = s;
    M[i] = (1.f - al) * M[i] + s;
}

__global__ void combine_k(const float* __restrict__ x, const float* __restrict__ gt,
                          const float* __restrict__ ao, const float* __restrict__ mc,
                          float* __restrict__ o, int c0)
{
    long idx = (long)blockIdx.x * 256 + threadIdx.x;
    int r = (int)(idx / D_), c = (int)(idx % D_);
    int b = r / C_, i = r % C_;
    float xv = x[((long)b * S_ + c0 + i) * D_ + c];
    float gv = gt[idx];
    o[idx] = xv + gv * ao[idx] + (1.f - gv) * mc[idx];
}

__global__ void silu_mul_k(float* __restrict__ f1, const float* __restrict__ f2)
{
    long i = (long)blockIdx.x * 256 + threadIdx.x;
    float v = f1[i];
    f1[i] = v / (1.f + expf(-v)) * f2[i];
}

__global__ void scatter_k(const float* __restrict__ o, float* __restrict__ outp, int c0)
{
    long idx = (long)blockIdx.x * 256 + threadIdx.x;
    int r = (int)(idx / D_), c = (int)(idx % D_);
    int b = r / C_, i = r % C_;
    outp[((long)b * S_ + c0 + i) * D_ + c] = o[idx];
}

// --------------------------------- launch -----------------------------------
extern "C" void kernel_launch(void* const* d_in, const int* in_sizes, int n_in,
                              void* d_out, int out_size)
{
    const float* x     = (const float*)d_in[0];
    const float* g1    = (const float*)d_in[1];
    const float* b1    = (const float*)d_in[2];
    const float* g2    = (const float*)d_in[3];
    const float* b2    = (const float*)d_in[4];
    const float* g3    = (const float*)d_in[5];
    const float* b3    = (const float*)d_in[6];
    const float* Wqm   = (const float*)d_in[7];
    const float* Wkm   = (const float*)d_in[8];
    const float* Wvm   = (const float*)d_in[9];
    const float* lr    = (const float*)d_in[10];
    const float* mom   = (const float*)d_in[11];
    const float* fg    = (const float*)d_in[12];
    const float* Wq    = (const float*)d_in[13];
    const float* bq    = (const float*)d_in[14];
    const float* Wk    = (const float*)d_in[15];
    const float* bk    = (const float*)d_in[16];
    const float* Wv    = (const float*)d_in[17];
    const float* bv    = (const float*)d_in[18];
    const float* Wo    = (const float*)d_in[19];
    const float* bo    = (const float*)d_in[20];
    const float* pk    = (const float*)d_in[21];
    const float* pv    = (const float*)d_in[22];
    const float* Wg    = (const float*)d_in[23];
    const float* bg    = (const float*)d_in[24];
    const float* Wgate = (const float*)d_in[25];
    const float* bgate = (const float*)d_in[26];
    const float* Wup   = (const float*)d_in[27];
    const float* bup   = (const float*)d_in[28];
    const float* Wdown = (const float*)d_in[29];
    const float* bdown = (const float*)d_in[30];
    float* outp = (float*)d_out;

    float *h1, *qm, *km, *vm, *mc, *pr, *grad, *Mm, *Sm, *h2, *qh, *kh, *vh;
    float *sc, *at, *ao, *gt, *o, *h3, *f1, *f2;
    cudaGetSymbolAddress((void**)&h1, g_h1);
    cudaGetSymbolAddress((void**)&qm, g_qm);
    cudaGetSymbolAddress((void**)&km, g_km);
    cudaGetSymbolAddress((void**)&vm, g_vm);
    cudaGetSymbolAddress((void**)&mc, g_mc);
    cudaGetSymbolAddress((void**)&pr, g_pr);
    cudaGetSymbolAddress((void**)&grad, g_grad);
    cudaGetSymbolAddress((void**)&Mm, g_Mst);
    cudaGetSymbolAddress((void**)&Sm, g_Sst);
    cudaGetSymbolAddress((void**)&h2, g_h2);
    cudaGetSymbolAddress((void**)&qh, g_qh);
    cudaGetSymbolAddress((void**)&kh, g_kh);
    cudaGetSymbolAddress((void**)&vh, g_vh);
    cudaGetSymbolAddress((void**)&sc, g_sc);
    cudaGetSymbolAddress((void**)&at, g_at);
    cudaGetSymbolAddress((void**)&ao, g_ao);
    cudaGetSymbolAddress((void**)&gt, g_gt);
    cudaGetSymbolAddress((void**)&o,  g_o);
    cudaGetSymbolAddress((void**)&h3, g_h3);
    cudaGetSymbolAddress((void**)&f1, g_f1);
    cudaGetSymbolAddress((void**)&f2, g_f2);

    const long ND  = (long)B_ * D_ * D_;      // 4M
    const long NBD = (long)BC_ * D_;          // 2M
    const long NBF = (long)BC_ * FF_;         // 8M

    zero2_k<<<(unsigned)(ND / 256), 256>>>(Mm, Sm);

    dim3 gp(D_ / 128, BC_ / 128, 1);          // 2048x1024 projections
    dim3 gf(FF_ / 128, BC_ / 128, 1);         // 2048x4096
    dim3 gd(D_ / 128, BC_ / 128, 1);          // 2048x1024 (down)
    dim3 gb(D_ / 128, C_ / 128, B_);          // batched 512x1024
    dim3 gg(D_ / 128, D_ / 128, B_);          // batched 1024x1024 (grad)

    for (int t = 0; t < NC_; t++) {
        int c0 = t * C_;
        // --- neural memory ---
        ln_k<0><<<BC_, 256>>>(x, nullptr, g1, b1, h1, c0);
        sgemm_k<0, false><<<gp, 256>>>(h1, Wqm, qm, nullptr, BC_, D_, D_, D_, 0, 0, 0, 1.f);
        sgemm_k<0, false><<<gp, 256>>>(h1, Wkm, km, nullptr, BC_, D_, D_, D_, 0, 0, 0, 1.f);
        rownorm_k<<<BC_, 256>>>(km);
        sgemm_k<0, false><<<gp, 256>>>(h1, Wvm, vm, nullptr, BC_, D_, D_, D_, 0, 0, 0, 1.f);
        sgemm_k<0, false><<<gb, 256>>>(qm, Mm, mc, nullptr, C_, D_, D_, D_,
                                       (long)C_ * D_, (long)D_ * D_, (long)C_ * D_, 1.f);
        sgemm_k<0, false><<<gb, 256>>>(km, Mm, pr, nullptr, C_, D_, D_, D_,
                                       (long)C_ * D_, (long)D_ * D_, (long)C_ * D_, 1.f);
        sub_k<<<(unsigned)(NBD / 256), 256>>>(pr, vm);
        sgemm_k<0, true><<<gg, 256>>>(km, pr, grad, nullptr, D_, D_, C_, D_,
                                      (long)C_ * D_, (long)C_ * D_, (long)D_ * D_, 1.f / C_);
        update_k<<<(unsigned)(ND / 256), 256>>>(Mm, Sm, grad, lr, mom, fg);

        // --- attention with persistent tokens ---
        ln_k<1><<<BC_, 256>>>(x, mc, g2, b2, h2, c0);
        sgemm_k<1, false><<<gp, 256>>>(h2, Wq, qh, bq, BC_, D_, D_, D_, 0, 0, 0, 1.f);
        sgemm_k<1, false><<<gp, 256>>>(h2, Wk, kh, bk, BC_, D_, D_, D_, 0, 0, 0, 1.f);
        sgemm_k<1, false><<<gp, 256>>>(h2, Wv, vh, bv, BC_, D_, D_, D_, 0, 0, 0, 1.f);
        attn_scores_k<<<dim3(9, 8, BH_), 256>>>(qh, kh, pk, sc);
        softmax_k<<<BH_ * C_, 256>>>(sc);
        attn_av_k<<<dim3(8, BH_), 256>>>(sc, vh, pv, at);
        sgemm_k<1, false><<<gp, 256>>>(at, Wo, ao, bo, BC_, D_, D_, D_, 0, 0, 0, 1.f);
        sgemm_k<2, false><<<gp, 256>>>(mc, Wg, gt, bg, BC_, D_, D_, D_, 0, 0, 0, 1.f);
        combine_k<<<(unsigned)(NBD / 256), 256>>>(x, gt, ao, mc, o, c0);

        // --- gated FFN ---
        ln_k<2><<<BC_, 256>>>(o, nullptr, g3, b3, h3, 0);
        sgemm_k<1, false><<<gf, 256>>>(h3, Wgate, f1, bgate, BC_, FF_, D_, D_, 0, 0, 0, 1.f);
        sgemm_k<1, false><<<gf, 256>>>(h3, Wup, f2, bup, BC_, FF_, D_, D_, 0, 0, 0, 1.f);
        silu_mul_k<<<(unsigned)(NBF / 256), 256>>>(f1, f2);
        sgemm_k<3, false><<<gd, 256>>>(f1, Wdown, o, bdown, BC_, D_, FF_, FF_, 0, 0, 0, 1.f);

        scatter_k<<<(unsigned)(NBD / 256), 256>>>(o, outp, c0);
    }
}

// round 2
// speedup vs baseline: 1.0032x; 1.0032x over previous
#include <cuda_runtime.h>
#include <math.h>

#define D_  1024
#define H_  16
#define DH_ 64
#define P_  16
#define C_  512
#define B_  4
#define S_  4096
#define FF_ 4096
#define NC_ 8
#define BC_ (B_*C_)      /* 2048 */
#define PC_ (P_+C_)      /* 528  */
#define BH_ (B_*H_)      /* 64   */

// ------------------------- scratch (device globals) -------------------------
__device__ float g_h1[BC_*D_];
__device__ float g_qm[BC_*D_];
__device__ float g_km[BC_*D_];
__device__ float g_vm[BC_*D_];
__device__ float g_mc[BC_*D_];          // mem_ctx
__device__ float g_pr[BC_*D_];          // pred, then pred - vm
__device__ float g_grad[B_*D_*D_];
__device__ float g_Mst[B_*D_*D_];       // memory matrix M
__device__ float g_Sst[B_*D_*D_];       // momentum S
__device__ float g_h2[BC_*D_];
__device__ float g_qh[BC_*D_];
__device__ float g_kh[BC_*D_];
__device__ float g_vh[BC_*D_];
__device__ float g_sc[BH_*C_*PC_];      // attention scores / probs
__device__ float g_at[BC_*D_];          // attention output (pre-Wo)
__device__ float g_ao[BC_*D_];
__device__ float g_gt[BC_*D_];          // gate
__device__ float g_o [BC_*D_];
__device__ float g_h3[BC_*D_];
__device__ float g_f1[BC_*FF_];
__device__ float g_f2[BC_*FF_];

// ------------------------- generic SGEMM 128x128x8 --------------------------
// C[M,N] = epilogue(alpha * op(A)[M,K] @ B[K,N])
// TA=false: A is MxK row-major (lda = K). TA=true: A physically KxM (lda = M-ish, passed).
// EPI: 0 = alpha*acc ; 1 = acc+bias ; 2 = sigmoid(acc+bias) ; 3 = C += acc + bias
template<int EPI, bool TA>
__global__ __launch_bounds__(256) void sgemm_k(
    const float* __restrict__ A, const float* __restrict__ Bm,
    float* __restrict__ Cm, const float* __restrict__ bias,
    int M, int N, int K, int lda,
    long sA, long sB, long sC, float alpha)
{
    int bz = blockIdx.z;
    A  += (long)bz * sA;
    Bm += (long)bz * sB;
    Cm += (long)bz * sC;

    __shared__ float As[8][128];
    __shared__ float Bs[8][128];

    int tid = threadIdx.x;
    int n0 = blockIdx.x * 128, m0 = blockIdx.y * 128;
    int ty = tid >> 4, tx = tid & 15;
    int mb = ty * 8, nb = tx * 8;

    float acc[8][8];
#pragma unroll
    for (int i = 0; i < 8; i++)
#pragma unroll
        for (int j = 0; j < 8; j++) acc[i][j] = 0.f;

    for (int k0 = 0; k0 < K; k0 += 8) {
        if (TA) {
            int k = tid >> 5, m4 = (tid & 31) << 2;
            float4 v = *(const float4*)&A[(long)(k0 + k) * lda + m0 + m4];
            *(float4*)&As[k][m4] = v;
        } else {
            int m = tid >> 1, kq = (tid & 1) << 2;
            float4 v = *(const float4*)&A[(long)(m0 + m) * lda + k0 + kq];
            As[kq + 0][m] = v.x; As[kq + 1][m] = v.y;
            As[kq + 2][m] = v.z; As[kq + 3][m] = v.w;
        }
        {
            int k = tid >> 5, n4 = (tid & 31) << 2;
            float4 v = *(const float4*)&Bm[(long)(k0 + k) * N + n0 + n4];
            *(float4*)&Bs[k][n4] = v;
        }
        __syncthreads();
#pragma unroll
        for (int k = 0; k < 8; k++) {
            float a[8], b[8];
#pragma unroll
            for (int i = 0; i < 8; i++) a[i] = As[k][mb + i];
#pragma unroll
            for (int j = 0; j < 8; j++) b[j] = Bs[k][nb + j];
#pragma unroll
            for (int i = 0; i < 8; i++)
#pragma unroll
                for (int j = 0; j < 8; j++)
                    acc[i][j] = fmaf(a[i], b[j], acc[i][j]);
        }
        __syncthreads();
    }

#pragma unroll
    for (int i = 0; i < 8; i++) {
        int r = m0 + mb + i;
        float* crow = &Cm[(long)r * N + n0 + nb];
#pragma unroll
        for (int j = 0; j < 8; j++) {
            float v = acc[i][j] * alpha;
            int c = n0 + nb + j;
            if (EPI == 1)      v = v + bias[c];
            else if (EPI == 2) v = 1.f / (1.f + expf(-(v + bias[c])));
            else if (EPI == 3) v = v + bias[c] + crow[j];
            crow[j] = v;
        }
    }
}

// ------------------------------- LayerNorm ----------------------------------
// MODE 0: src rows mapped from x chunk; MODE 1: x chunk + residual; MODE 2: direct rows
template<int MODE>
__global__ __launch_bounds__(256) void ln_k(
    const float* __restrict__ src, const float* __restrict__ res,
    const float* __restrict__ gam, const float* __restrict__ bet,
    float* __restrict__ out, int c0)
{
    int r = blockIdx.x;
    const float* p;
    if (MODE == 2) p = src + (long)r * D_;
    else { int b = r / C_, i = r % C_; p = src + ((long)b * S_ + c0 + i) * D_; }

    int tid = threadIdx.x;
    float v[4], s = 0.f, sq = 0.f;
#pragma unroll
    for (int k = 0; k < 4; k++) {
        int c = tid + k * 256;
        float xv = p[c];
        if (MODE == 1) xv += res[(long)r * D_ + c];
        v[k] = xv; s += xv; sq += xv * xv;
    }
    __shared__ float shs[8], shq[8];
#pragma unroll
    for (int o = 16; o; o >>= 1) {
        s  += __shfl_xor_sync(0xffffffffu, s,  o);
        sq += __shfl_xor_sync(0xffffffffu, sq, o);
    }
    if ((tid & 31) == 0) { shs[tid >> 5] = s; shq[tid >> 5] = sq; }
    __syncthreads();
    s = 0.f; sq = 0.f;
#pragma unroll
    for (int i = 0; i < 8; i++) { s += shs[i]; sq += shq[i]; }
    float m  = s * (1.f / D_);
    float var = sq * (1.f / D_) - m * m;
    float rs = rsqrtf(var + 1e-5f);
#pragma unroll
    for (int k = 0; k < 4; k++) {
        int c = tid + k * 256;
        out[(long)r * D_ + c] = (v[k] - m) * rs * gam[c] + bet[c];
    }
}

// row L2 normalize: km *= rsqrt(sum(km^2)+1e-6)
__global__ __launch_bounds__(256) void rownorm_k(float* __restrict__ km)
{
    int r = blockIdx.x, tid = threadIdx.x;
    float* p = km + (long)r * D_;
    float v[4], sq = 0.f;
#pragma unroll
    for (int k = 0; k < 4; k++) { int c = tid + k * 256; v[k] = p[c]; sq += v[k] * v[k]; }
    __shared__ float shq[8];
#pragma unroll
    for (int o = 16; o; o >>= 1) sq += __shfl_xor_sync(0xffffffffu, sq, o);
    if ((tid & 31) == 0) shq[tid >> 5] = sq;
    __syncthreads();
    sq = 0.f;
#pragma unroll
    for (int i = 0; i < 8; i++) sq += shq[i];
    float rs = rsqrtf(sq + 1e-6f);
#pragma unroll
    for (int k = 0; k < 4; k++) { int c = tid + k * 256; p[c] = v[k] * rs; }
}

// -------------------------------- attention ---------------------------------
// scores[bh, i, j] = 0.125 * q . k + mask ; grid (9 jtiles, 8 itiles, BH)
__global__ __launch_bounds__(256) void attn_scores_k(
    const float* __restrict__ qh, const float* __restrict__ kh,
    const float* __restrict__ pk, float* __restrict__ sc)
{
    int bh = blockIdx.z; int b = bh >> 4, h = bh & 15;
    int i0 = blockIdx.y * 64, j0 = blockIdx.x * 64;
    __shared__ float Qs[64][16];
    __shared__ float Ks[64][16];
    int tid = threadIdx.x;
    int ty = tid >> 4, tx = tid & 15;
    float acc[4][4] = {};
    for (int k0 = 0; k0 < DH_; k0 += 16) {
        for (int t = tid; t < 1024; t += 256) {
            int r = t >> 4, c = t & 15;
            Qs[r][c] = qh[(((long)b * C_ + i0 + r) * H_ + h) * DH_ + k0 + c];
            int j = j0 + r;
            float kv = 0.f;
            if (j < PC_) {
                kv = (j < P_) ? pk[((long)j * H_ + h) * DH_ + k0 + c]
                              : kh[(((long)b * C_ + (j - P_)) * H_ + h) * DH_ + k0 + c];
            }
            Ks[r][c] = kv;
        }
        __syncthreads();
#pragma unroll
        for (int kk = 0; kk < 16; kk++) {
            float qr[4], kr[4];
#pragma unroll
            for (int i = 0; i < 4; i++) qr[i] = Qs[ty * 4 + i][kk];
#pragma unroll
            for (int j = 0; j < 4; j++) kr[j] = Ks[tx * 4 + j][kk];
#pragma unroll
            for (int i = 0; i < 4; i++)
#pragma unroll
                for (int j = 0; j < 4; j++) acc[i][j] += qr[i] * kr[j];
        }
        __syncthreads();
    }
#pragma unroll
    for (int i = 0; i < 4; i++) {
        int gi = i0 + ty * 4 + i;
#pragma unroll
        for (int j = 0; j < 4; j++) {
            int gj = j0 + tx * 4 + j;
            if (gj < PC_) {
                float m = (gj < P_ || (gj - P_) <= gi) ? 0.f : -1e9f;
                sc[((long)bh * C_ + gi) * PC_ + gj] = acc[i][j] * 0.125f + m;
            }
        }
    }
}

__global__ __launch_bounds__(256) void softmax_k(float* __restrict__ sc)
{
    float* row = sc + (long)blockIdx.x * PC_;
    int tid = threadIdx.x;
    __shared__ float sh[8];
    float mx = -1e30f;
    for (int c = tid; c < PC_; c += 256) mx = fmaxf(mx, row[c]);
#pragma unroll
    for (int o = 16; o; o >>= 1) mx = fmaxf(mx, __shfl_xor_sync(0xffffffffu, mx, o));
    if ((tid & 31) == 0) sh[tid >> 5] = mx;
    __syncthreads();
    mx = sh[0];
#pragma unroll
    for (int i = 1; i < 8; i++) mx = fmaxf(mx, sh[i]);
    float s = 0.f;
    for (int c = tid; c < PC_; c += 256) { float e = expf(row[c] - mx); row[c] = e; s += e; }
    __syncthreads();
#pragma unroll
    for (int o = 16; o; o >>= 1) s += __shfl_xor_sync(0xffffffffu, s, o);
    if ((tid & 31) == 0) sh[tid >> 5] = s;
    __syncthreads();
    s = 0.f;
#pragma unroll
    for (int i = 0; i < 8; i++) s += sh[i];
    float inv = 1.f / s;
    for (int c = tid; c < PC_; c += 256) row[c] *= inv;
}

// out[b,i,h,:] = probs @ V ; grid (8 itiles, BH)
__global__ __launch_bounds__(256) void attn_av_k(
    const float* __restrict__ sc, const float* __restrict__ vh,
    const float* __restrict__ pv, float* __restrict__ outp)
{
    int bh = blockIdx.y; int b = bh >> 4, h = bh & 15;
    int i0 = blockIdx.x * 64;
    __shared__ float As[64][16];
    __shared__ float Vs[16][64];
    int tid = threadIdx.x;
    int ty = tid >> 4, tx = tid & 15;
    float acc[4][4] = {};
    for (int k0 = 0; k0 < PC_; k0 += 16) {
        for (int t = tid; t < 1024; t += 256) {
            int r = t >> 4, c = t & 15;
            As[r][c] = sc[((long)bh * C_ + i0 + r) * PC_ + k0 + c];
        }
        for (int t = tid; t < 1024; t += 256) {
            int kk = t >> 6, d = t & 63;
            int j = k0 + kk;
            Vs[kk][d] = (j < P_) ? pv[((long)j * H_ + h) * DH_ + d]
                                 : vh[(((long)b * C_ + (j - P_)) * H_ + h) * DH_ + d];
        }
        __syncthreads();
#pragma unroll
        for (int kk = 0; kk < 16; kk++) {
            float ar[4], vr[4];
#pragma unroll
            for (int i = 0; i < 4; i++) ar[i] = As[ty * 4 + i][kk];
#pragma unroll
            for (int j = 0; j < 4; j++) vr[j] = Vs[kk][tx * 4 + j];
#pragma unroll
            for (int i = 0; i < 4; i++)
#pragma unroll
                for (int j = 0; j < 4; j++) acc[i][j] += ar[i] * vr[j];
        }
        __syncthreads();
    }
#pragma unroll
    for (int i = 0; i < 4; i++) {
        int gi = i0 + ty * 4 + i;
#pragma unroll
        for (int j = 0; j < 4; j++) {
            outp[((long)b * C_ + gi) * D_ + h * DH_ + tx * 4 + j] = acc[i][j];
        }
    }
}

// ------------------------------- elementwise --------------------------------
__global__ void zero2_k(float* __restrict__ a, float* __restrict__ b)
{
    long i = (long)blockIdx.x * 256 + threadIdx.x;
    a[i] = 0.f; b[i] = 0.f;
}

__global__ void sub_k(float* __restrict__ p, const float* __restrict__ v)
{
    long i = (long)blockIdx.x * 256 + threadIdx.x;
    p[i] -= v[i];
}

__global__ void update_k(float* __restrict__ M, float* __restrict__ S,
                         const float* __restrict__ grad,
                         const float* __restrict__ lr,
                         const float* __restrict__ mom,
                         const float* __restrict__ fg)
{
    long i = (long)blockIdx.x * 256 + threadIdx.x;
    float th = 1.f / (1.f + expf(-lr[0]));
    float et = 1.f / (1.f + expf(-mom[0]));
    float al = 1.f / (1.f + expf(-fg[0]));
    float s = et * S[i] - th * grad[i];
    S[i] = s;
    M[i] = (1.f - al) * M[i] + s;
}

__global__ void combine_k(const float* __restrict__ x, const float* __restrict__ gt,
                          const float* __restrict__ ao, const float* __restrict__ mc,
                          float* __restrict__ o, int c0)
{
    long idx = (long)blockIdx.x * 256 + threadIdx.x;
    int r = (int)(idx / D_), c = (int)(idx % D_);
    int b = r / C_, i = r % C_;
    float xv = x[((long)b * S_ + c0 + i) * D_ + c];
    float gv = gt[idx];
    o[idx] = xv + gv * ao[idx] + (1.f - gv) * mc[idx];
}

__global__ void silu_mul_k(float* __restrict__ f1, const float* __restrict__ f2)
{
    long i = (long)blockIdx.x * 256 + threadIdx.x;
    float v = f1[i];
    f1[i] = v / (1.f + expf(-v)) * f2[i];
}

__global__ void scatter_k(const float* __restrict__ o, float* __restrict__ outp, int c0)
{
    long idx = (long)blockIdx.x * 256 + threadIdx.x;
    int r = (int)(idx / D_), c = (int)(idx % D_);
    int b = r / C_, i = r % C_;
    outp[((long)b * S_ + c0 + i) * D_ + c] = o[idx];
}

// --------------------------------- launch -----------------------------------
extern "C" void kernel_launch(void* const* d_in, const int* in_sizes, int n_in,
                              void* d_out, int out_size)
{
    const float* x     = (const float*)d_in[0];
    const float* g1    = (const float*)d_in[1];
    const float* b1    = (const float*)d_in[2];
    const float* g2    = (const float*)d_in[3];
    const float* b2    = (const float*)d_in[4];
    const float* g3    = (const float*)d_in[5];
    const float* b3    = (const float*)d_in[6];
    const float* Wqm   = (const float*)d_in[7];
    const float* Wkm   = (const float*)d_in[8];
    const float* Wvm   = (const float*)d_in[9];
    const float* lr    = (const float*)d_in[10];
    const float* mom   = (const float*)d_in[11];
    const float* fg    = (const float*)d_in[12];
    const float* Wq    = (const float*)d_in[13];
    const float* bq    = (const float*)d_in[14];
    const float* Wk    = (const float*)d_in[15];
    const float* bk    = (const float*)d_in[16];
    const float* Wv    = (const float*)d_in[17];
    const float* bv    = (const float*)d_in[18];
    const float* Wo    = (const float*)d_in[19];
    const float* bo    = (const float*)d_in[20];
    const float* pk    = (const float*)d_in[21];
    const float* pv    = (const float*)d_in[22];
    const float* Wg    = (const float*)d_in[23];
    const float* bg    = (const float*)d_in[24];
    const float* Wgate = (const float*)d_in[25];
    const float* bgate = (const float*)d_in[26];
    const float* Wup   = (const float*)d_in[27];
    const float* bup   = (const float*)d_in[28];
    const float* Wdown = (const float*)d_in[29];
    const float* bdown = (const float*)d_in[30];
    float* outp = (float*)d_out;

    float *h1, *qm, *km, *vm, *mc, *pr, *grad, *Mm, *Sm, *h2, *qh, *kh, *vh;
    float *sc, *at, *ao, *gt, *o, *h3, *f1, *f2;
    cudaGetSymbolAddress((void**)&h1, g_h1);
    cudaGetSymbolAddress((void**)&qm, g_qm);
    cudaGetSymbolAddress((void**)&km, g_km);
    cudaGetSymbolAddress((void**)&vm, g_vm);
    cudaGetSymbolAddress((void**)&mc, g_mc);
    cudaGetSymbolAddress((void**)&pr, g_pr);
    cudaGetSymbolAddress((void**)&grad, g_grad);
    cudaGetSymbolAddress((void**)&Mm, g_Mst);
    cudaGetSymbolAddress((void**)&Sm, g_Sst);
    cudaGetSymbolAddress((void**)&h2, g_h2);
    cudaGetSymbolAddress((void**)&qh, g_qh);
    cudaGetSymbolAddress((void**)&kh, g_kh);
    cudaGetSymbolAddress((void**)&vh, g_vh);
    cudaGetSymbolAddress((void**)&sc, g_sc);
    cudaGetSymbolAddress((void**)&at, g_at);
    cudaGetSymbolAddress((void**)&ao, g_ao);
    cudaGetSymbolAddress((void**)&gt, g_gt);
    cudaGetSymbolAddress((void**)&o,  g_o);
    cudaGetSymbolAddress((void**)&h3, g_h3);
    cudaGetSymbolAddress((void**)&f1, g_f1);
    cudaGetSymbolAddress((void**)&f2, g_f2);

    const long ND  = (long)B_ * D_ * D_;      // 4M
    const long NBD = (long)BC_ * D_;          // 2M
    const long NBF = (long)BC_ * FF_;         // 8M

    zero2_k<<<(unsigned)(ND / 256), 256>>>(Mm, Sm);

    dim3 gp(D_ / 128, BC_ / 128, 1);          // 2048x1024 projections
    dim3 gf(FF_ / 128, BC_ / 128, 1);         // 2048x4096
    dim3 gd(D_ / 128, BC_ / 128, 1);          // 2048x1024 (down)
    dim3 gb(D_ / 128, C_ / 128, B_);          // batched 512x1024
    dim3 gg(D_ / 128, D_ / 128, B_);          // batched 1024x1024 (grad)

    for (int t = 0; t < NC_; t++) {
        int c0 = t * C_;
        // --- neural memory ---
        ln_k<0><<<BC_, 256>>>(x, nullptr, g1, b1, h1, c0);
        sgemm_k<0, false><<<gp, 256>>>(h1, Wqm, qm, nullptr, BC_, D_, D_, D_, 0, 0, 0, 1.f);
        sgemm_k<0, false><<<gp, 256>>>(h1, Wkm, km, nullptr, BC_, D_, D_, D_, 0, 0, 0, 1.f);
        rownorm_k<<<BC_, 256>>>(km);
        sgemm_k<0, false><<<gp, 256>>>(h1, Wvm, vm, nullptr, BC_, D_, D_, D_, 0, 0, 0, 1.f);
        sgemm_k<0, false><<<gb, 256>>>(qm, Mm, mc, nullptr, C_, D_, D_, D_,
                                       (long)C_ * D_, (long)D_ * D_, (long)C_ * D_, 1.f);
        sgemm_k<0, false><<<gb, 256>>>(km, Mm, pr, nullptr, C_, D_, D_, D_,
                                       (long)C_ * D_, (long)D_ * D_, (long)C_ * D_, 1.f);
        sub_k<<<(unsigned)(NBD / 256), 256>>>(pr, vm);
        sgemm_k<0, true><<<gg, 256>>>(km, pr, grad, nullptr, D_, D_, C_, D_,
                                      (long)C_ * D_, (long)C_ * D_, (long)D_ * D_, 1.f / C_);
        update_k<<<(unsigned)(ND / 256), 256>>>(Mm, Sm, grad, lr, mom, fg);

        // --- attention with persistent tokens ---
        ln_k<1><<<BC_, 256>>>(x, mc, g2, b2, h2, c0);
        sgemm_k<1, false><<<gp, 256>>>(h2, Wq, qh, bq, BC_, D_, D_, D_, 0, 0, 0, 1.f);
        sgemm_k<1, false><<<gp, 256>>>(h2, Wk, kh, bk, BC_, D_, D_, D_, 0, 0, 0, 1.f);
        sgemm_k<1, false><<<gp, 256>>>(h2, Wv, vh, bv, BC_, D_, D_, D_, 0, 0, 0, 1.f);
        attn_scores_k<<<dim3(9, 8, BH_), 256>>>(qh, kh, pk, sc);
        softmax_k<<<BH_ * C_, 256>>>(sc);
        attn_av_k<<<dim3(8, BH_), 256>>>(sc, vh, pv, at);
        sgemm_k<1, false><<<gp, 256>>>(at, Wo, ao, bo, BC_, D_, D_, D_, 0, 0, 0, 1.f);
        sgemm_k<2, false><<<gp, 256>>>(mc, Wg, gt, bg, BC_, D_, D_, D_, 0, 0, 0, 1.f);
        combine_k<<<(unsigned)(NBD / 256), 256>>>(x, gt, ao, mc, o, c0);

        // --- gated FFN ---
        ln_k<2><<<BC_, 256>>>(o, nullptr, g3, b3, h3, 0);
        sgemm_k<1, false><<<gf, 256>>>(h3, Wgate, f1, bgate, BC_, FF_, D_, D_, 0, 0, 0, 1.f);
        sgemm_k<1, false><<<gf, 256>>>(h3, Wup, f2, bup, BC_, FF_, D_, D_, 0, 0, 0, 1.f);
        silu_mul_k<<<(unsigned)(NBF / 256), 256>>>(f1, f2);
        sgemm_k<3, false><<<gd, 256>>>(f1, Wdown, o, bdown, BC_, D_, FF_, FF_, 0, 0, 0, 1.f);

        scatter_k<<<(unsigned)(NBD / 256), 256>>>(o, outp, c0);
    }
}

// round 5
// speedup vs baseline: 1.2323x; 1.2284x over previous
#include <cuda_runtime.h>
#include <cuda_bf16.h>
#include <math.h>
#include <stdint.h>

#define D_  1024
#define H_  16
#define DH_ 64
#define P_  16
#define C_  512
#define B_  4
#define S_  4096
#define FF_ 4096
#define NC_ 8
#define BC_ (B_*C_)      /* 2048 */
#define PC_ (P_+C_)      /* 528  */
#define BH_ (B_*H_)      /* 64   */

// ------------------------- scratch (device globals) -------------------------
__device__ float g_h1[BC_*D_];
__device__ float g_qm[BC_*D_];
__device__ float g_km[BC_*D_];
__device__ float g_vm[BC_*D_];
__device__ float g_mc[BC_*D_];
__device__ float g_pr[BC_*D_];
__device__ float g_grad[B_*D_*D_];
__device__ float g_Mst[B_*D_*D_];
__device__ float g_Sst[B_*D_*D_];
__device__ float g_h2[BC_*D_];
__device__ float g_qh[BC_*D_];
__device__ float g_kh[BC_*D_];
__device__ float g_vh[BC_*D_];
__device__ float g_sc[BH_*C_*PC_];
__device__ float g_at[BC_*D_];
__device__ float g_ao[BC_*D_];
__device__ float g_gt[BC_*D_];
__device__ float g_o [BC_*D_];
__device__ float g_h3[BC_*D_];
__device__ float g_f1[BC_*FF_];
__device__ float g_f2[BC_*FF_];

// bf16 split operand buffers: [0,len) = hi, [len,2len) = lo. [N,K] K-major.
__device__ __nv_bfloat16 w_qm[2*D_*D_];
__device__ __nv_bfloat16 w_km[2*D_*D_];
__device__ __nv_bfloat16 w_vm[2*D_*D_];
__device__ __nv_bfloat16 w_q [2*D_*D_];
__device__ __nv_bfloat16 w_k [2*D_*D_];
__device__ __nv_bfloat16 w_v [2*D_*D_];
__device__ __nv_bfloat16 w_o [2*D_*D_];
__device__ __nv_bfloat16 w_g [2*D_*D_];
__device__ __nv_bfloat16 w_gate[(long)2*FF_*D_];
__device__ __nv_bfloat16 w_up  [(long)2*FF_*D_];
__device__ __nv_bfloat16 w_down[(long)2*D_*FF_];
__device__ __nv_bfloat16 t_M [2*B_*D_*D_];        // M^T per batch (hi|lo)
__device__ __nv_bfloat16 t_km[(long)2*B_*D_*C_];  // km^T (hi|lo)
__device__ __nv_bfloat16 t_pr[(long)2*B_*D_*C_];  // (pred-vm)^T (hi|lo)

// ----------------------------- PTX helpers ----------------------------------
__device__ __forceinline__ uint32_t smem_u32(const void* p) {
    uint32_t a;
    asm("{ .reg .u64 t; cvta.to.shared.u64 t, %1; cvt.u32.u64 %0, t; }"
        : "=r"(a) : "l"(p));
    return a;
}
__device__ __forceinline__ void ldsm4(uint32_t& r0, uint32_t& r1, uint32_t& r2,
                                      uint32_t& r3, uint32_t addr) {
    asm volatile("ldmatrix.sync.aligned.m8n8.x4.shared.b16 {%0,%1,%2,%3}, [%4];"
                 : "=r"(r0), "=r"(r1), "=r"(r2), "=r"(r3) : "r"(addr));
}
#define MMA16816(d, a, b0, b1)                                                   \
    asm volatile(                                                                \
        "mma.sync.aligned.m16n8k16.row.col.f32.bf16.bf16.f32 "                   \
        "{%0,%1,%2,%3}, {%4,%5,%6,%7}, {%8,%9}, {%0,%1,%2,%3};"                  \
        : "+f"((d)[0]), "+f"((d)[1]), "+f"((d)[2]), "+f"((d)[3])                 \
        : "r"((a)[0]), "r"((a)[1]), "r"((a)[2]), "r"((a)[3]), "r"(b0), "r"(b1))

// fp32 pair -> (hi bf16x2, lo bf16x2)
__device__ __forceinline__ void split2(float2 f, uint32_t& h, uint32_t& l) {
    __nv_bfloat162 hb = __float22bfloat162_rn(f);
    float2 hf = __bfloat1622float2(hb);
    __nv_bfloat162 lb = __float22bfloat162_rn(make_float2(f.x - hf.x, f.y - hf.y));
    h = *(uint32_t*)&hb;
    l = *(uint32_t*)&lb;
}

// ------------------ split-bf16 3-pass HMMA GEMM (mma.sync) ------------------
// C[M,N] = epi(alpha * A[M,K] @ B[N,K]^T), fp32-grade accuracy via
// a_hi*b_hi + a_lo*b_hi + a_hi*b_lo. CTA tile 128x128, K-step 32, dbl-buffered.
// A: TA=0 fp32 (split on load); TA=1 pre-split bf16 (Ah/Al).
// EPI: 0 = alpha*acc ; 1 = acc+bias ; 2 = sigmoid(acc+bias) ; 3 = C += acc+bias
#define LDA_ 40
#define TSZ_ (128 * LDA_)
#define TM_SMEM (8 * TSZ_ * 2)   /* 81920 B */

template<int EPI, int TA>
__global__ __launch_bounds__(256) void tmma_k(
    const void* __restrict__ Ahv, const void* __restrict__ Alv,
    const __nv_bfloat16* __restrict__ Bwh, const __nv_bfloat16* __restrict__ Bwl,
    float* __restrict__ Cm, const float* __restrict__ bias,
    int Ncols, int K, long sA, long sB, long sC, float alpha)
{
    extern __shared__ __nv_bfloat16 sm_[];
    __nv_bfloat16* Ah_s = sm_;              // [2][TSZ_]
    __nv_bfloat16* Al_s = sm_ + 2 * TSZ_;
    __nv_bfloat16* Bh_s = sm_ + 4 * TSZ_;
    __nv_bfloat16* Bl_s = sm_ + 6 * TSZ_;

    const int bz = blockIdx.z;
    const float*         Af  = (const float*)Ahv + (TA ? 0 : bz * sA);
    const __nv_bfloat16* Abh = (const __nv_bfloat16*)Ahv + (TA ? bz * sA : 0);
    const __nv_bfloat16* Abl = (const __nv_bfloat16*)Alv + (TA ? bz * sA : 0);
    const __nv_bfloat16* Bbh = Bwh + bz * sB;
    const __nv_bfloat16* Bbl = Bwl + bz * sB;
    Cm += bz * sC;

    const int tid = threadIdx.x, warp = tid >> 5, lane = tid & 31;
    const int n0 = blockIdx.x * 128, m0 = blockIdx.y * 128;
    const int mo = (warp >> 2) * 64, no = (warp & 3) * 32;

    const int lr = tid >> 1;          // loader row 0..127
    const int lc = (tid & 1) * 16;    // loader col base

    float acc[4][4][4] = {};
    float4 sa[4];                     // staging (TA=0)
    uint4  sah[2], sal[2];            // staging (TA=1)
    uint4  sbh[2], sbl[2];

    const int KT = K >> 5;
    const int lrow = lane & 15, lcol = (lane >> 4) << 3;

    // ---- preload tile 0 into buffer 0 ----
    {
        if (TA == 0) {
#pragma unroll
            for (int j = 0; j < 4; j++)
                sa[j] = *(const float4*)(Af + (long)(m0 + lr) * K + lc + 4 * j);
#pragma unroll
            for (int j = 0; j < 4; j++) {
                uint32_t h0, l0, h1, l1;
                split2(make_float2(sa[j].x, sa[j].y), h0, l0);
                split2(make_float2(sa[j].z, sa[j].w), h1, l1);
                uint2 uh, ul;
                uh.x = h0; uh.y = h1; ul.x = l0; ul.y = l1;
                *(uint2*)&Ah_s[lr * LDA_ + lc + 4 * j] = uh;
                *(uint2*)&Al_s[lr * LDA_ + lc + 4 * j] = ul;
            }
        } else {
#pragma unroll
            for (int j = 0; j < 2; j++) {
                sah[j] = *(const uint4*)(Abh + (long)(m0 + lr) * K + lc + 8 * j);
                sal[j] = *(const uint4*)(Abl + (long)(m0 + lr) * K + lc + 8 * j);
            }
#pragma unroll
            for (int j = 0; j < 2; j++) {
                *(uint4*)&Ah_s[lr * LDA_ + lc + 8 * j] = sah[j];
                *(uint4*)&Al_s[lr * LDA_ + lc + 8 * j] = sal[j];
            }
        }
#pragma unroll
        for (int j = 0; j < 2; j++) {
            sbh[j] = *(const uint4*)(Bbh + (long)(n0 + lr) * K + lc + 8 * j);
            sbl[j] = *(const uint4*)(Bbl + (long)(n0 + lr) * K + lc + 8 * j);
        }
#pragma unroll
        for (int j = 0; j < 2; j++) {
            *(uint4*)&Bh_s[lr * LDA_ + lc + 8 * j] = sbh[j];
            *(uint4*)&Bl_s[lr * LDA_ + lc + 8 * j] = sbl[j];
        }
    }
    __syncthreads();

    for (int kt = 0; kt < KT; kt++) {
        const int buf = kt & 1;
        // ---- prefetch next tile into registers ----
        if (kt + 1 < KT) {
            const int k0 = (kt + 1) << 5;
            if (TA == 0) {
#pragma unroll
                for (int j = 0; j < 4; j++)
                    sa[j] = *(const float4*)(Af + (long)(m0 + lr) * K + k0 + lc + 4 * j);
            } else {
#pragma unroll
                for (int j = 0; j < 2; j++) {
                    sah[j] = *(const uint4*)(Abh + (long)(m0 + lr) * K + k0 + lc + 8 * j);
                    sal[j] = *(const uint4*)(Abl + (long)(m0 + lr) * K + k0 + lc + 8 * j);
                }
            }
#pragma unroll
            for (int j = 0; j < 2; j++) {
                sbh[j] = *(const uint4*)(Bbh + (long)(n0 + lr) * K + k0 + lc + 8 * j);
                sbl[j] = *(const uint4*)(Bbl + (long)(n0 + lr) * K + k0 + lc + 8 * j);
            }
        }
        // ---- compute from buf: 3 passes (hh, lh, hl) x 2 k-halves ----
#pragma unroll
        for (int h = 0; h < 2; h++) {
#pragma unroll
            for (int pass = 0; pass < 3; pass++) {
                const __nv_bfloat16* At = ((pass == 1) ? Al_s : Ah_s) + buf * TSZ_;
                const __nv_bfloat16* Bt = ((pass == 2) ? Bl_s : Bh_s) + buf * TSZ_;
                uint32_t a[4][4], q[8];
#pragma unroll
                for (int mt = 0; mt < 4; mt++) {
                    uint32_t ad = smem_u32(&At[(mo + mt * 16 + lrow) * LDA_ + h * 16 + lcol]);
                    ldsm4(a[mt][0], a[mt][1], a[mt][2], a[mt][3], ad);
                }
#pragma unroll
                for (int g = 0; g < 2; g++) {
                    uint32_t bd = smem_u32(&Bt[(no + g * 16 + lrow) * LDA_ + h * 16 + lcol]);
                    ldsm4(q[g * 4 + 0], q[g * 4 + 1], q[g * 4 + 2], q[g * 4 + 3], bd);
                }
#pragma unroll
                for (int mt = 0; mt < 4; mt++)
#pragma unroll
                    for (int j = 0; j < 4; j++) {
                        uint32_t b0 = q[(j >> 1) * 4 + (j & 1)];
                        uint32_t b1 = q[(j >> 1) * 4 + (j & 1) + 2];
                        MMA16816(acc[mt][j], a[mt], b0, b1);
                    }
            }
        }
        // ---- store staged tile into other buffer ----
        if (kt + 1 < KT) {
            const int nb = (kt + 1) & 1;
            if (TA == 0) {
#pragma unroll
                for (int j = 0; j < 4; j++) {
                    uint32_t h0, l0, h1, l1;
                    split2(make_float2(sa[j].x, sa[j].y), h0, l0);
                    split2(make_float2(sa[j].z, sa[j].w), h1, l1);
                    uint2 uh, ul;
                    uh.x = h0; uh.y = h1; ul.x = l0; ul.y = l1;
                    *(uint2*)&Ah_s[nb * TSZ_ + lr * LDA_ + lc + 4 * j] = uh;
                    *(uint2*)&Al_s[nb * TSZ_ + lr * LDA_ + lc + 4 * j] = ul;
                }
            } else {
#pragma unroll
                for (int j = 0; j < 2; j++) {
                    *(uint4*)&Ah_s[nb * TSZ_ + lr * LDA_ + lc + 8 * j] = sah[j];
                    *(uint4*)&Al_s[nb * TSZ_ + lr * LDA_ + lc + 8 * j] = sal[j];
                }
            }
#pragma unroll
            for (int j = 0; j < 2; j++) {
                *(uint4*)&Bh_s[nb * TSZ_ + lr * LDA_ + lc + 8 * j] = sbh[j];
                *(uint4*)&Bl_s[nb * TSZ_ + lr * LDA_ + lc + 8 * j] = sbl[j];
            }
        }
        __syncthreads();
    }

    // ------------------------------ epilogue --------------------------------
#pragma unroll
    for (int mt = 0; mt < 4; mt++) {
#pragma unroll
        for (int j = 0; j < 4; j++) {
            int row = m0 + mo + mt * 16 + (lane >> 2);
            int col = n0 + no + j * 8 + (lane & 3) * 2;
#pragma unroll
            for (int hh = 0; hh < 2; hh++) {
                int r = row + hh * 8;
                float v0 = acc[mt][j][hh * 2 + 0] * alpha;
                float v1 = acc[mt][j][hh * 2 + 1] * alpha;
                float* cp = Cm + (long)r * Ncols + col;
                if (EPI >= 1) {
                    float2 bv = *(const float2*)(bias + col);
                    v0 += bv.x; v1 += bv.y;
                }
                if (EPI == 2) {
                    v0 = 1.f / (1.f + expf(-v0));
                    v1 = 1.f / (1.f + expf(-v1));
                }
                if (EPI == 3) {
                    float2 c = *(float2*)cp;
                    v0 += c.x; v1 += c.y;
                }
                float2 o; o.x = v0; o.y = v1;
                *(float2*)cp = o;
            }
        }
    }
}

// ---------------- transpose + fp32 -> split-bf16 convert --------------------
__global__ __launch_bounds__(256) void tconv2_k(
    const float* __restrict__ in, __nv_bfloat16* __restrict__ out_hi,
    __nv_bfloat16* __restrict__ out_lo, int R, int Cc, long sIn, long sOut)
{
    __shared__ float t[32][33];
    in     += (long)blockIdx.z * sIn;
    out_hi += (long)blockIdx.z * sOut;
    out_lo += (long)blockIdx.z * sOut;
    int r0 = blockIdx.y * 32, c0 = blockIdx.x * 32;
    int tx = threadIdx.x & 31, ty = threadIdx.x >> 5;
#pragma unroll
    for (int i = 0; i < 32; i += 8)
        t[ty + i][tx] = in[(long)(r0 + ty + i) * Cc + c0 + tx];
    __syncthreads();
#pragma unroll
    for (int i = 0; i < 32; i += 8) {
        float v = t[tx][ty + i];
        __nv_bfloat16 hb = __float2bfloat16(v);
        out_hi[(long)(c0 + ty + i) * R + r0 + tx] = hb;
        out_lo[(long)(c0 + ty + i) * R + r0 + tx] = __float2bfloat16(v - __bfloat162float(hb));
    }
}

// ------------------------------- LayerNorm ----------------------------------
template<int MODE>
__global__ __launch_bounds__(256) void ln_k(
    const float* __restrict__ src, const float* __restrict__ res,
    const float* __restrict__ gam, const float* __restrict__ bet,
    float* __restrict__ out, int c0)
{
    int r = blockIdx.x;
    const float* p;
    if (MODE == 2) p = src + (long)r * D_;
    else { int b = r / C_, i = r % C_; p = src + ((long)b * S_ + c0 + i) * D_; }

    int tid = threadIdx.x;
    float v[4], s = 0.f, sq = 0.f;
#pragma unroll
    for (int k = 0; k < 4; k++) {
        int c = tid + k * 256;
        float xv = p[c];
        if (MODE == 1) xv += res[(long)r * D_ + c];
        v[k] = xv; s += xv; sq += xv * xv;
    }
    __shared__ float shs[8], shq[8];
#pragma unroll
    for (int o = 16; o; o >>= 1) {
        s  += __shfl_xor_sync(0xffffffffu, s,  o);
        sq += __shfl_xor_sync(0xffffffffu, sq, o);
    }
    if ((tid & 31) == 0) { shs[tid >> 5] = s; shq[tid >> 5] = sq; }
    __syncthreads();
    s = 0.f; sq = 0.f;
#pragma unroll
    for (int i = 0; i < 8; i++) { s += shs[i]; sq += shq[i]; }
    float m  = s * (1.f / D_);
    float var = sq * (1.f / D_) - m * m;
    float rs = rsqrtf(var + 1e-5f);
#pragma unroll
    for (int k = 0; k < 4; k++) {
        int c = tid + k * 256;
        out[(long)r * D_ + c] = (v[k] - m) * rs * gam[c] + bet[c];
    }
}

__global__ __launch_bounds__(256) void rownorm_k(float* __restrict__ km)
{
    int r = blockIdx.x, tid = threadIdx.x;
    float* p = km + (long)r * D_;
    float v[4], sq = 0.f;
#pragma unroll
    for (int k = 0; k < 4; k++) { int c = tid + k * 256; v[k] = p[c]; sq += v[k] * v[k]; }
    __shared__ float shq[8];
#pragma unroll
    for (int o = 16; o; o >>= 1) sq += __shfl_xor_sync(0xffffffffu, sq, o);
    if ((tid & 31) == 0) shq[tid >> 5] = sq;
    __syncthreads();
    sq = 0.f;
#pragma unroll
    for (int i = 0; i < 8; i++) sq += shq[i];
    float rs = rsqrtf(sq + 1e-6f);
#pragma unroll
    for (int k = 0; k < 4; k++) { int c = tid + k * 256; p[c] = v[k] * rs; }
}

// -------------------------------- attention ---------------------------------
__global__ __launch_bounds__(256) void attn_scores_k(
    const float* __restrict__ qh, const float* __restrict__ kh,
    const float* __restrict__ pk, float* __restrict__ sc)
{
    int bh = blockIdx.z; int b = bh >> 4, h = bh & 15;
    int i0 = blockIdx.y * 64, j0 = blockIdx.x * 64;
    __shared__ float Qs[64][16];
    __shared__ float Ks[64][16];
    int tid = threadIdx.x;
    int ty = tid >> 4, tx = tid & 15;
    float acc[4][4] = {};
    for (int k0 = 0; k0 < DH_; k0 += 16) {
        for (int t = tid; t < 1024; t += 256) {
            int r = t >> 4, c = t & 15;
            Qs[r][c] = qh[(((long)b * C_ + i0 + r) * H_ + h) * DH_ + k0 + c];
            int j = j0 + r;
            float kv = 0.f;
            if (j < PC_) {
                kv = (j < P_) ? pk[((long)j * H_ + h) * DH_ + k0 + c]
                              : kh[(((long)b * C_ + (j - P_)) * H_ + h) * DH_ + k0 + c];
            }
            Ks[r][c] = kv;
        }
        __syncthreads();
#pragma unroll
        for (int kk = 0; kk < 16; kk++) {
            float qr[4], kr[4];
#pragma unroll
            for (int i = 0; i < 4; i++) qr[i] = Qs[ty * 4 + i][kk];
#pragma unroll
            for (int j = 0; j < 4; j++) kr[j] = Ks[tx * 4 + j][kk];
#pragma unroll
            for (int i = 0; i < 4; i++)
#pragma unroll
                for (int j = 0; j < 4; j++) acc[i][j] += qr[i] * kr[j];
        }
        __syncthreads();
    }
#pragma unroll
    for (int i = 0; i < 4; i++) {
        int gi = i0 + ty * 4 + i;
#pragma unroll
        for (int j = 0; j < 4; j++) {
            int gj = j0 + tx * 4 + j;
            if (gj < PC_) {
                float m = (gj < P_ || (gj - P_) <= gi) ? 0.f : -1e9f;
                sc[((long)bh * C_ + gi) * PC_ + gj] = acc[i][j] * 0.125f + m;
            }
        }
    }
}

__global__ __launch_bounds__(256) void softmax_k(float* __restrict__ sc)
{
    float* row = sc + (long)blockIdx.x * PC_;
    int tid = threadIdx.x;
    __shared__ float sh[8];
    float mx = -1e30f;
    for (int c = tid; c < PC_; c += 256) mx = fmaxf(mx, row[c]);
#pragma unroll
    for (int o = 16; o; o >>= 1) mx = fmaxf(mx, __shfl_xor_sync(0xffffffffu, mx, o));
    if ((tid & 31) == 0) sh[tid >> 5] = mx;
    __syncthreads();
    mx = sh[0];
#pragma unroll
    for (int i = 1; i < 8; i++) mx = fmaxf(mx, sh[i]);
    float s = 0.f;
    for (int c = tid; c < PC_; c += 256) { float e = expf(row[c] - mx); row[c] = e; s += e; }
    __syncthreads();
#pragma unroll
    for (int o = 16; o; o >>= 1) s += __shfl_xor_sync(0xffffffffu, s, o);
    if ((tid & 31) == 0) sh[tid >> 5] = s;
    __syncthreads();
    s = 0.f;
#pragma unroll
    for (int i = 0; i < 8; i++) s += sh[i];
    float inv = 1.f / s;
    for (int c = tid; c < PC_; c += 256) row[c] *= inv;
}

__global__ __launch_bounds__(256) void attn_av_k(
    const float* __restrict__ sc, const float* __restrict__ vh,
    const float* __restrict__ pv, float* __restrict__ outp)
{
    int bh = blockIdx.y; int b = bh >> 4, h = bh & 15;
    int i0 = blockIdx.x * 64;
    __shared__ float As[64][16];
    __shared__ float Vs[16][64];
    int tid = threadIdx.x;
    int ty = tid >> 4, tx = tid & 15;
    float acc[4][4] = {};
    for (int k0 = 0; k0 < PC_; k0 += 16) {
        for (int t = tid; t < 1024; t += 256) {
            int r = t >> 4, c = t & 15;
            As[r][c] = sc[((long)bh * C_ + i0 + r) * PC_ + k0 + c];
        }
        for (int t = tid; t < 1024; t += 256) {
            int kk = t >> 6, d = t & 63;
            int j = k0 + kk;
            Vs[kk][d] = (j < P_) ? pv[((long)j * H_ + h) * DH_ + d]
                                 : vh[(((long)b * C_ + (j - P_)) * H_ + h) * DH_ + d];
        }
        __syncthreads();
#pragma unroll
        for (int kk = 0; kk < 16; kk++) {
            float ar[4], vr[4];
#pragma unroll
            for (int i = 0; i < 4; i++) ar[i] = As[ty * 4 + i][kk];
#pragma unroll
            for (int j = 0; j < 4; j++) vr[j] = Vs[kk][tx * 4 + j];
#pragma unroll
            for (int i = 0; i < 4; i++)
#pragma unroll
                for (int j = 0; j < 4; j++) acc[i][j] += ar[i] * vr[j];
        }
        __syncthreads();
    }
#pragma unroll
    for (int i = 0; i < 4; i++) {
        int gi = i0 + ty * 4 + i;
#pragma unroll
        for (int j = 0; j < 4; j++) {
            outp[((long)b * C_ + gi) * D_ + h * DH_ + tx * 4 + j] = acc[i][j];
        }
    }
}

// ------------------------------- elementwise --------------------------------
__global__ void zero2_k(float* __restrict__ a, float* __restrict__ b)
{
    long i = (long)blockIdx.x * 256 + threadIdx.x;
    a[i] = 0.f; b[i] = 0.f;
}

__global__ void sub_k(float* __restrict__ p, const float* __restrict__ v)
{
    long i = (long)blockIdx.x * 256 + threadIdx.x;
    p[i] -= v[i];
}

__global__ void update_k(float* __restrict__ M, float* __restrict__ S,
                         const float* __restrict__ grad,
                         const float* __restrict__ lr,
                         const float* __restrict__ mom,
                         const float* __restrict__ fg)
{
    long i = (long)blockIdx.x * 256 + threadIdx.x;
    float th = 1.f / (1.f + expf(-lr[0]));
    float et = 1.f / (1.f + expf(-mom[0]));
    float al = 1.f / (1.f + expf(-fg[0]));
    float s = et * S[i] - th * grad[i];
    S[i] = s;
    M[i] = (1.f - al) * M[i] + s;
}

__global__ void combine_k(const float* __restrict__ x, const float* __restrict__ gt,
                          const float* __restrict__ ao, const float* __restrict__ mc,
                          float* __restrict__ o, int c0)
{
    long idx = (long)blockIdx.x * 256 + threadIdx.x;
    int r = (int)(idx / D_), c = (int)(idx % D_);
    int b = r / C_, i = r % C_;
    float xv = x[((long)b * S_ + c0 + i) * D_ + c];
    float gv = gt[idx];
    o[idx] = xv + gv * ao[idx] + (1.f - gv) * mc[idx];
}

__global__ void silu_mul_k(float* __restrict__ f1, const float* __restrict__ f2)
{
    long i = (long)blockIdx.x * 256 + threadIdx.x;
    float v = f1[i];
    f1[i] = v / (1.f + expf(-v)) * f2[i];
}

__global__ void scatter_k(const float* __restrict__ o, float* __restrict__ outp, int c0)
{
    long idx = (long)blockIdx.x * 256 + threadIdx.x;
    int r = (int)(idx / D_), c = (int)(idx % D_);
    int b = r / C_, i = r % C_;
    outp[((long)b * S_ + c0 + i) * D_ + c] = o[idx];
}

// --------------------------------- launch -----------------------------------
extern "C" void kernel_launch(void* const* d_in, const int* in_sizes, int n_in,
                              void* d_out, int out_size)
{
    const float* x     = (const float*)d_in[0];
    const float* g1    = (const float*)d_in[1];
    const float* b1    = (const float*)d_in[2];
    const float* g2    = (const float*)d_in[3];
    const float* b2    = (const float*)d_in[4];
    const float* g3    = (const float*)d_in[5];
    const float* b3    = (const float*)d_in[6];
    const float* Wqm   = (const float*)d_in[7];
    const float* Wkm   = (const float*)d_in[8];
    const float* Wvm   = (const float*)d_in[9];
    const float* lr    = (const float*)d_in[10];
    const float* mom   = (const float*)d_in[11];
    const float* fg    = (const float*)d_in[12];
    const float* Wq    = (const float*)d_in[13];
    const float* bq    = (const float*)d_in[14];
    const float* Wk    = (const float*)d_in[15];
    const float* bk    = (const float*)d_in[16];
    const float* Wv    = (const float*)d_in[17];
    const float* bv    = (const float*)d_in[18];
    const float* Wo    = (const float*)d_in[19];
    const float* bo    = (const float*)d_in[20];
    const float* pk    = (const float*)d_in[21];
    const float* pv    = (const float*)d_in[22];
    const float* Wg    = (const float*)d_in[23];
    const float* bg    = (const float*)d_in[24];
    const float* Wgate = (const float*)d_in[25];
    const float* bgate = (const float*)d_in[26];
    const float* Wup   = (const float*)d_in[27];
    const float* bup   = (const float*)d_in[28];
    const float* Wdown = (const float*)d_in[29];
    const float* bdown = (const float*)d_in[30];
    float* outp = (float*)d_out;

    float *h1, *qm, *km, *vm, *mc, *pr, *grad, *Mm, *Sm, *h2, *qh, *kh, *vh;
    float *sc, *at, *ao, *gt, *o, *h3, *f1, *f2;
    __nv_bfloat16 *wqm, *wkm, *wvm, *wq, *wk, *wv, *wo, *wg, *wgate, *wup, *wdown;
    __nv_bfloat16 *tM, *tkm, *tpr;
    cudaGetSymbolAddress((void**)&h1, g_h1);
    cudaGetSymbolAddress((void**)&qm, g_qm);
    cudaGetSymbolAddress((void**)&km, g_km);
    cudaGetSymbolAddress((void**)&vm, g_vm);
    cudaGetSymbolAddress((void**)&mc, g_mc);
    cudaGetSymbolAddress((void**)&pr, g_pr);
    cudaGetSymbolAddress((void**)&grad, g_grad);
    cudaGetSymbolAddress((void**)&Mm, g_Mst);
    cudaGetSymbolAddress((void**)&Sm, g_Sst);
    cudaGetSymbolAddress((void**)&h2, g_h2);
    cudaGetSymbolAddress((void**)&qh, g_qh);
    cudaGetSymbolAddress((void**)&kh, g_kh);
    cudaGetSymbolAddress((void**)&vh, g_vh);
    cudaGetSymbolAddress((void**)&sc, g_sc);
    cudaGetSymbolAddress((void**)&at, g_at);
    cudaGetSymbolAddress((void**)&ao, g_ao);
    cudaGetSymbolAddress((void**)&gt, g_gt);
    cudaGetSymbolAddress((void**)&o,  g_o);
    cudaGetSymbolAddress((void**)&h3, g_h3);
    cudaGetSymbolAddress((void**)&f1, g_f1);
    cudaGetSymbolAddress((void**)&f2, g_f2);
    cudaGetSymbolAddress((void**)&wqm, w_qm);
    cudaGetSymbolAddress((void**)&wkm, w_km);
    cudaGetSymbolAddress((void**)&wvm, w_vm);
    cudaGetSymbolAddress((void**)&wq,  w_q);
    cudaGetSymbolAddress((void**)&wk,  w_k);
    cudaGetSymbolAddress((void**)&wv,  w_v);
    cudaGetSymbolAddress((void**)&wo,  w_o);
    cudaGetSymbolAddress((void**)&wg,  w_g);
    cudaGetSymbolAddress((void**)&wgate, w_gate);
    cudaGetSymbolAddress((void**)&wup,   w_up);
    cudaGetSymbolAddress((void**)&wdown, w_down);
    cudaGetSymbolAddress((void**)&tM,  t_M);
    cudaGetSymbolAddress((void**)&tkm, t_km);
    cudaGetSymbolAddress((void**)&tpr, t_pr);

    static int smem_set = 0;
    if (!smem_set) {
        cudaFuncSetAttribute(tmma_k<0,0>, cudaFuncAttributeMaxDynamicSharedMemorySize, TM_SMEM);
        cudaFuncSetAttribute(tmma_k<1,0>, cudaFuncAttributeMaxDynamicSharedMemorySize, TM_SMEM);
        cudaFuncSetAttribute(tmma_k<2,0>, cudaFuncAttributeMaxDynamicSharedMemorySize, TM_SMEM);
        cudaFuncSetAttribute(tmma_k<3,0>, cudaFuncAttributeMaxDynamicSharedMemorySize, TM_SMEM);
        cudaFuncSetAttribute(tmma_k<0,1>, cudaFuncAttributeMaxDynamicSharedMemorySize, TM_SMEM);
        smem_set = 1;
    }

    const long ND  = (long)B_ * D_ * D_;
    const long NBD = (long)BC_ * D_;
    const long NBF = (long)BC_ * FF_;
    const long sCD = (long)C_ * D_;
    const long sDD = (long)D_ * D_;
    const long sDC = (long)D_ * C_;
    const long LDD  = (long)D_ * D_;        // hi|lo offset for DxD weights
    const long LFD  = (long)FF_ * D_;
    const long LND  = ND;                   // hi|lo offset for tM
    const long LDC4 = (long)B_ * D_ * C_;   // hi|lo offset for tkm/tpr

    zero2_k<<<(unsigned)(ND / 256), 256>>>(Mm, Sm);

    // ---- one-time weight transpose+convert ([K,N] fp32 -> [N,K] bf16 hi|lo) ----
    dim3 t256(256);
    tconv2_k<<<dim3(D_/32,  D_/32, 1), t256>>>(Wqm,   wqm,   wqm + LDD,   D_,  D_,  0, 0);
    tconv2_k<<<dim3(D_/32,  D_/32, 1), t256>>>(Wkm,   wkm,   wkm + LDD,   D_,  D_,  0, 0);
    tconv2_k<<<dim3(D_/32,  D_/32, 1), t256>>>(Wvm,   wvm,   wvm + LDD,   D_,  D_,  0, 0);
    tconv2_k<<<dim3(D_/32,  D_/32, 1), t256>>>(Wq,    wq,    wq  + LDD,   D_,  D_,  0, 0);
    tconv2_k<<<dim3(D_/32,  D_/32, 1), t256>>>(Wk,    wk,    wk  + LDD,   D_,  D_,  0, 0);
    tconv2_k<<<dim3(D_/32,  D_/32, 1), t256>>>(Wv,    wv,    wv  + LDD,   D_,  D_,  0, 0);
    tconv2_k<<<dim3(D_/32,  D_/32, 1), t256>>>(Wo,    wo,    wo  + LDD,   D_,  D_,  0, 0);
    tconv2_k<<<dim3(D_/32,  D_/32, 1), t256>>>(Wg,    wg,    wg  + LDD,   D_,  D_,  0, 0);
    tconv2_k<<<dim3(FF_/32, D_/32, 1), t256>>>(Wgate, wgate, wgate + LFD, D_,  FF_, 0, 0);
    tconv2_k<<<dim3(FF_/32, D_/32, 1), t256>>>(Wup,   wup,   wup   + LFD, D_,  FF_, 0, 0);
    tconv2_k<<<dim3(D_/32, FF_/32, 1), t256>>>(Wdown, wdown, wdown + LFD, FF_, D_,  0, 0);

    dim3 gp(D_ / 128, BC_ / 128, 1);
    dim3 gf(FF_ / 128, BC_ / 128, 1);
    dim3 gb(D_ / 128, C_ / 128, B_);
    dim3 gg(D_ / 128, D_ / 128, B_);

    for (int t = 0; t < NC_; t++) {
        int c0 = t * C_;
        // --- neural memory ---
        tconv2_k<<<dim3(D_/32, D_/32, B_), t256>>>(Mm, tM, tM + LND, D_, D_, sDD, sDD);
        ln_k<0><<<BC_, 256>>>(x, nullptr, g1, b1, h1, c0);
        tmma_k<0,0><<<gp, 256, TM_SMEM>>>(h1, nullptr, wqm, wqm + LDD, qm, nullptr, D_, D_, 0, 0, 0, 1.f);
        tmma_k<0,0><<<gp, 256, TM_SMEM>>>(h1, nullptr, wkm, wkm + LDD, km, nullptr, D_, D_, 0, 0, 0, 1.f);
        rownorm_k<<<BC_, 256>>>(km);
        tmma_k<0,0><<<gp, 256, TM_SMEM>>>(h1, nullptr, wvm, wvm + LDD, vm, nullptr, D_, D_, 0, 0, 0, 1.f);
        tmma_k<0,0><<<gb, 256, TM_SMEM>>>(qm, nullptr, tM, tM + LND, mc, nullptr, D_, D_, sCD, sDD, sCD, 1.f);
        tmma_k<0,0><<<gb, 256, TM_SMEM>>>(km, nullptr, tM, tM + LND, pr, nullptr, D_, D_, sCD, sDD, sCD, 1.f);
        sub_k<<<(unsigned)(NBD / 256), 256>>>(pr, vm);
        tconv2_k<<<dim3(D_/32, C_/32, B_), t256>>>(km, tkm, tkm + LDC4, C_, D_, sCD, sDC);
        tconv2_k<<<dim3(D_/32, C_/32, B_), t256>>>(pr, tpr, tpr + LDC4, C_, D_, sCD, sDC);
        tmma_k<0,1><<<gg, 256, TM_SMEM>>>(tkm, tkm + LDC4, tpr, tpr + LDC4, grad, nullptr, D_, C_, sDC, sDC, sDD, 1.f / C_);
        update_k<<<(unsigned)(ND / 256), 256>>>(Mm, Sm, grad, lr, mom, fg);

        // --- attention with persistent tokens ---
        ln_k<1><<<BC_, 256>>>(x, mc, g2, b2, h2, c0);
        tmma_k<1,0><<<gp, 256, TM_SMEM>>>(h2, nullptr, wq, wq + LDD, qh, bq, D_, D_, 0, 0, 0, 1.f);
        tmma_k<1,0><<<gp, 256, TM_SMEM>>>(h2, nullptr, wk, wk + LDD, kh, bk, D_, D_, 0, 0, 0, 1.f);
        tmma_k<1,0><<<gp, 256, TM_SMEM>>>(h2, nullptr, wv, wv + LDD, vh, bv, D_, D_, 0, 0, 0, 1.f);
        attn_scores_k<<<dim3(9, 8, BH_), 256>>>(qh, kh, pk, sc);
        softmax_k<<<BH_ * C_, 256>>>(sc);
        attn_av_k<<<dim3(8, BH_), 256>>>(sc, vh, pv, at);
        tmma_k<1,0><<<gp, 256, TM_SMEM>>>(at, nullptr, wo, wo + LDD, ao, bo, D_, D_, 0, 0, 0, 1.f);
        tmma_k<2,0><<<gp, 256, TM_SMEM>>>(mc, nullptr, wg, wg + LDD, gt, bg, D_, D_, 0, 0, 0, 1.f);
        combine_k<<<(unsigned)(NBD / 256), 256>>>(x, gt, ao, mc, o, c0);

        // --- gated FFN ---
        ln_k<2><<<BC_, 256>>>(o, nullptr, g3, b3, h3, 0);
        tmma_k<1,0><<<gf, 256, TM_SMEM>>>(h3, nullptr, wgate, wgate + LFD, f1, bgate, FF_, D_, 0, 0, 0, 1.f);
        tmma_k<1,0><<<gf, 256, TM_SMEM>>>(h3, nullptr, wup,   wup   + LFD, f2, bup,   FF_, D_, 0, 0, 0, 1.f);
        silu_mul_k<<<(unsigned)(NBF / 256), 256>>>(f1, f2);
        tmma_k<3,0><<<gp, 256, TM_SMEM>>>(f1, nullptr, wdown, wdown + LFD, o, bdown, D_, FF_, 0, 0, 0, 1.f);

        scatter_k<<<(unsigned)(NBD / 256), 256>>>(o, outp, c0);
    }
}

// round 6
// speedup vs baseline: 2.4955x; 2.0251x over previous
#include <cuda_runtime.h>
#include <cuda_bf16.h>
#include <math.h>
#include <stdint.h>

#define D_  1024
#define H_  16
#define DH_ 64
#define P_  16
#define C_  512
#define B_  4
#define S_  4096
#define FF_ 4096
#define NC_ 8
#define BC_ (B_*C_)      /* 2048 */
#define PC_ (P_+C_)      /* 528  */
#define BH_ (B_*H_)      /* 64   */

// ------------------------- scratch (device globals) -------------------------
__device__ float g_h1[BC_*D_];
__device__ float g_qm[BC_*D_];
__device__ float g_km[BC_*D_];
__device__ float g_vm[BC_*D_];
__device__ float g_mc[BC_*D_];
__device__ float g_pr[BC_*D_];
__device__ float g_grad[B_*D_*D_];
__device__ float g_Mst[B_*D_*D_];
__device__ float g_Sst[B_*D_*D_];
__device__ float g_h2[BC_*D_];
__device__ float g_qh[BC_*D_];
__device__ float g_kh[BC_*D_];
__device__ float g_vh[BC_*D_];
__device__ float g_sc[BH_*C_*PC_];
__device__ float g_at[BC_*D_];
__device__ float g_ao[BC_*D_];
__device__ float g_gt[BC_*D_];
__device__ float g_o [BC_*D_];
__device__ float g_h3[BC_*D_];
__device__ float g_f1[BC_*FF_];
__device__ float g_f2[BC_*FF_];

// tf32-rounded fp32 operand buffers ([N,K] K-major for mma B operand)
__device__ float w_qm[D_*D_];
__device__ float w_km[D_*D_];
__device__ float w_vm[D_*D_];
__device__ float w_q [D_*D_];
__device__ float w_k [D_*D_];
__device__ float w_v [D_*D_];
__device__ float w_o [D_*D_];
__device__ float w_g [D_*D_];
__device__ float w_gate[(long)FF_*D_];
__device__ float w_up  [(long)FF_*D_];
__device__ float w_down[(long)D_*FF_];
__device__ float t_M [B_*D_*D_];        // M^T per batch
__device__ float t_km[(long)B_*D_*C_];  // km^T
__device__ float t_pr[(long)B_*D_*C_];  // (pred-vm)^T

// ----------------------------- PTX helpers ----------------------------------
__device__ __forceinline__ uint32_t smem_u32(const void* p) {
    uint32_t a;
    asm("{ .reg .u64 t; cvta.to.shared.u64 t, %1; cvt.u32.u64 %0, t; }"
        : "=r"(a) : "l"(p));
    return a;
}
__device__ __forceinline__ uint32_t tf32_rna(float f) {
    uint32_t u;
    asm("cvt.rna.tf32.f32 %0, %1;" : "=r"(u) : "f"(f));
    return u;
}
#define CP_ASYNC16(dst, src)                                                     \
    asm volatile("cp.async.cg.shared.global [%0], [%1], 16;" :: "r"(dst), "l"(src))
#define CP_COMMIT()  asm volatile("cp.async.commit_group;")
#define CP_WAIT(n)   asm volatile("cp.async.wait_group %0;" :: "n"(n))

#define MMAT(d, a, b0, b1)                                                       \
    asm volatile(                                                                \
        "mma.sync.aligned.m16n8k8.row.col.f32.tf32.tf32.f32 "                    \
        "{%0,%1,%2,%3}, {%4,%5,%6,%7}, {%8,%9}, {%0,%1,%2,%3};"                  \
        : "+f"((d)[0]), "+f"((d)[1]), "+f"((d)[2]), "+f"((d)[3])                 \
        : "r"((a)[0]), "r"((a)[1]), "r"((a)[2]), "r"((a)[3]), "r"(b0), "r"(b1))

// ------------------- TF32 HMMA GEMM, cp.async 3-stage -----------------------
// C[M,N] = epi(alpha * A[M,K] @ B[N,K]^T). A fp32 (cvt.rna on fragment load),
// B fp32 pre-rounded to tf32. CTA tile 128x128, K-step 32, 3-stage cp.async.
// EPI: 0 = alpha*acc ; 1 = acc+bias ; 2 = sigmoid(acc+bias) ; 3 = C += acc+bias
#define LDT_ 36
#define TILE_F (128 * LDT_)
#define TM_SMEM (3 * 2 * TILE_F * 4)   /* 110592 B */

template<int EPI>
__global__ __launch_bounds__(256) void tmma_k(
    const float* __restrict__ A, const float* __restrict__ Bw,
    float* __restrict__ Cm, const float* __restrict__ bias,
    int Ncols, int K, long sA, long sB, long sC, float alpha)
{
    extern __shared__ float smf[];
    const int bz = blockIdx.z;
    A  += bz * sA;
    Bw += bz * sB;
    Cm += bz * sC;

    const int tid = threadIdx.x, warp = tid >> 5, lane = tid & 31;
    const int n0 = blockIdx.x * 128, m0 = blockIdx.y * 128;
    const int mo = (warp >> 2) * 64, no = (warp & 3) * 32;
    const int grp = lane >> 2, tig = lane & 3;

    const int lr = tid >> 3;           // loader row 0..31 (x4 iters -> 128)
    const int lc = (tid & 7) << 2;     // loader col (floats)

    float acc[4][4][4] = {};
    const int KT = K >> 5;

    // ---- prologue: issue stages 0,1 ----
#pragma unroll
    for (int s = 0; s < 2; s++) {
        const int k0 = s << 5;
        float* As = smf + s * 2 * TILE_F;
        float* Bs = As + TILE_F;
#pragma unroll
        for (int i = 0; i < 4; i++) {
            int r = lr + 32 * i;
            CP_ASYNC16(smem_u32(&As[r * LDT_ + lc]), A  + (long)(m0 + r) * K + k0 + lc);
            CP_ASYNC16(smem_u32(&Bs[r * LDT_ + lc]), Bw + (long)(n0 + r) * K + k0 + lc);
        }
        CP_COMMIT();
    }

    for (int kt = 0; kt < KT; kt++) {
        if (kt + 1 < KT) { CP_WAIT(1); } else { CP_WAIT(0); }
        __syncthreads();

        // ---- issue stage kt+2 ----
        if (kt + 2 < KT) {
            const int s = (kt + 2) % 3;
            const int k0 = (kt + 2) << 5;
            float* As = smf + s * 2 * TILE_F;
            float* Bs = As + TILE_F;
#pragma unroll
            for (int i = 0; i < 4; i++) {
                int r = lr + 32 * i;
                CP_ASYNC16(smem_u32(&As[r * LDT_ + lc]), A  + (long)(m0 + r) * K + k0 + lc);
                CP_ASYNC16(smem_u32(&Bs[r * LDT_ + lc]), Bw + (long)(n0 + r) * K + k0 + lc);
            }
            CP_COMMIT();
        }

        // ---- compute stage kt ----
        const float* As = smf + (kt % 3) * 2 * TILE_F;
        const float* Bs = As + TILE_F;
#pragma unroll
        for (int k8 = 0; k8 < 4; k8++) {
            const int kc = k8 * 8 + tig;
            uint32_t a[4][4], b[4][2];
#pragma unroll
            for (int mt = 0; mt < 4; mt++) {
                const int m = mo + mt * 16 + grp;
                a[mt][0] = tf32_rna(As[m * LDT_ + kc]);
                a[mt][1] = tf32_rna(As[(m + 8) * LDT_ + kc]);
                a[mt][2] = tf32_rna(As[m * LDT_ + kc + 4]);
                a[mt][3] = tf32_rna(As[(m + 8) * LDT_ + kc + 4]);
            }
#pragma unroll
            for (int j = 0; j < 4; j++) {
                const int n = no + j * 8 + grp;
                b[j][0] = __float_as_uint(Bs[n * LDT_ + kc]);
                b[j][1] = __float_as_uint(Bs[n * LDT_ + kc + 4]);
            }
#pragma unroll
            for (int mt = 0; mt < 4; mt++)
#pragma unroll
                for (int j = 0; j < 4; j++)
                    MMAT(acc[mt][j], a[mt], b[j][0], b[j][1]);
        }
    }

    // ------------------------------ epilogue --------------------------------
#pragma unroll
    for (int mt = 0; mt < 4; mt++) {
#pragma unroll
        for (int j = 0; j < 4; j++) {
            int row = m0 + mo + mt * 16 + grp;
            int col = n0 + no + j * 8 + tig * 2;
#pragma unroll
            for (int hh = 0; hh < 2; hh++) {
                int r = row + hh * 8;
                float v0 = acc[mt][j][hh * 2 + 0] * alpha;
                float v1 = acc[mt][j][hh * 2 + 1] * alpha;
                float* cp = Cm + (long)r * Ncols + col;
                if (EPI >= 1) {
                    float2 bv = *(const float2*)(bias + col);
                    v0 += bv.x; v1 += bv.y;
                }
                if (EPI == 2) {
                    v0 = 1.f / (1.f + expf(-v0));
                    v1 = 1.f / (1.f + expf(-v1));
                }
                if (EPI == 3) {
                    float2 c = *(float2*)cp;
                    v0 += c.x; v1 += c.y;
                }
                float2 o; o.x = v0; o.y = v1;
                *(float2*)cp = o;
            }
        }
    }
}

// ------------- transpose + tf32-round (fp32 -> tf32-in-fp32) ----------------
__global__ __launch_bounds__(256) void tconv_k(
    const float* __restrict__ in, float* __restrict__ out,
    int R, int Cc, long sIn, long sOut)
{
    __shared__ float t[32][33];
    in  += (long)blockIdx.z * sIn;
    out += (long)blockIdx.z * sOut;
    int r0 = blockIdx.y * 32, c0 = blockIdx.x * 32;
    int tx = threadIdx.x & 31, ty = threadIdx.x >> 5;
#pragma unroll
    for (int i = 0; i < 32; i += 8)
        t[ty + i][tx] = in[(long)(r0 + ty + i) * Cc + c0 + tx];
    __syncthreads();
#pragma unroll
    for (int i = 0; i < 32; i += 8)
        out[(long)(c0 + ty + i) * R + r0 + tx] = __uint_as_float(tf32_rna(t[tx][ty + i]));
}

// ------------------------------- LayerNorm ----------------------------------
template<int MODE>
__global__ __launch_bounds__(256) void ln_k(
    const float* __restrict__ src, const float* __restrict__ res,
    const float* __restrict__ gam, const float* __restrict__ bet,
    float* __restrict__ out, int c0)
{
    int r = blockIdx.x;
    const float* p;
    if (MODE == 2) p = src + (long)r * D_;
    else { int b = r / C_, i = r % C_; p = src + ((long)b * S_ + c0 + i) * D_; }

    int tid = threadIdx.x;
    float v[4], s = 0.f, sq = 0.f;
#pragma unroll
    for (int k = 0; k < 4; k++) {
        int c = tid + k * 256;
        float xv = p[c];
        if (MODE == 1) xv += res[(long)r * D_ + c];
        v[k] = xv; s += xv; sq += xv * xv;
    }
    __shared__ float shs[8], shq[8];
#pragma unroll
    for (int o = 16; o; o >>= 1) {
        s  += __shfl_xor_sync(0xffffffffu, s,  o);
        sq += __shfl_xor_sync(0xffffffffu, sq, o);
    }
    if ((tid & 31) == 0) { shs[tid >> 5] = s; shq[tid >> 5] = sq; }
    __syncthreads();
    s = 0.f; sq = 0.f;
#pragma unroll
    for (int i = 0; i < 8; i++) { s += shs[i]; sq += shq[i]; }
    float m  = s * (1.f / D_);
    float var = sq * (1.f / D_) - m * m;
    float rs = rsqrtf(var + 1e-5f);
#pragma unroll
    for (int k = 0; k < 4; k++) {
        int c = tid + k * 256;
        out[(long)r * D_ + c] = (v[k] - m) * rs * gam[c] + bet[c];
    }
}

__global__ __launch_bounds__(256) void rownorm_k(float* __restrict__ km)
{
    int r = blockIdx.x, tid = threadIdx.x;
    float* p = km + (long)r * D_;
    float v[4], sq = 0.f;
#pragma unroll
    for (int k = 0; k < 4; k++) { int c = tid + k * 256; v[k] = p[c]; sq += v[k] * v[k]; }
    __shared__ float shq[8];
#pragma unroll
    for (int o = 16; o; o >>= 1) sq += __shfl_xor_sync(0xffffffffu, sq, o);
    if ((tid & 31) == 0) shq[tid >> 5] = sq;
    __syncthreads();
    sq = 0.f;
#pragma unroll
    for (int i = 0; i < 8; i++) sq += shq[i];
    float rs = rsqrtf(sq + 1e-6f);
#pragma unroll
    for (int k = 0; k < 4; k++) { int c = tid + k * 256; p[c] = v[k] * rs; }
}

// -------------------------------- attention ---------------------------------
__global__ __launch_bounds__(256) void attn_scores_k(
    const float* __restrict__ qh, const float* __restrict__ kh,
    const float* __restrict__ pk, float* __restrict__ sc)
{
    int bh = blockIdx.z; int b = bh >> 4, h = bh & 15;
    int i0 = blockIdx.y * 64, j0 = blockIdx.x * 64;
    __shared__ float Qs[64][16];
    __shared__ float Ks[64][16];
    int tid = threadIdx.x;
    int ty = tid >> 4, tx = tid & 15;
    float acc[4][4] = {};
    for (int k0 = 0; k0 < DH_; k0 += 16) {
        for (int t = tid; t < 1024; t += 256) {
            int r = t >> 4, c = t & 15;
            Qs[r][c] = qh[(((long)b * C_ + i0 + r) * H_ + h) * DH_ + k0 + c];
            int j = j0 + r;
            float kv = 0.f;
            if (j < PC_) {
                kv = (j < P_) ? pk[((long)j * H_ + h) * DH_ + k0 + c]
                              : kh[(((long)b * C_ + (j - P_)) * H_ + h) * DH_ + k0 + c];
            }
            Ks[r][c] = kv;
        }
        __syncthreads();
#pragma unroll
        for (int kk = 0; kk < 16; kk++) {
            float qr[4], kr[4];
#pragma unroll
            for (int i = 0; i < 4; i++) qr[i] = Qs[ty * 4 + i][kk];
#pragma unroll
            for (int j = 0; j < 4; j++) kr[j] = Ks[tx * 4 + j][kk];
#pragma unroll
            for (int i = 0; i < 4; i++)
#pragma unroll
                for (int j = 0; j < 4; j++) acc[i][j] += qr[i] * kr[j];
        }
        __syncthreads();
    }
#pragma unroll
    for (int i = 0; i < 4; i++) {
        int gi = i0 + ty * 4 + i;
#pragma unroll
        for (int j = 0; j < 4; j++) {
            int gj = j0 + tx * 4 + j;
            if (gj < PC_) {
                float m = (gj < P_ || (gj - P_) <= gi) ? 0.f : -1e9f;
                sc[((long)bh * C_ + gi) * PC_ + gj] = acc[i][j] * 0.125f + m;
            }
        }
    }
}

__global__ __launch_bounds__(256) void softmax_k(float* __restrict__ sc)
{
    float* row = sc + (long)blockIdx.x * PC_;
    int tid = threadIdx.x;
    __shared__ float sh[8];
    float mx = -1e30f;
    for (int c = tid; c < PC_; c += 256) mx = fmaxf(mx, row[c]);
#pragma unroll
    for (int o = 16; o; o >>= 1) mx = fmaxf(mx, __shfl_xor_sync(0xffffffffu, mx, o));
    if ((tid & 31) == 0) sh[tid >> 5] = mx;
    __syncthreads();
    mx = sh[0];
#pragma unroll
    for (int i = 1; i < 8; i++) mx = fmaxf(mx, sh[i]);
    float s = 0.f;
    for (int c = tid; c < PC_; c += 256) { float e = expf(row[c] - mx); row[c] = e; s += e; }
    __syncthreads();
#pragma unroll
    for (int o = 16; o; o >>= 1) s += __shfl_xor_sync(0xffffffffu, s, o);
    if ((tid & 31) == 0) sh[tid >> 5] = s;
    __syncthreads();
    s = 0.f;
#pragma unroll
    for (int i = 0; i < 8; i++) s += sh[i];
    float inv = 1.f / s;
    for (int c = tid; c < PC_; c += 256) row[c] *= inv;
}

__global__ __launch_bounds__(256) void attn_av_k(
    const float* __restrict__ sc, const float* __restrict__ vh,
    const float* __restrict__ pv, float* __restrict__ outp)
{
    int bh = blockIdx.y; int b = bh >> 4, h = bh & 15;
    int i0 = blockIdx.x * 64;
    __shared__ float As[64][16];
    __shared__ float Vs[16][64];
    int tid = threadIdx.x;
    int ty = tid >> 4, tx = tid & 15;
    float acc[4][4] = {};
    for (int k0 = 0; k0 < PC_; k0 += 16) {
        for (int t = tid; t < 1024; t += 256) {
            int r = t >> 4, c = t & 15;
            As[r][c] = sc[((long)bh * C_ + i0 + r) * PC_ + k0 + c];
        }
        for (int t = tid; t < 1024; t += 256) {
            int kk = t >> 6, d = t & 63;
            int j = k0 + kk;
            Vs[kk][d] = (j < P_) ? pv[((long)j * H_ + h) * DH_ + d]
                                 : vh[(((long)b * C_ + (j - P_)) * H_ + h) * DH_ + d];
        }
        __syncthreads();
#pragma unroll
        for (int kk = 0; kk < 16; kk++) {
            float ar[4], vr[4];
#pragma unroll
            for (int i = 0; i < 4; i++) ar[i] = As[ty * 4 + i][kk];
#pragma unroll
            for (int j = 0; j < 4; j++) vr[j] = Vs[kk][tx * 4 + j];
#pragma unroll
            for (int i = 0; i < 4; i++)
#pragma unroll
                for (int j = 0; j < 4; j++) acc[i][j] += ar[i] * vr[j];
        }
        __syncthreads();
    }
#pragma unroll
    for (int i = 0; i < 4; i++) {
        int gi = i0 + ty * 4 + i;
#pragma unroll
        for (int j = 0; j < 4; j++) {
            outp[((long)b * C_ + gi) * D_ + h * DH_ + tx * 4 + j] = acc[i][j];
        }
    }
}

// ------------------------------- elementwise --------------------------------
__global__ void zero2_k(float* __restrict__ a, float* __restrict__ b)
{
    long i = (long)blockIdx.x * 256 + threadIdx.x;
    a[i] = 0.f; b[i] = 0.f;
}

__global__ void sub_k(float* __restrict__ p, const float* __restrict__ v)
{
    long i = (long)blockIdx.x * 256 + threadIdx.x;
    p[i] -= v[i];
}

__global__ void update_k(float* __restrict__ M, float* __restrict__ S,
                         const float* __restrict__ grad,
                         const float* __restrict__ lr,
                         const float* __restrict__ mom,
                         const float* __restrict__ fg)
{
    long i = (long)blockIdx.x * 256 + threadIdx.x;
    float th = 1.f / (1.f + expf(-lr[0]));
    float et = 1.f / (1.f + expf(-mom[0]));
    float al = 1.f / (1.f + expf(-fg[0]));
    float s = et * S[i] - th * grad[i];
    S[i] = s;
    M[i] = (1.f - al) * M[i] + s;
}

__global__ void combine_k(const float* __restrict__ x, const float* __restrict__ gt,
                          const float* __restrict__ ao, const float* __restrict__ mc,
                          float* __restrict__ o, int c0)
{
    long idx = (long)blockIdx.x * 256 + threadIdx.x;
    int r = (int)(idx / D_), c = (int)(idx % D_);
    int b = r / C_, i = r % C_;
    float xv = x[((long)b * S_ + c0 + i) * D_ + c];
    float gv = gt[idx];
    o[idx] = xv + gv * ao[idx] + (1.f - gv) * mc[idx];
}

__global__ void silu_mul_k(float* __restrict__ f1, const float* __restrict__ f2)
{
    long i = (long)blockIdx.x * 256 + threadIdx.x;
    float v = f1[i];
    f1[i] = v / (1.f + expf(-v)) * f2[i];
}

__global__ void scatter_k(const float* __restrict__ o, float* __restrict__ outp, int c0)
{
    long idx = (long)blockIdx.x * 256 + threadIdx.x;
    int r = (int)(idx / D_), c = (int)(idx % D_);
    int b = r / C_, i = r % C_;
    outp[((long)b * S_ + c0 + i) * D_ + c] = o[idx];
}

// --------------------------------- launch -----------------------------------
extern "C" void kernel_launch(void* const* d_in, const int* in_sizes, int n_in,
                              void* d_out, int out_size)
{
    const float* x     = (const float*)d_in[0];
    const float* g1    = (const float*)d_in[1];
    const float* b1    = (const float*)d_in[2];
    const float* g2    = (const float*)d_in[3];
    const float* b2    = (const float*)d_in[4];
    const float* g3    = (const float*)d_in[5];
    const float* b3    = (const float*)d_in[6];
    const float* Wqm   = (const float*)d_in[7];
    const float* Wkm   = (const float*)d_in[8];
    const float* Wvm   = (const float*)d_in[9];
    const float* lr    = (const float*)d_in[10];
    const float* mom   = (const float*)d_in[11];
    const float* fg    = (const float*)d_in[12];
    const float* Wq    = (const float*)d_in[13];
    const float* bq    = (const float*)d_in[14];
    const float* Wk    = (const float*)d_in[15];
    const float* bk    = (const float*)d_in[16];
    const float* Wv    = (const float*)d_in[17];
    const float* bv    = (const float*)d_in[18];
    const float* Wo    = (const float*)d_in[19];
    const float* bo    = (const float*)d_in[20];
    const float* pk    = (const float*)d_in[21];
    const float* pv    = (const float*)d_in[22];
    const float* Wg    = (const float*)d_in[23];
    const float* bg    = (const float*)d_in[24];
    const float* Wgate = (const float*)d_in[25];
    const float* bgate = (const float*)d_in[26];
    const float* Wup   = (const float*)d_in[27];
    const float* bup   = (const float*)d_in[28];
    const float* Wdown = (const float*)d_in[29];
    const float* bdown = (const float*)d_in[30];
    float* outp = (float*)d_out;

    float *h1, *qm, *km, *vm, *mc, *pr, *grad, *Mm, *Sm, *h2, *qh, *kh, *vh;
    float *sc, *at, *ao, *gt, *o, *h3, *f1, *f2;
    float *wqm, *wkm, *wvm, *wq, *wk, *wv, *wo, *wg, *wgate, *wup, *wdown;
    float *tM, *tkm, *tpr;
    cudaGetSymbolAddress((void**)&h1, g_h1);
    cudaGetSymbolAddress((void**)&qm, g_qm);
    cudaGetSymbolAddress((void**)&km, g_km);
    cudaGetSymbolAddress((void**)&vm, g_vm);
    cudaGetSymbolAddress((void**)&mc, g_mc);
    cudaGetSymbolAddress((void**)&pr, g_pr);
    cudaGetSymbolAddress((void**)&grad, g_grad);
    cudaGetSymbolAddress((void**)&Mm, g_Mst);
    cudaGetSymbolAddress((void**)&Sm, g_Sst);
    cudaGetSymbolAddress((void**)&h2, g_h2);
    cudaGetSymbolAddress((void**)&qh, g_qh);
    cudaGetSymbolAddress((void**)&kh, g_kh);
    cudaGetSymbolAddress((void**)&vh, g_vh);
    cudaGetSymbolAddress((void**)&sc, g_sc);
    cudaGetSymbolAddress((void**)&at, g_at);
    cudaGetSymbolAddress((void**)&ao, g_ao);
    cudaGetSymbolAddress((void**)&gt, g_gt);
    cudaGetSymbolAddress((void**)&o,  g_o);
    cudaGetSymbolAddress((void**)&h3, g_h3);
    cudaGetSymbolAddress((void**)&f1, g_f1);
    cudaGetSymbolAddress((void**)&f2, g_f2);
    cudaGetSymbolAddress((void**)&wqm, w_qm);
    cudaGetSymbolAddress((void**)&wkm, w_km);
    cudaGetSymbolAddress((void**)&wvm, w_vm);
    cudaGetSymbolAddress((void**)&wq,  w_q);
    cudaGetSymbolAddress((void**)&wk,  w_k);
    cudaGetSymbolAddress((void**)&wv,  w_v);
    cudaGetSymbolAddress((void**)&wo,  w_o);
    cudaGetSymbolAddress((void**)&wg,  w_g);
    cudaGetSymbolAddress((void**)&wgate, w_gate);
    cudaGetSymbolAddress((void**)&wup,   w_up);
    cudaGetSymbolAddress((void**)&wdown, w_down);
    cudaGetSymbolAddress((void**)&tM,  t_M);
    cudaGetSymbolAddress((void**)&tkm, t_km);
    cudaGetSymbolAddress((void**)&tpr, t_pr);

    cudaFuncSetAttribute(tmma_k<0>, cudaFuncAttributeMaxDynamicSharedMemorySize, TM_SMEM);
    cudaFuncSetAttribute(tmma_k<1>, cudaFuncAttributeMaxDynamicSharedMemorySize, TM_SMEM);
    cudaFuncSetAttribute(tmma_k<2>, cudaFuncAttributeMaxDynamicSharedMemorySize, TM_SMEM);
    cudaFuncSetAttribute(tmma_k<3>, cudaFuncAttributeMaxDynamicSharedMemorySize, TM_SMEM);

    const long ND  = (long)B_ * D_ * D_;
    const long NBD = (long)BC_ * D_;
    const long NBF = (long)BC_ * FF_;
    const long sCD = (long)C_ * D_;
    const long sDD = (long)D_ * D_;
    const long sDC = (long)D_ * C_;

    zero2_k<<<(unsigned)(ND / 256), 256>>>(Mm, Sm);

    // ---- one-time weight transpose + tf32 rounding ----
    dim3 t256(256);
    tconv_k<<<dim3(D_/32,  D_/32, 1), t256>>>(Wqm,   wqm,   D_,  D_,  0, 0);
    tconv_k<<<dim3(D_/32,  D_/32, 1), t256>>>(Wkm,   wkm,   D_,  D_,  0, 0);
    tconv_k<<<dim3(D_/32,  D_/32, 1), t256>>>(Wvm,   wvm,   D_,  D_,  0, 0);
    tconv_k<<<dim3(D_/32,  D_/32, 1), t256>>>(Wq,    wq,    D_,  D_,  0, 0);
    tconv_k<<<dim3(D_/32,  D_/32, 1), t256>>>(Wk,    wk,    D_,  D_,  0, 0);
    tconv_k<<<dim3(D_/32,  D_/32, 1), t256>>>(Wv,    wv,    D_,  D_,  0, 0);
    tconv_k<<<dim3(D_/32,  D_/32, 1), t256>>>(Wo,    wo,    D_,  D_,  0, 0);
    tconv_k<<<dim3(D_/32,  D_/32, 1), t256>>>(Wg,    wg,    D_,  D_,  0, 0);
    tconv_k<<<dim3(FF_/32, D_/32, 1), t256>>>(Wgate, wgate, D_,  FF_, 0, 0);
    tconv_k<<<dim3(FF_/32, D_/32, 1), t256>>>(Wup,   wup,   D_,  FF_, 0, 0);
    tconv_k<<<dim3(D_/32, FF_/32, 1), t256>>>(Wdown, wdown, FF_, D_,  0, 0);

    dim3 gp(D_ / 128, BC_ / 128, 1);
    dim3 gf(FF_ / 128, BC_ / 128, 1);
    dim3 gb(D_ / 128, C_ / 128, B_);
    dim3 gg(D_ / 128, D_ / 128, B_);

    for (int t = 0; t < NC_; t++) {
        int c0 = t * C_;
        // --- neural memory ---
        tconv_k<<<dim3(D_/32, D_/32, B_), t256>>>(Mm, tM, D_, D_, sDD, sDD);
        ln_k<0><<<BC_, 256>>>(x, nullptr, g1, b1, h1, c0);
        tmma_k<0><<<gp, 256, TM_SMEM>>>(h1, wqm, qm, nullptr, D_, D_, 0, 0, 0, 1.f);
        tmma_k<0><<<gp, 256, TM_SMEM>>>(h1, wkm, km, nullptr, D_, D_, 0, 0, 0, 1.f);
        rownorm_k<<<BC_, 256>>>(km);
        tmma_k<0><<<gp, 256, TM_SMEM>>>(h1, wvm, vm, nullptr, D_, D_, 0, 0, 0, 1.f);
        tmma_k<0><<<gb, 256, TM_SMEM>>>(qm, tM, mc, nullptr, D_, D_, sCD, sDD, sCD, 1.f);
        tmma_k<0><<<gb, 256, TM_SMEM>>>(km, tM, pr, nullptr, D_, D_, sCD, sDD, sCD, 1.f);
        sub_k<<<(unsigned)(NBD / 256), 256>>>(pr, vm);
        tconv_k<<<dim3(D_/32, C_/32, B_), t256>>>(km, tkm, C_, D_, sCD, sDC);
        tconv_k<<<dim3(D_/32, C_/32, B_), t256>>>(pr, tpr, C_, D_, sCD, sDC);
        tmma_k<0><<<gg, 256, TM_SMEM>>>(tkm, tpr, grad, nullptr, D_, C_, sDC, sDC, sDD, 1.f / C_);
        update_k<<<(unsigned)(ND / 256), 256>>>(Mm, Sm, grad, lr, mom, fg);

        // --- attention with persistent tokens ---
        ln_k<1><<<BC_, 256>>>(x, mc, g2, b2, h2, c0);
        tmma_k<1><<<gp, 256, TM_SMEM>>>(h2, wq, qh, bq, D_, D_, 0, 0, 0, 1.f);
        tmma_k<1><<<gp, 256, TM_SMEM>>>(h2, wk, kh, bk, D_, D_, 0, 0, 0, 1.f);
        tmma_k<1><<<gp, 256, TM_SMEM>>>(h2, wv, vh, bv, D_, D_, 0, 0, 0, 1.f);
        attn_scores_k<<<dim3(9, 8, BH_), 256>>>(qh, kh, pk, sc);
        softmax_k<<<BH_ * C_, 256>>>(sc);
        attn_av_k<<<dim3(8, BH_), 256>>>(sc, vh, pv, at);
        tmma_k<1><<<gp, 256, TM_SMEM>>>(at, wo, ao, bo, D_, D_, 0, 0, 0, 1.f);
        tmma_k<2><<<gp, 256, TM_SMEM>>>(mc, wg, gt, bg, D_, D_, 0, 0, 0, 1.f);
        combine_k<<<(unsigned)(NBD / 256), 256>>>(x, gt, ao, mc, o, c0);

        // --- gated FFN ---
        ln_k<2><<<BC_, 256>>>(o, nullptr, g3, b3, h3, 0);
        tmma_k<1><<<gf, 256, TM_SMEM>>>(h3, wgate, f1, bgate, FF_, D_, 0, 0, 0, 1.f);
        tmma_k<1><<<gf, 256, TM_SMEM>>>(h3, wup,   f2, bup,   FF_, D_, 0, 0, 0, 1.f);
        silu_mul_k<<<(unsigned)(NBF / 256), 256>>>(f1, f2);
        tmma_k<3><<<gp, 256, TM_SMEM>>>(f1, wdown, o, bdown, D_, FF_, 0, 0, 0, 1.f);

        scatter_k<<<(unsigned)(NBD / 256), 256>>>(o, outp, c0);
    }
}

// round 7
// speedup vs baseline: 4.1329x; 1.6561x over previous
#include <cuda_runtime.h>
#include <cuda_bf16.h>
#include <math.h>
#include <stdint.h>

#define D_  1024
#define H_  16
#define DH_ 64
#define P_  16
#define C_  512
#define B_  4
#define S_  4096
#define FF_ 4096
#define NC_ 8
#define BC_ (B_*C_)      /* 2048 */
#define PC_ (P_+C_)      /* 528  */
#define PCP_ 640         /* padded key length (5*128) */
#define BH_ (B_*H_)      /* 64   */

// ------------------------- scratch (device globals) -------------------------
__device__ float g_h1[BC_*D_];
__device__ float g_qm[BC_*D_];
__device__ float g_km[BC_*D_];
__device__ float g_vm[BC_*D_];
__device__ float g_mc[BC_*D_];
__device__ float g_pr[BC_*D_];
__device__ float g_grad[B_*D_*D_];
__device__ float g_Mst[B_*D_*D_];
__device__ float g_Sst[B_*D_*D_];
__device__ float g_h2[BC_*D_];
__device__ float g_qb[(long)BH_*C_*DH_];     // q head-major, tf32
__device__ float g_kb[(long)BH_*PCP_*DH_];   // keys (pk rows 0..15), tf32
__device__ float g_vbT[(long)BH_*DH_*PCP_];  // v transposed, tf32
__device__ float g_sc[(long)BH_*C_*PCP_];
__device__ float g_at[BC_*D_];
__device__ float g_ao[BC_*D_];
__device__ float g_gt[BC_*D_];
__device__ float g_o [BC_*D_];
__device__ float g_h3[BC_*D_];
__device__ float g_f1[BC_*FF_];
__device__ float g_f2[BC_*FF_];

// tf32-rounded fp32 operand buffers ([N,K] K-major for mma B operand)
__device__ float w_qm[D_*D_];
__device__ float w_km[D_*D_];
__device__ float w_vm[D_*D_];
__device__ float w_q [D_*D_];
__device__ float w_k [D_*D_];
__device__ float w_v [D_*D_];
__device__ float w_o [D_*D_];
__device__ float w_g [D_*D_];
__device__ float w_gate[(long)FF_*D_];
__device__ float w_up  [(long)FF_*D_];
__device__ float w_down[(long)D_*FF_];
__device__ float t_M [B_*D_*D_];
__device__ float t_km[(long)B_*D_*C_];
__device__ float t_pr[(long)B_*D_*C_];

// ----------------------------- PTX helpers ----------------------------------
__device__ __forceinline__ uint32_t smem_u32(const void* p) {
    uint32_t a;
    asm("{ .reg .u64 t; cvta.to.shared.u64 t, %1; cvt.u32.u64 %0, t; }"
        : "=r"(a) : "l"(p));
    return a;
}
__device__ __forceinline__ uint32_t tf32_rna(float f) {
    uint32_t u;
    asm("cvt.rna.tf32.f32 %0, %1;" : "=r"(u) : "f"(f));
    return u;
}
__device__ __forceinline__ void ldsm4(uint32_t& r0, uint32_t& r1, uint32_t& r2,
                                      uint32_t& r3, uint32_t addr) {
    asm volatile("ldmatrix.sync.aligned.m8n8.x4.shared.b16 {%0,%1,%2,%3}, [%4];"
                 : "=r"(r0), "=r"(r1), "=r"(r2), "=r"(r3) : "r"(addr));
}
#define CP_ASYNC16(dst, src)                                                     \
    asm volatile("cp.async.cg.shared.global [%0], [%1], 16;" :: "r"(dst), "l"(src))
#define CP_COMMIT()  asm volatile("cp.async.commit_group;")
#define CP_WAIT(n)   asm volatile("cp.async.wait_group %0;" :: "n"(n))

#define MMAT(d, a, b0, b1)                                                       \
    asm volatile(                                                                \
        "mma.sync.aligned.m16n8k8.row.col.f32.tf32.tf32.f32 "                    \
        "{%0,%1,%2,%3}, {%4,%5,%6,%7}, {%8,%9}, {%0,%1,%2,%3};"                  \
        : "+f"((d)[0]), "+f"((d)[1]), "+f"((d)[2]), "+f"((d)[3])                 \
        : "r"((a)[0]), "r"((a)[1]), "r"((a)[2]), "r"((a)[3]), "r"(b0), "r"(b1))

// ------------------- TF32 HMMA GEMM, cp.async 3-stage, ldmatrix -------------
// C[M,N] = epi(alpha * A[M,K] @ B[N,K]^T). A fp32 (cvt.rna on fragments),
// B fp32 pre-rounded to tf32. CTA tile 128x128, K-step 32.
// EPI: 0 plain; 1 +bias; 2 sigmoid(+bias); 3 C+=acc+bias; 4 acc-aux;
//      5 C+=acc+bias & write outp chunk; 6/7/8 attention q/k/v stores.
#define LDT_ 36
#define TILE_F (128 * LDT_)
#define TM_SMEM (3 * 2 * TILE_F * 4)   /* 110592 B */

template<int EPI>
__global__ __launch_bounds__(256) void tmma_k(
    const float* __restrict__ A, const float* __restrict__ Bw,
    float* __restrict__ Cm, const float* __restrict__ bias,
    float* __restrict__ aux, int Ncols, int K,
    long sA, long sB, long sC, float alpha, int c0)
{
    extern __shared__ float smf[];
    const int bz = blockIdx.z;
    A  += bz * sA;
    Bw += bz * sB;
    Cm += bz * sC;
    const float* auxp = (EPI == 4 && aux) ? aux + bz * sC : aux;

    const int tid = threadIdx.x, warp = tid >> 5, lane = tid & 31;
    const int n0 = blockIdx.x * 128, m0 = blockIdx.y * 128;
    const int mo = (warp >> 2) * 64, no = (warp & 3) * 32;
    const int grp = lane >> 2, tig = lane & 3;

    // ldmatrix lane offsets
    const int a_row = (lane & 7) + ((lane & 8) ? 8 : 0);
    const int a_col = (lane & 16) ? 4 : 0;
    const int b_row = (lane & 7) + ((lane & 16) ? 8 : 0);
    const int b_col = (lane & 8) ? 4 : 0;

    const int lr = tid >> 3;
    const int lc = (tid & 7) << 2;

    float acc[4][4][4] = {};
    const int KT = K >> 5;

#pragma unroll
    for (int s = 0; s < 2; s++) {
        const int k0 = s << 5;
        float* As = smf + s * 2 * TILE_F;
        float* Bs = As + TILE_F;
#pragma unroll
        for (int i = 0; i < 4; i++) {
            int r = lr + 32 * i;
            CP_ASYNC16(smem_u32(&As[r * LDT_ + lc]), A  + (long)(m0 + r) * K + k0 + lc);
            CP_ASYNC16(smem_u32(&Bs[r * LDT_ + lc]), Bw + (long)(n0 + r) * K + k0 + lc);
        }
        CP_COMMIT();
    }

    for (int kt = 0; kt < KT; kt++) {
        if (kt + 1 < KT) { CP_WAIT(1); } else { CP_WAIT(0); }
        __syncthreads();

        if (kt + 2 < KT) {
            const int s = (kt + 2) % 3;
            const int k0 = (kt + 2) << 5;
            float* As = smf + s * 2 * TILE_F;
            float* Bs = As + TILE_F;
#pragma unroll
            for (int i = 0; i < 4; i++) {
                int r = lr + 32 * i;
                CP_ASYNC16(smem_u32(&As[r * LDT_ + lc]), A  + (long)(m0 + r) * K + k0 + lc);
                CP_ASYNC16(smem_u32(&Bs[r * LDT_ + lc]), Bw + (long)(n0 + r) * K + k0 + lc);
            }
            CP_COMMIT();
        }

        const float* As = smf + (kt % 3) * 2 * TILE_F;
        const float* Bs = As + TILE_F;
        const uint32_t uA = smem_u32(As), uB = smem_u32(Bs);
#pragma unroll
        for (int k8 = 0; k8 < 4; k8++) {
            const int kc = k8 * 8;
            uint32_t a[4][4], b[4][2];
#pragma unroll
            for (int mt = 0; mt < 4; mt++) {
                uint32_t ad = uA + (uint32_t)(((mo + mt * 16 + a_row) * LDT_ + kc + a_col) * 4);
                ldsm4(a[mt][0], a[mt][1], a[mt][2], a[mt][3], ad);
#pragma unroll
                for (int q = 0; q < 4; q++)
                    a[mt][q] = tf32_rna(__uint_as_float(a[mt][q]));
            }
            {
                uint32_t bd0 = uB + (uint32_t)(((no + b_row) * LDT_ + kc + b_col) * 4);
                ldsm4(b[0][0], b[0][1], b[1][0], b[1][1], bd0);
                uint32_t bd1 = uB + (uint32_t)(((no + 16 + b_row) * LDT_ + kc + b_col) * 4);
                ldsm4(b[2][0], b[2][1], b[3][0], b[3][1], bd1);
            }
#pragma unroll
            for (int mt = 0; mt < 4; mt++)
#pragma unroll
                for (int j = 0; j < 4; j++)
                    MMAT(acc[mt][j], a[mt], b[j][0], b[j][1]);
        }
    }

    // ------------------------------ epilogue --------------------------------
#pragma unroll
    for (int mt = 0; mt < 4; mt++) {
#pragma unroll
        for (int j = 0; j < 4; j++) {
            int row = m0 + mo + mt * 16 + grp;
            int col = n0 + no + j * 8 + tig * 2;
#pragma unroll
            for (int hh = 0; hh < 2; hh++) {
                int r = row + hh * 8;
                float v0 = acc[mt][j][hh * 2 + 0] * alpha;
                float v1 = acc[mt][j][hh * 2 + 1] * alpha;
                if (EPI == 1 || EPI == 2 || EPI == 3 || EPI == 5 ||
                    EPI == 6 || EPI == 7 || EPI == 8) {
                    float2 bv = *(const float2*)(bias + col);
                    v0 += bv.x; v1 += bv.y;
                }
                if (EPI <= 5) {
                    float* cp = Cm + (long)r * Ncols + col;
                    if (EPI == 2) {
                        v0 = 1.f / (1.f + expf(-v0));
                        v1 = 1.f / (1.f + expf(-v1));
                    }
                    if (EPI == 3 || EPI == 5) {
                        float2 c = *(float2*)cp;
                        v0 += c.x; v1 += c.y;
                    }
                    if (EPI == 4) {
                        float2 av = *(const float2*)(auxp + (long)r * Ncols + col);
                        v0 -= av.x; v1 -= av.y;
                    }
                    float2 o; o.x = v0; o.y = v1;
                    *(float2*)cp = o;
                    if (EPI == 5) {
                        int b = r >> 9, i = r & 511;
                        *(float2*)(aux + ((long)b * S_ + c0 + i) * D_ + col) = o;
                    }
                } else {
                    int b = r >> 9, i = r & 511;
                    int h = col >> 6, d = col & 63;
                    float2 o;
                    o.x = __uint_as_float(tf32_rna(v0));
                    o.y = __uint_as_float(tf32_rna(v1));
                    if (EPI == 6) {
                        *(float2*)(Cm + (((long)(b * H_ + h) * C_ + i) * DH_ + d)) = o;
                    } else if (EPI == 7) {
                        *(float2*)(Cm + (((long)(b * H_ + h) * PCP_ + P_ + i) * DH_ + d)) = o;
                    } else {
                        Cm[((long)(b * H_ + h) * DH_ + d)     * PCP_ + P_ + i] = o.x;
                        Cm[((long)(b * H_ + h) * DH_ + d + 1) * PCP_ + P_ + i] = o.y;
                    }
                }
            }
        }
    }
}

// ------------------ attention scores: S = Q @ K^T * 0.125 + mask ------------
#define SC_SMEM (2 * 2 * TILE_F * 4)   /* 73728 B */
__global__ __launch_bounds__(256) void attn_sc_k(
    const float* __restrict__ qb, const float* __restrict__ kb,
    float* __restrict__ sc)
{
    extern __shared__ float smf[];
    const int bh = blockIdx.z;
    const int n0 = blockIdx.x * 128, m0 = blockIdx.y * 128;
    const float* Aq = qb + (long)bh * C_ * DH_;
    const float* Bk = kb + (long)bh * PCP_ * DH_;

    const int tid = threadIdx.x, warp = tid >> 5, lane = tid & 31;
    const int mo = (warp >> 2) * 64, no = (warp & 3) * 32;
    const int grp = lane >> 2, tig = lane & 3;
    const int a_row = (lane & 7) + ((lane & 8) ? 8 : 0);
    const int a_col = (lane & 16) ? 4 : 0;
    const int b_row = (lane & 7) + ((lane & 16) ? 8 : 0);
    const int b_col = (lane & 8) ? 4 : 0;
    const int lr = tid >> 3, lc = (tid & 7) << 2;

    float acc[4][4][4] = {};

#pragma unroll
    for (int s = 0; s < 2; s++) {
        const int k0 = s << 5;
        float* As = smf + s * 2 * TILE_F;
        float* Bs = As + TILE_F;
#pragma unroll
        for (int i = 0; i < 4; i++) {
            int r = lr + 32 * i;
            CP_ASYNC16(smem_u32(&As[r * LDT_ + lc]), Aq + (long)(m0 + r) * DH_ + k0 + lc);
            CP_ASYNC16(smem_u32(&Bs[r * LDT_ + lc]), Bk + (long)(n0 + r) * DH_ + k0 + lc);
        }
        CP_COMMIT();
    }
    CP_WAIT(0);
    __syncthreads();

#pragma unroll
    for (int kt = 0; kt < 2; kt++) {
        const float* As = smf + kt * 2 * TILE_F;
        const float* Bs = As + TILE_F;
        const uint32_t uA = smem_u32(As), uB = smem_u32(Bs);
#pragma unroll
        for (int k8 = 0; k8 < 4; k8++) {
            const int kc = k8 * 8;
            uint32_t a[4][4], b[4][2];
#pragma unroll
            for (int mt = 0; mt < 4; mt++) {
                uint32_t ad = uA + (uint32_t)(((mo + mt * 16 + a_row) * LDT_ + kc + a_col) * 4);
                ldsm4(a[mt][0], a[mt][1], a[mt][2], a[mt][3], ad);
            }
            uint32_t bd0 = uB + (uint32_t)(((no + b_row) * LDT_ + kc + b_col) * 4);
            ldsm4(b[0][0], b[0][1], b[1][0], b[1][1], bd0);
            uint32_t bd1 = uB + (uint32_t)(((no + 16 + b_row) * LDT_ + kc + b_col) * 4);
            ldsm4(b[2][0], b[2][1], b[3][0], b[3][1], bd1);
#pragma unroll
            for (int mt = 0; mt < 4; mt++)
#pragma unroll
                for (int j = 0; j < 4; j++)
                    MMAT(acc[mt][j], a[mt], b[j][0], b[j][1]);
        }
    }

#pragma unroll
    for (int mt = 0; mt < 4; mt++) {
#pragma unroll
        for (int j = 0; j < 4; j++) {
            int row = m0 + mo + mt * 16 + grp;
            int col = n0 + no + j * 8 + tig * 2;
#pragma unroll
            for (int hh = 0; hh < 2; hh++) {
                int gi = row + hh * 8;
                float2 o;
                o.x = (col     < P_ || (col     - P_) <= gi) ? acc[mt][j][hh*2+0] * 0.125f : -1e9f;
                o.y = (col + 1 < P_ || (col + 1 - P_) <= gi) ? acc[mt][j][hh*2+1] * 0.125f : -1e9f;
                *(float2*)(sc + ((long)bh * C_ + gi) * PCP_ + col) = o;
            }
        }
    }
}

// ------------------- attention AV: O = P @ V (P tf32, V^T tf32) -------------
#define AV_ATILE (128 * LDT_)
#define AV_BTILE (64 * LDT_)
#define AV_STAGE (AV_ATILE + AV_BTILE)
#define AV_SMEM (3 * AV_STAGE * 4)   /* 82944 B */
__global__ __launch_bounds__(256) void attn_av_k(
    const float* __restrict__ sc, const float* __restrict__ vbT,
    float* __restrict__ at)
{
    extern __shared__ float smf[];
    const int bh = blockIdx.y, b = bh >> 4, h = bh & 15;
    const int m0 = blockIdx.x * 128;
    const float* Ap = sc + ((long)bh * C_ + m0) * PCP_;
    const float* Bv = vbT + (long)bh * DH_ * PCP_;

    const int tid = threadIdx.x, warp = tid >> 5, lane = tid & 31;
    const int mo = (warp & 3) * 32, no = (warp >> 2) * 32;
    const int grp = lane >> 2, tig = lane & 3;
    const int a_row = (lane & 7) + ((lane & 8) ? 8 : 0);
    const int a_col = (lane & 16) ? 4 : 0;
    const int b_row = (lane & 7) + ((lane & 16) ? 8 : 0);
    const int b_col = (lane & 8) ? 4 : 0;
    const int lr = tid >> 3, lc = (tid & 7) << 2;

    float acc[2][4][4] = {};
    const int KT = PCP_ >> 5;   // 20

#pragma unroll
    for (int s = 0; s < 2; s++) {
        const int k0 = s << 5;
        float* As = smf + s * AV_STAGE;
        float* Bs = As + AV_ATILE;
#pragma unroll
        for (int i = 0; i < 4; i++) {
            int r = lr + 32 * i;
            CP_ASYNC16(smem_u32(&As[r * LDT_ + lc]), Ap + (long)r * PCP_ + k0 + lc);
        }
#pragma unroll
        for (int i = 0; i < 2; i++) {
            int r = lr + 32 * i;
            CP_ASYNC16(smem_u32(&Bs[r * LDT_ + lc]), Bv + (long)r * PCP_ + k0 + lc);
        }
        CP_COMMIT();
    }

    for (int kt = 0; kt < KT; kt++) {
        if (kt + 1 < KT) { CP_WAIT(1); } else { CP_WAIT(0); }
        __syncthreads();
        if (kt + 2 < KT) {
            const int s = (kt + 2) % 3;
            const int k0 = (kt + 2) << 5;
            float* As = smf + s * AV_STAGE;
            float* Bs = As + AV_ATILE;
#pragma unroll
            for (int i = 0; i < 4; i++) {
                int r = lr + 32 * i;
                CP_ASYNC16(smem_u32(&As[r * LDT_ + lc]), Ap + (long)r * PCP_ + k0 + lc);
            }
#pragma unroll
            for (int i = 0; i < 2; i++) {
                int r = lr + 32 * i;
                CP_ASYNC16(smem_u32(&Bs[r * LDT_ + lc]), Bv + (long)r * PCP_ + k0 + lc);
            }
            CP_COMMIT();
        }

        const float* As = smf + (kt % 3) * AV_STAGE;
        const float* Bs = As + AV_ATILE;
        const uint32_t uA = smem_u32(As), uB = smem_u32(Bs);
#pragma unroll
        for (int k8 = 0; k8 < 4; k8++) {
            const int kc = k8 * 8;
            uint32_t a[2][4], bq[4][2];
#pragma unroll
            for (int mt = 0; mt < 2; mt++) {
                uint32_t ad = uA + (uint32_t)(((mo + mt * 16 + a_row) * LDT_ + kc + a_col) * 4);
                ldsm4(a[mt][0], a[mt][1], a[mt][2], a[mt][3], ad);
            }
            uint32_t bd0 = uB + (uint32_t)(((no + b_row) * LDT_ + kc + b_col) * 4);
            ldsm4(bq[0][0], bq[0][1], bq[1][0], bq[1][1], bd0);
            uint32_t bd1 = uB + (uint32_t)(((no + 16 + b_row) * LDT_ + kc + b_col) * 4);
            ldsm4(bq[2][0], bq[2][1], bq[3][0], bq[3][1], bd1);
#pragma unroll
            for (int mt = 0; mt < 2; mt++)
#pragma unroll
                for (int j = 0; j < 4; j++)
                    MMAT(acc[mt][j], a[mt], bq[j][0], bq[j][1]);
        }
    }

#pragma unroll
    for (int mt = 0; mt < 2; mt++) {
#pragma unroll
        for (int j = 0; j < 4; j++) {
            int row = m0 + mo + mt * 16 + grp;
            int col = no + j * 8 + tig * 2;
#pragma unroll
            for (int hh = 0; hh < 2; hh++) {
                int gi = row + hh * 8;
                float2 o;
                o.x = acc[mt][j][hh * 2 + 0];
                o.y = acc[mt][j][hh * 2 + 1];
                *(float2*)(at + ((long)b * C_ + gi) * D_ + h * DH_ + col) = o;
            }
        }
    }
}

// ------------- transpose + tf32-round (fp32 -> tf32-in-fp32) ----------------
__global__ __launch_bounds__(256) void tconv_k(
    const float* __restrict__ in, float* __restrict__ out,
    int R, int Cc, long sIn, long sOut)
{
    __shared__ float t[32][33];
    in  += (long)blockIdx.z * sIn;
    out += (long)blockIdx.z * sOut;
    int r0 = blockIdx.y * 32, c0 = blockIdx.x * 32;
    int tx = threadIdx.x & 31, ty = threadIdx.x >> 5;
#pragma unroll
    for (int i = 0; i < 32; i += 8)
        t[ty + i][tx] = in[(long)(r0 + ty + i) * Cc + c0 + tx];
    __syncthreads();
#pragma unroll
    for (int i = 0; i < 32; i += 8)
        out[(long)(c0 + ty + i) * R + r0 + tx] = __uint_as_float(tf32_rna(t[tx][ty + i]));
}

// ------------------------------- LayerNorm ----------------------------------
template<int MODE>
__global__ __launch_bounds__(256) void ln_k(
    const float* __restrict__ src, const float* __restrict__ res,
    const float* __restrict__ gam, const float* __restrict__ bet,
    float* __restrict__ out, int c0)
{
    int r = blockIdx.x;
    const float* p;
    if (MODE == 2) p = src + (long)r * D_;
    else { int b = r / C_, i = r % C_; p = src + ((long)b * S_ + c0 + i) * D_; }

    int tid = threadIdx.x;
    float v[4], s = 0.f, sq = 0.f;
#pragma unroll
    for (int k = 0; k < 4; k++) {
        int c = tid + k * 256;
        float xv = p[c];
        if (MODE == 1) xv += res[(long)r * D_ + c];
        v[k] = xv; s += xv; sq += xv * xv;
    }
    __shared__ float shs[8], shq[8];
#pragma unroll
    for (int o = 16; o; o >>= 1) {
        s  += __shfl_xor_sync(0xffffffffu, s,  o);
        sq += __shfl_xor_sync(0xffffffffu, sq, o);
    }
    if ((tid & 31) == 0) { shs[tid >> 5] = s; shq[tid >> 5] = sq; }
    __syncthreads();
    s = 0.f; sq = 0.f;
#pragma unroll
    for (int i = 0; i < 8; i++) { s += shs[i]; sq += shq[i]; }
    float m  = s * (1.f / D_);
    float var = sq * (1.f / D_) - m * m;
    float rs = rsqrtf(var + 1e-5f);
#pragma unroll
    for (int k = 0; k < 4; k++) {
        int c = tid + k * 256;
        out[(long)r * D_ + c] = (v[k] - m) * rs * gam[c] + bet[c];
    }
}

__global__ __launch_bounds__(256) void rownorm_k(float* __restrict__ km)
{
    int r = blockIdx.x, tid = threadIdx.x;
    float* p = km + (long)r * D_;
    float v[4], sq = 0.f;
#pragma unroll
    for (int k = 0; k < 4; k++) { int c = tid + k * 256; v[k] = p[c]; sq += v[k] * v[k]; }
    __shared__ float shq[8];
#pragma unroll
    for (int o = 16; o; o >>= 1) sq += __shfl_xor_sync(0xffffffffu, sq, o);
    if ((tid & 31) == 0) shq[tid >> 5] = sq;
    __syncthreads();
    sq = 0.f;
#pragma unroll
    for (int i = 0; i < 8; i++) sq += shq[i];
    float rs = rsqrtf(sq + 1e-6f);
#pragma unroll
    for (int k = 0; k < 4; k++) { int c = tid + k * 256; p[c] = v[k] * rs; }
}

// ------------------------- softmax (row length PCP) -------------------------
__global__ __launch_bounds__(256) void softmax_k(float* __restrict__ sc)
{
    float* row = sc + (long)blockIdx.x * PCP_;
    int tid = threadIdx.x;
    __shared__ float sh[8];
    float mx = -1e30f;
    for (int c = tid; c < PCP_; c += 256) mx = fmaxf(mx, row[c]);
#pragma unroll
    for (int o = 16; o; o >>= 1) mx = fmaxf(mx, __shfl_xor_sync(0xffffffffu, mx, o));
    if ((tid & 31) == 0) sh[tid >> 5] = mx;
    __syncthreads();
    mx = sh[0];
#pragma unroll
    for (int i = 1; i < 8; i++) mx = fmaxf(mx, sh[i]);
    float s = 0.f;
    float ev[3];
    int idx = 0;
    for (int c = tid; c < PCP_; c += 256, idx++) {
        float e = expf(row[c] - mx);
        ev[idx] = e; s += e;
    }
    __syncthreads();
#pragma unroll
    for (int o = 16; o; o >>= 1) s += __shfl_xor_sync(0xffffffffu, s, o);
    if ((tid & 31) == 0) sh[tid >> 5] = s;
    __syncthreads();
    s = 0.f;
#pragma unroll
    for (int i = 0; i < 8; i++) s += sh[i];
    float inv = 1.f / s;
    idx = 0;
    for (int c = tid; c < PCP_; c += 256, idx++)
        row[c] = __uint_as_float(tf32_rna(ev[idx] * inv));
}

// ------------------------------- elementwise --------------------------------
__global__ void zero2_k(float* __restrict__ a, float* __restrict__ b)
{
    long i = (long)blockIdx.x * 256 + threadIdx.x;
    a[i] = 0.f; b[i] = 0.f;
}

__global__ void fillpkv_k(const float* __restrict__ pk, const float* __restrict__ pv,
                          float* __restrict__ kb, float* __restrict__ vbT)
{
    int idx = blockIdx.x * 256 + threadIdx.x;   // 64*16*64 = 65536
    int bh = idx >> 10, rem = idx & 1023;
    int p = rem >> 6, d = rem & 63;
    int h = bh & 15;
    float kv = pk[((long)p * H_ + h) * DH_ + d];
    float vv = pv[((long)p * H_ + h) * DH_ + d];
    kb[((long)bh * PCP_ + p) * DH_ + d] = __uint_as_float(tf32_rna(kv));
    vbT[((long)bh * DH_ + d) * PCP_ + p] = __uint_as_float(tf32_rna(vv));
}

__global__ void update_k(float* __restrict__ M, float* __restrict__ S,
                         const float* __restrict__ grad,
                         const float* __restrict__ lr,
                         const float* __restrict__ mom,
                         const float* __restrict__ fg)
{
    long i = (long)blockIdx.x * 256 + threadIdx.x;
    float th = 1.f / (1.f + expf(-lr[0]));
    float et = 1.f / (1.f + expf(-mom[0]));
    float al = 1.f / (1.f + expf(-fg[0]));
    float s = et * S[i] - th * grad[i];
    S[i] = s;
    M[i] = (1.f - al) * M[i] + s;
}

__global__ void combine_k(const float* __restrict__ x, const float* __restrict__ gt,
                          const float* __restrict__ ao, const float* __restrict__ mc,
                          float* __restrict__ o, int c0)
{
    long idx = (long)blockIdx.x * 256 + threadIdx.x;
    int r = (int)(idx / D_), c = (int)(idx % D_);
    int b = r / C_, i = r % C_;
    float xv = x[((long)b * S_ + c0 + i) * D_ + c];
    float gv = gt[idx];
    o[idx] = xv + gv * ao[idx] + (1.f - gv) * mc[idx];
}

__global__ void silu_mul_k(float* __restrict__ f1, const float* __restrict__ f2)
{
    long i = (long)blockIdx.x * 256 + threadIdx.x;
    float v = f1[i];
    f1[i] = v / (1.f + expf(-v)) * f2[i];
}

// --------------------------------- launch -----------------------------------
extern "C" void kernel_launch(void* const* d_in, const int* in_sizes, int n_in,
                              void* d_out, int out_size)
{
    const float* x     = (const float*)d_in[0];
    const float* g1    = (const float*)d_in[1];
    const float* b1    = (const float*)d_in[2];
    const float* g2    = (const float*)d_in[3];
    const float* b2    = (const float*)d_in[4];
    const float* g3    = (const float*)d_in[5];
    const float* b3    = (const float*)d_in[6];
    const float* Wqm   = (const float*)d_in[7];
    const float* Wkm   = (const float*)d_in[8];
    const float* Wvm   = (const float*)d_in[9];
    const float* lr    = (const float*)d_in[10];
    const float* mom   = (const float*)d_in[11];
    const float* fg    = (const float*)d_in[12];
    const float* Wq    = (const float*)d_in[13];
    const float* bq    = (const float*)d_in[14];
    const float* Wk    = (const float*)d_in[15];
    const float* bk    = (const float*)d_in[16];
    const float* Wv    = (const float*)d_in[17];
    const float* bv    = (const float*)d_in[18];
    const float* Wo    = (const float*)d_in[19];
    const float* bo    = (const float*)d_in[20];
    const float* pk    = (const float*)d_in[21];
    const float* pv    = (const float*)d_in[22];
    const float* Wg    = (const float*)d_in[23];
    const float* bg    = (const float*)d_in[24];
    const float* Wgate = (const float*)d_in[25];
    const float* bgate = (const float*)d_in[26];
    const float* Wup   = (const float*)d_in[27];
    const float* bup   = (const float*)d_in[28];
    const float* Wdown = (const float*)d_in[29];
    const float* bdown = (const float*)d_in[30];
    float* outp = (float*)d_out;

    float *h1, *qm, *km, *vm, *mc, *pr, *grad, *Mm, *Sm, *h2;
    float *qb, *kb, *vbT, *sc, *at, *ao, *gt, *o, *h3, *f1, *f2;
    float *wqm, *wkm, *wvm, *wq, *wk, *wv, *wo, *wg, *wgate, *wup, *wdown;
    float *tM, *tkm, *tpr;
    cudaGetSymbolAddress((void**)&h1, g_h1);
    cudaGetSymbolAddress((void**)&qm, g_qm);
    cudaGetSymbolAddress((void**)&km, g_km);
    cudaGetSymbolAddress((void**)&vm, g_vm);
    cudaGetSymbolAddress((void**)&mc, g_mc);
    cudaGetSymbolAddress((void**)&pr, g_pr);
    cudaGetSymbolAddress((void**)&grad, g_grad);
    cudaGetSymbolAddress((void**)&Mm, g_Mst);
    cudaGetSymbolAddress((void**)&Sm, g_Sst);
    cudaGetSymbolAddress((void**)&h2, g_h2);
    cudaGetSymbolAddress((void**)&qb, g_qb);
    cudaGetSymbolAddress((void**)&kb, g_kb);
    cudaGetSymbolAddress((void**)&vbT, g_vbT);
    cudaGetSymbolAddress((void**)&sc, g_sc);
    cudaGetSymbolAddress((void**)&at, g_at);
    cudaGetSymbolAddress((void**)&ao, g_ao);
    cudaGetSymbolAddress((void**)&gt, g_gt);
    cudaGetSymbolAddress((void**)&o,  g_o);
    cudaGetSymbolAddress((void**)&h3, g_h3);
    cudaGetSymbolAddress((void**)&f1, g_f1);
    cudaGetSymbolAddress((void**)&f2, g_f2);
    cudaGetSymbolAddress((void**)&wqm, w_qm);
    cudaGetSymbolAddress((void**)&wkm, w_km);
    cudaGetSymbolAddress((void**)&wvm, w_vm);
    cudaGetSymbolAddress((void**)&wq,  w_q);
    cudaGetSymbolAddress((void**)&wk,  w_k);
    cudaGetSymbolAddress((void**)&wv,  w_v);
    cudaGetSymbolAddress((void**)&wo,  w_o);
    cudaGetSymbolAddress((void**)&wg,  w_g);
    cudaGetSymbolAddress((void**)&wgate, w_gate);
    cudaGetSymbolAddress((void**)&wup,   w_up);
    cudaGetSymbolAddress((void**)&wdown, w_down);
    cudaGetSymbolAddress((void**)&tM,  t_M);
    cudaGetSymbolAddress((void**)&tkm, t_km);
    cudaGetSymbolAddress((void**)&tpr, t_pr);

    cudaFuncSetAttribute(tmma_k<0>, cudaFuncAttributeMaxDynamicSharedMemorySize, TM_SMEM);
    cudaFuncSetAttribute(tmma_k<1>, cudaFuncAttributeMaxDynamicSharedMemorySize, TM_SMEM);
    cudaFuncSetAttribute(tmma_k<2>, cudaFuncAttributeMaxDynamicSharedMemorySize, TM_SMEM);
    cudaFuncSetAttribute(tmma_k<3>, cudaFuncAttributeMaxDynamicSharedMemorySize, TM_SMEM);
    cudaFuncSetAttribute(tmma_k<4>, cudaFuncAttributeMaxDynamicSharedMemorySize, TM_SMEM);
    cudaFuncSetAttribute(tmma_k<5>, cudaFuncAttributeMaxDynamicSharedMemorySize, TM_SMEM);
    cudaFuncSetAttribute(tmma_k<6>, cudaFuncAttributeMaxDynamicSharedMemorySize, TM_SMEM);
    cudaFuncSetAttribute(tmma_k<7>, cudaFuncAttributeMaxDynamicSharedMemorySize, TM_SMEM);
    cudaFuncSetAttribute(tmma_k<8>, cudaFuncAttributeMaxDynamicSharedMemorySize, TM_SMEM);
    cudaFuncSetAttribute(attn_sc_k, cudaFuncAttributeMaxDynamicSharedMemorySize, SC_SMEM);
    cudaFuncSetAttribute(attn_av_k, cudaFuncAttributeMaxDynamicSharedMemorySize, AV_SMEM);

    const long ND  = (long)B_ * D_ * D_;
    const long NBD = (long)BC_ * D_;
    const long NBF = (long)BC_ * FF_;
    const long sCD = (long)C_ * D_;
    const long sDD = (long)D_ * D_;
    const long sDC = (long)D_ * C_;

    zero2_k<<<(unsigned)(ND / 256), 256>>>(Mm, Sm);
    fillpkv_k<<<256, 256>>>(pk, pv, kb, vbT);

    dim3 t256(256);
    tconv_k<<<dim3(D_/32,  D_/32, 1), t256>>>(Wqm,   wqm,   D_,  D_,  0, 0);
    tconv_k<<<dim3(D_/32,  D_/32, 1), t256>>>(Wkm,   wkm,   D_,  D_,  0, 0);
    tconv_k<<<dim3(D_/32,  D_/32, 1), t256>>>(Wvm,   wvm,   D_,  D_,  0, 0);
    tconv_k<<<dim3(D_/32,  D_/32, 1), t256>>>(Wq,    wq,    D_,  D_,  0, 0);
    tconv_k<<<dim3(D_/32,  D_/32, 1), t256>>>(Wk,    wk,    D_,  D_,  0, 0);
    tconv_k<<<dim3(D_/32,  D_/32, 1), t256>>>(Wv,    wv,    D_,  D_,  0, 0);
    tconv_k<<<dim3(D_/32,  D_/32, 1), t256>>>(Wo,    wo,    D_,  D_,  0, 0);
    tconv_k<<<dim3(D_/32,  D_/32, 1), t256>>>(Wg,    wg,    D_,  D_,  0, 0);
    tconv_k<<<dim3(FF_/32, D_/32, 1), t256>>>(Wgate, wgate, D_,  FF_, 0, 0);
    tconv_k<<<dim3(FF_/32, D_/32, 1), t256>>>(Wup,   wup,   D_,  FF_, 0, 0);
    tconv_k<<<dim3(D_/32, FF_/32, 1), t256>>>(Wdown, wdown, FF_, D_,  0, 0);

    dim3 gp(D_ / 128, BC_ / 128, 1);
    dim3 gf(FF_ / 128, BC_ / 128, 1);
    dim3 gb(D_ / 128, C_ / 128, B_);
    dim3 gg(D_ / 128, D_ / 128, B_);

    for (int t = 0; t < NC_; t++) {
        int c0 = t * C_;
        // --- neural memory ---
        tconv_k<<<dim3(D_/32, D_/32, B_), t256>>>(Mm, tM, D_, D_, sDD, sDD);
        ln_k<0><<<BC_, 256>>>(x, nullptr, g1, b1, h1, c0);
        tmma_k<0><<<gp, 256, TM_SMEM>>>(h1, wqm, qm, nullptr, nullptr, D_, D_, 0, 0, 0, 1.f, 0);
        tmma_k<0><<<gp, 256, TM_SMEM>>>(h1, wkm, km, nullptr, nullptr, D_, D_, 0, 0, 0, 1.f, 0);
        rownorm_k<<<BC_, 256>>>(km);
        tmma_k<0><<<gp, 256, TM_SMEM>>>(h1, wvm, vm, nullptr, nullptr, D_, D_, 0, 0, 0, 1.f, 0);
        tmma_k<0><<<gb, 256, TM_SMEM>>>(qm, tM, mc, nullptr, nullptr, D_, D_, sCD, sDD, sCD, 1.f, 0);
        tmma_k<4><<<gb, 256, TM_SMEM>>>(km, tM, pr, nullptr, vm, D_, D_, sCD, sDD, sCD, 1.f, 0);
        tconv_k<<<dim3(D_/32, C_/32, B_), t256>>>(km, tkm, C_, D_, sCD, sDC);
        tconv_k<<<dim3(D_/32, C_/32, B_), t256>>>(pr, tpr, C_, D_, sCD, sDC);
        tmma_k<0><<<gg, 256, TM_SMEM>>>(tkm, tpr, grad, nullptr, nullptr, D_, C_, sDC, sDC, sDD, 1.f / C_, 0);
        update_k<<<(unsigned)(ND / 256), 256>>>(Mm, Sm, grad, lr, mom, fg);

        // --- attention with persistent tokens (tf32 mma) ---
        ln_k<1><<<BC_, 256>>>(x, mc, g2, b2, h2, c0);
        tmma_k<6><<<gp, 256, TM_SMEM>>>(h2, wq, qb, bq, nullptr, D_, D_, 0, 0, 0, 1.f, 0);
        tmma_k<7><<<gp, 256, TM_SMEM>>>(h2, wk, kb, bk, nullptr, D_, D_, 0, 0, 0, 1.f, 0);
        tmma_k<8><<<gp, 256, TM_SMEM>>>(h2, wv, vbT, bv, nullptr, D_, D_, 0, 0, 0, 1.f, 0);
        attn_sc_k<<<dim3(PCP_/128, C_/128, BH_), 256, SC_SMEM>>>(qb, kb, sc);
        softmax_k<<<BH_ * C_, 256>>>(sc);
        attn_av_k<<<dim3(C_/128, BH_), 256, AV_SMEM>>>(sc, vbT, at);
        tmma_k<1><<<gp, 256, TM_SMEM>>>(at, wo, ao, bo, nullptr, D_, D_, 0, 0, 0, 1.f, 0);
        tmma_k<2><<<gp, 256, TM_SMEM>>>(mc, wg, gt, bg, nullptr, D_, D_, 0, 0, 0, 1.f, 0);
        combine_k<<<(unsigned)(NBD / 256), 256>>>(x, gt, ao, mc, o, c0);

        // --- gated FFN ---
        ln_k<2><<<BC_, 256>>>(o, nullptr, g3, b3, h3, 0);
        tmma_k<1><<<gf, 256, TM_SMEM>>>(h3, wgate, f1, bgate, nullptr, FF_, D_, 0, 0, 0, 1.f, 0);
        tmma_k<1><<<gf, 256, TM_SMEM>>>(h3, wup,   f2, bup,   nullptr, FF_, D_, 0, 0, 0, 1.f, 0);
        silu_mul_k<<<(unsigned)(NBF / 256), 256>>>(f1, f2);
        tmma_k<5><<<gp, 256, TM_SMEM>>>(f1, wdown, o, bdown, outp, D_, FF_, 0, 0, 0, 1.f, c0);
    }
}

// round 8
// speedup vs baseline: 4.7977x; 1.1609x over previous
#include <cuda_runtime.h>
#include <cuda_bf16.h>
#include <math.h>
#include <stdint.h>

#define D_  1024
#define H_  16
#define DH_ 64
#define P_  16
#define C_  512
#define B_  4
#define S_  4096
#define FF_ 4096
#define NC_ 8
#define BC_ (B_*C_)      /* 2048 */
#define PC_ (P_+C_)      /* 528  */
#define PCP_ 640         /* padded key length (5*128) */
#define BH_ (B_*H_)      /* 64   */

static constexpr long QB_OFFc = 0;
static constexpr long KB_OFFc = (long)BH_ * C_ * DH_;
static constexpr long VB_OFFc = KB_OFFc + (long)BH_ * PCP_ * DH_;
static constexpr long ATTN_SZ = VB_OFFc + (long)BH_ * DH_ * PCP_;

// ------------------------- scratch (device globals) -------------------------
__device__ float g_h1[BC_*D_];
__device__ float g_qkvm[(long)BC_*3*D_];     // qm|km|vm, row stride 3072
__device__ float g_mc[BC_*D_];
__device__ float g_pr[BC_*D_];
__device__ float g_grad[B_*D_*D_];
__device__ float g_Mst[B_*D_*D_];
__device__ float g_Sst[B_*D_*D_];
__device__ float g_h2[BC_*D_];
__device__ float g_attn[(size_t)ATTN_SZ];    // qb | kb | vbT (tf32)
__device__ float g_sc[(long)BH_*C_*PCP_];
__device__ float g_at[BC_*D_];
__device__ float g_ao[BC_*D_];
__device__ float g_gt[BC_*D_];
__device__ float g_o [BC_*D_];
__device__ float g_h3[BC_*D_];
__device__ float g_f12[(long)BC_*2*FF_];     // f1|f2, row stride 8192

// tf32-rounded fp32 operand buffers ([N,K] K-major for mma B operand)
__device__ float w_mem[(long)3*D_*D_];       // Wqm^T|Wkm^T|Wvm^T
__device__ float w_qkv[(long)3*D_*D_];       // Wq^T|Wk^T|Wv^T
__device__ float w_o [D_*D_];
__device__ float w_g [D_*D_];
__device__ float w_gu[(long)2*FF_*D_];       // Wgate^T|Wup^T
__device__ float w_down[(long)D_*FF_];
__device__ float t_M [B_*D_*D_];             // M^T (tf32), for NEXT chunk
__device__ float t_km[(long)B_*D_*C_];
__device__ float t_pr[(long)B_*D_*C_];
__device__ float b_qkv[3*D_];
__device__ float b_gu[2*FF_];

// ----------------------------- PTX helpers ----------------------------------
__device__ __forceinline__ uint32_t smem_u32(const void* p) {
    uint32_t a;
    asm("{ .reg .u64 t; cvta.to.shared.u64 t, %1; cvt.u32.u64 %0, t; }"
        : "=r"(a) : "l"(p));
    return a;
}
__device__ __forceinline__ uint32_t tf32_rna(float f) {
    uint32_t u;
    asm("cvt.rna.tf32.f32 %0, %1;" : "=r"(u) : "f"(f));
    return u;
}
__device__ __forceinline__ float rndf(float f) {
    return __uint_as_float(tf32_rna(f));
}
__device__ __forceinline__ void ldsm4(uint32_t& r0, uint32_t& r1, uint32_t& r2,
                                      uint32_t& r3, uint32_t addr) {
    asm volatile("ldmatrix.sync.aligned.m8n8.x4.shared.b16 {%0,%1,%2,%3}, [%4];"
                 : "=r"(r0), "=r"(r1), "=r"(r2), "=r"(r3) : "r"(addr));
}
#define CP_ASYNC16(dst, src)                                                     \
    asm volatile("cp.async.cg.shared.global [%0], [%1], 16;" :: "r"(dst), "l"(src))
#define CP_COMMIT()  asm volatile("cp.async.commit_group;")
#define CP_WAIT(n)   asm volatile("cp.async.wait_group %0;" :: "n"(n))

#define MMAT(d, a, b0, b1)                                                       \
    asm volatile(                                                                \
        "mma.sync.aligned.m16n8k8.row.col.f32.tf32.tf32.f32 "                    \
        "{%0,%1,%2,%3}, {%4,%5,%6,%7}, {%8,%9}, {%0,%1,%2,%3};"                  \
        : "+f"((d)[0]), "+f"((d)[1]), "+f"((d)[2]), "+f"((d)[3])                 \
        : "r"((a)[0]), "r"((a)[1]), "r"((a)[2]), "r"((a)[3]), "r"(b0), "r"(b1))

// ------------------- TF32 HMMA GEMM, cp.async 3-stage, ldmatrix -------------
// C = epi(alpha * A[M,K] @ B[N,K]^T). A fp32; if CVT, cvt.rna A fragments
// (else A must be pre-rounded tf32). B pre-rounded tf32.
// EPI: 0 plain; 1 +bias; 2 sigmoid(+bias); 4 acc-aux; 5 C+=acc+bias & outp;
//      9 round store; 10 +bias, round, scatter q|k|vT.
#define LDT_ 36
#define TILE_F (128 * LDT_)
#define TM_SMEM (3 * 2 * TILE_F * 4)   /* 110592 B */

template<int EPI, int CVT>
__global__ __launch_bounds__(256) void tmma_k(
    const float* __restrict__ A, const float* __restrict__ Bw,
    float* __restrict__ Cm, const float* __restrict__ bias,
    float* __restrict__ aux, int ldc, int K, int lda, int ldaux,
    long sA, long sB, long sC, float alpha, int c0)
{
    extern __shared__ float smf[];
    const int bz = blockIdx.z;
    A  += bz * sA;
    Bw += bz * sB;
    Cm += bz * sC;
    const float* auxp = (EPI == 4) ? aux + bz * sA : aux;

    const int tid = threadIdx.x, warp = tid >> 5, lane = tid & 31;
    const int n0 = blockIdx.x * 128, m0 = blockIdx.y * 128;
    const int mo = (warp >> 2) * 64, no = (warp & 3) * 32;
    const int grp = lane >> 2, tig = lane & 3;

    const int a_row = (lane & 7) + ((lane & 8) ? 8 : 0);
    const int a_col = (lane & 16) ? 4 : 0;
    const int b_row = (lane & 7) + ((lane & 16) ? 8 : 0);
    const int b_col = (lane & 8) ? 4 : 0;

    const int lr = tid >> 3;
    const int lc = (tid & 7) << 2;

    float acc[4][4][4] = {};
    const int KT = K >> 5;

#pragma unroll
    for (int s = 0; s < 2; s++) {
        const int k0 = s << 5;
        float* As = smf + s * 2 * TILE_F;
        float* Bs = As + TILE_F;
#pragma unroll
        for (int i = 0; i < 4; i++) {
            int r = lr + 32 * i;
            CP_ASYNC16(smem_u32(&As[r * LDT_ + lc]), A  + (long)(m0 + r) * lda + k0 + lc);
            CP_ASYNC16(smem_u32(&Bs[r * LDT_ + lc]), Bw + (long)(n0 + r) * K + k0 + lc);
        }
        CP_COMMIT();
    }

    for (int kt = 0; kt < KT; kt++) {
        if (kt + 1 < KT) { CP_WAIT(1); } else { CP_WAIT(0); }
        __syncthreads();

        if (kt + 2 < KT) {
            const int s = (kt + 2) % 3;
            const int k0 = (kt + 2) << 5;
            float* As = smf + s * 2 * TILE_F;
            float* Bs = As + TILE_F;
#pragma unroll
            for (int i = 0; i < 4; i++) {
                int r = lr + 32 * i;
                CP_ASYNC16(smem_u32(&As[r * LDT_ + lc]), A  + (long)(m0 + r) * lda + k0 + lc);
                CP_ASYNC16(smem_u32(&Bs[r * LDT_ + lc]), Bw + (long)(n0 + r) * K + k0 + lc);
            }
            CP_COMMIT();
        }

        const float* As = smf + (kt % 3) * 2 * TILE_F;
        const float* Bs = As + TILE_F;
        const uint32_t uA = smem_u32(As), uB = smem_u32(Bs);
#pragma unroll
        for (int k8 = 0; k8 < 4; k8++) {
            const int kc = k8 * 8;
            uint32_t a[4][4], b[4][2];
#pragma unroll
            for (int mt = 0; mt < 4; mt++) {
                uint32_t ad = uA + (uint32_t)(((mo + mt * 16 + a_row) * LDT_ + kc + a_col) * 4);
                ldsm4(a[mt][0], a[mt][1], a[mt][2], a[mt][3], ad);
                if (CVT) {
#pragma unroll
                    for (int q = 0; q < 4; q++)
                        a[mt][q] = tf32_rna(__uint_as_float(a[mt][q]));
                }
            }
            {
                uint32_t bd0 = uB + (uint32_t)(((no + b_row) * LDT_ + kc + b_col) * 4);
                ldsm4(b[0][0], b[0][1], b[1][0], b[1][1], bd0);
                uint32_t bd1 = uB + (uint32_t)(((no + 16 + b_row) * LDT_ + kc + b_col) * 4);
                ldsm4(b[2][0], b[2][1], b[3][0], b[3][1], bd1);
            }
#pragma unroll
            for (int mt = 0; mt < 4; mt++)
#pragma unroll
                for (int j = 0; j < 4; j++)
                    MMAT(acc[mt][j], a[mt], b[j][0], b[j][1]);
        }
    }

    // ------------------------------ epilogue --------------------------------
#pragma unroll
    for (int mt = 0; mt < 4; mt++) {
#pragma unroll
        for (int j = 0; j < 4; j++) {
            int row = m0 + mo + mt * 16 + grp;
            int col = n0 + no + j * 8 + tig * 2;
#pragma unroll
            for (int hh = 0; hh < 2; hh++) {
                int r = row + hh * 8;
                float v0 = acc[mt][j][hh * 2 + 0] * alpha;
                float v1 = acc[mt][j][hh * 2 + 1] * alpha;
                if (EPI == 1 || EPI == 2 || EPI == 5 || EPI == 10) {
                    float2 bv = *(const float2*)(bias + col);
                    v0 += bv.x; v1 += bv.y;
                }
                if (EPI == 10) {
                    int b = r >> 9, i = r & 511;
                    int seg = col >> 10, cl = col & 1023;
                    int h = cl >> 6, d = cl & 63;
                    float2 o;
                    o.x = rndf(v0); o.y = rndf(v1);
                    if (seg == 0)
                        *(float2*)(Cm + ((((long)b * H_ + h) * C_ + i) * DH_ + d)) = o;
                    else if (seg == 1)
                        *(float2*)(Cm + KB_OFFc + ((((long)b * H_ + h) * PCP_ + P_ + i) * DH_ + d)) = o;
                    else {
                        Cm[VB_OFFc + (((long)b * H_ + h) * DH_ + d)     * PCP_ + P_ + i] = o.x;
                        Cm[VB_OFFc + (((long)b * H_ + h) * DH_ + d + 1) * PCP_ + P_ + i] = o.y;
                    }
                } else {
                    float* cp = Cm + (long)r * ldc + col;
                    if (EPI == 2) {
                        v0 = 1.f / (1.f + expf(-v0));
                        v1 = 1.f / (1.f + expf(-v1));
                    }
                    if (EPI == 5) {
                        float2 c = *(float2*)cp;
                        v0 += c.x; v1 += c.y;
                    }
                    if (EPI == 4) {
                        float2 av = *(const float2*)(auxp + (long)r * ldaux + col);
                        v0 -= av.x; v1 -= av.y;
                    }
                    float2 o;
                    if (EPI == 9) { o.x = rndf(v0); o.y = rndf(v1); }
                    else          { o.x = v0;       o.y = v1; }
                    *(float2*)cp = o;
                    if (EPI == 5) {
                        int b = r >> 9, i = r & 511;
                        *(float2*)(aux + ((long)b * S_ + c0 + i) * D_ + col) = o;
                    }
                }
            }
        }
    }
}

// ------------------ attention scores: S = Q @ K^T * 0.125 + mask ------------
#define SC_SMEM (2 * 2 * TILE_F * 4)
__global__ __launch_bounds__(256) void attn_sc_k(
    const float* __restrict__ qb, const float* __restrict__ kb,
    float* __restrict__ sc)
{
    extern __shared__ float smf[];
    const int bh = blockIdx.z;
    const int n0 = blockIdx.x * 128, m0 = blockIdx.y * 128;
    const float* Aq = qb + (long)bh * C_ * DH_;
    const float* Bk = kb + (long)bh * PCP_ * DH_;

    const int tid = threadIdx.x, warp = tid >> 5, lane = tid & 31;
    const int mo = (warp >> 2) * 64, no = (warp & 3) * 32;
    const int grp = lane >> 2, tig = lane & 3;
    const int a_row = (lane & 7) + ((lane & 8) ? 8 : 0);
    const int a_col = (lane & 16) ? 4 : 0;
    const int b_row = (lane & 7) + ((lane & 16) ? 8 : 0);
    const int b_col = (lane & 8) ? 4 : 0;
    const int lr = tid >> 3, lc = (tid & 7) << 2;

    float acc[4][4][4] = {};

#pragma unroll
    for (int s = 0; s < 2; s++) {
        const int k0 = s << 5;
        float* As = smf + s * 2 * TILE_F;
        float* Bs = As + TILE_F;
#pragma unroll
        for (int i = 0; i < 4; i++) {
            int r = lr + 32 * i;
            CP_ASYNC16(smem_u32(&As[r * LDT_ + lc]), Aq + (long)(m0 + r) * DH_ + k0 + lc);
            CP_ASYNC16(smem_u32(&Bs[r * LDT_ + lc]), Bk + (long)(n0 + r) * DH_ + k0 + lc);
        }
        CP_COMMIT();
    }
    CP_WAIT(0);
    __syncthreads();

#pragma unroll
    for (int kt = 0; kt < 2; kt++) {
        const float* As = smf + kt * 2 * TILE_F;
        const float* Bs = As + TILE_F;
        const uint32_t uA = smem_u32(As), uB = smem_u32(Bs);
#pragma unroll
        for (int k8 = 0; k8 < 4; k8++) {
            const int kc = k8 * 8;
            uint32_t a[4][4], b[4][2];
#pragma unroll
            for (int mt = 0; mt < 4; mt++) {
                uint32_t ad = uA + (uint32_t)(((mo + mt * 16 + a_row) * LDT_ + kc + a_col) * 4);
                ldsm4(a[mt][0], a[mt][1], a[mt][2], a[mt][3], ad);
            }
            uint32_t bd0 = uB + (uint32_t)(((no + b_row) * LDT_ + kc + b_col) * 4);
            ldsm4(b[0][0], b[0][1], b[1][0], b[1][1], bd0);
            uint32_t bd1 = uB + (uint32_t)(((no + 16 + b_row) * LDT_ + kc + b_col) * 4);
            ldsm4(b[2][0], b[2][1], b[3][0], b[3][1], bd1);
#pragma unroll
            for (int mt = 0; mt < 4; mt++)
#pragma unroll
                for (int j = 0; j < 4; j++)
                    MMAT(acc[mt][j], a[mt], b[j][0], b[j][1]);
        }
    }

#pragma unroll
    for (int mt = 0; mt < 4; mt++) {
#pragma unroll
        for (int j = 0; j < 4; j++) {
            int row = m0 + mo + mt * 16 + grp;
            int col = n0 + no + j * 8 + tig * 2;
#pragma unroll
            for (int hh = 0; hh < 2; hh++) {
                int gi = row + hh * 8;
                float2 o;
                o.x = (col     < P_ || (col     - P_) <= gi) ? acc[mt][j][hh*2+0] * 0.125f : -1e9f;
                o.y = (col + 1 < P_ || (col + 1 - P_) <= gi) ? acc[mt][j][hh*2+1] * 0.125f : -1e9f;
                *(float2*)(sc + ((long)bh * C_ + gi) * PCP_ + col) = o;
            }
        }
    }
}

// ------------------- attention AV: O = P @ V (P tf32, V^T tf32) -------------
#define AV_ATILE (128 * LDT_)
#define AV_BTILE (64 * LDT_)
#define AV_STAGE (AV_ATILE + AV_BTILE)
#define AV_SMEM (3 * AV_STAGE * 4)
__global__ __launch_bounds__(256) void attn_av_k(
    const float* __restrict__ sc, const float* __restrict__ vbT,
    float* __restrict__ at)
{
    extern __shared__ float smf[];
    const int bh = blockIdx.y, b = bh >> 4, h = bh & 15;
    const int m0 = blockIdx.x * 128;
    const float* Ap = sc + ((long)bh * C_ + m0) * PCP_;
    const float* Bv = vbT + (long)bh * DH_ * PCP_;

    const int tid = threadIdx.x, warp = tid >> 5, lane = tid & 31;
    const int mo = (warp & 3) * 32, no = (warp >> 2) * 32;
    const int grp = lane >> 2, tig = lane & 3;
    const int a_row = (lane & 7) + ((lane & 8) ? 8 : 0);
    const int a_col = (lane & 16) ? 4 : 0;
    const int b_row = (lane & 7) + ((lane & 16) ? 8 : 0);
    const int b_col = (lane & 8) ? 4 : 0;
    const int lr = tid >> 3, lc = (tid & 7) << 2;

    float acc[2][4][4] = {};
    const int KT = PCP_ >> 5;

#pragma unroll
    for (int s = 0; s < 2; s++) {
        const int k0 = s << 5;
        float* As = smf + s * AV_STAGE;
        float* Bs = As + AV_ATILE;
#pragma unroll
        for (int i = 0; i < 4; i++) {
            int r = lr + 32 * i;
            CP_ASYNC16(smem_u32(&As[r * LDT_ + lc]), Ap + (long)r * PCP_ + k0 + lc);
        }
#pragma unroll
        for (int i = 0; i < 2; i++) {
            int r = lr + 32 * i;
            CP_ASYNC16(smem_u32(&Bs[r * LDT_ + lc]), Bv + (long)r * PCP_ + k0 + lc);
        }
        CP_COMMIT();
    }

    for (int kt = 0; kt < KT; kt++) {
        if (kt + 1 < KT) { CP_WAIT(1); } else { CP_WAIT(0); }
        __syncthreads();
        if (kt + 2 < KT) {
            const int s = (kt + 2) % 3;
            const int k0 = (kt + 2) << 5;
            float* As = smf + s * AV_STAGE;
            float* Bs = As + AV_ATILE;
#pragma unroll
            for (int i = 0; i < 4; i++) {
                int r = lr + 32 * i;
                CP_ASYNC16(smem_u32(&As[r * LDT_ + lc]), Ap + (long)r * PCP_ + k0 + lc);
            }
#pragma unroll
            for (int i = 0; i < 2; i++) {
                int r = lr + 32 * i;
                CP_ASYNC16(smem_u32(&Bs[r * LDT_ + lc]), Bv + (long)r * PCP_ + k0 + lc);
            }
            CP_COMMIT();
        }

        const float* As = smf + (kt % 3) * AV_STAGE;
        const float* Bs = As + AV_ATILE;
        const uint32_t uA = smem_u32(As), uB = smem_u32(Bs);
#pragma unroll
        for (int k8 = 0; k8 < 4; k8++) {
            const int kc = k8 * 8;
            uint32_t a[2][4], bq[4][2];
#pragma unroll
            for (int mt = 0; mt < 2; mt++) {
                uint32_t ad = uA + (uint32_t)(((mo + mt * 16 + a_row) * LDT_ + kc + a_col) * 4);
                ldsm4(a[mt][0], a[mt][1], a[mt][2], a[mt][3], ad);
            }
            uint32_t bd0 = uB + (uint32_t)(((no + b_row) * LDT_ + kc + b_col) * 4);
            ldsm4(bq[0][0], bq[0][1], bq[1][0], bq[1][1], bd0);
            uint32_t bd1 = uB + (uint32_t)(((no + 16 + b_row) * LDT_ + kc + b_col) * 4);
            ldsm4(bq[2][0], bq[2][1], bq[3][0], bq[3][1], bd1);
#pragma unroll
            for (int mt = 0; mt < 2; mt++)
#pragma unroll
                for (int j = 0; j < 4; j++)
                    MMAT(acc[mt][j], a[mt], bq[j][0], bq[j][1]);
        }
    }

#pragma unroll
    for (int mt = 0; mt < 2; mt++) {
#pragma unroll
        for (int j = 0; j < 4; j++) {
            int row = m0 + mo + mt * 16 + grp;
            int col = no + j * 8 + tig * 2;
#pragma unroll
            for (int hh = 0; hh < 2; hh++) {
                int gi = row + hh * 8;
                float2 o;
                o.x = rndf(acc[mt][j][hh * 2 + 0]);
                o.y = rndf(acc[mt][j][hh * 2 + 1]);
                *(float2*)(at + ((long)b * C_ + gi) * D_ + h * DH_ + col) = o;
            }
        }
    }
}

// --------- transpose + tf32-round (fp32 -> tf32-in-fp32), strided in --------
__global__ __launch_bounds__(256) void tconv_k(
    const float* __restrict__ in, float* __restrict__ out,
    int R, int ldin, long sIn, long sOut)
{
    __shared__ float t[32][33];
    in  += (long)blockIdx.z * sIn;
    out += (long)blockIdx.z * sOut;
    int r0 = blockIdx.y * 32, c0 = blockIdx.x * 32;
    int tx = threadIdx.x & 31, ty = threadIdx.x >> 5;
#pragma unroll
    for (int i = 0; i < 32; i += 8)
        t[ty + i][tx] = in[(long)(r0 + ty + i) * ldin + c0 + tx];
    __syncthreads();
#pragma unroll
    for (int i = 0; i < 32; i += 8)
        out[(long)(c0 + ty + i) * R + r0 + tx] = rndf(t[tx][ty + i]);
}

// --------------------- LayerNorm (tf32-rounded output) ----------------------
template<int MODE>   // 0: x chunk ; 1: x chunk + residual
__global__ __launch_bounds__(256) void ln_k(
    const float* __restrict__ src, const float* __restrict__ res,
    const float* __restrict__ gam, const float* __restrict__ bet,
    float* __restrict__ out, int c0)
{
    int r = blockIdx.x;
    int b = r >> 9, i = r & 511;
    const float* p = src + ((long)b * S_ + c0 + i) * D_;

    int tid = threadIdx.x;
    float v[4], s = 0.f, sq = 0.f;
#pragma unroll
    for (int k = 0; k < 4; k++) {
        int c = tid + k * 256;
        float xv = p[c];
        if (MODE == 1) xv += res[(long)r * D_ + c];
        v[k] = xv; s += xv; sq += xv * xv;
    }
    __shared__ float shs[8], shq[8];
#pragma unroll
    for (int o = 16; o; o >>= 1) {
        s  += __shfl_xor_sync(0xffffffffu, s,  o);
        sq += __shfl_xor_sync(0xffffffffu, sq, o);
    }
    if ((tid & 31) == 0) { shs[tid >> 5] = s; shq[tid >> 5] = sq; }
    __syncthreads();
    s = 0.f; sq = 0.f;
#pragma unroll
    for (int i2 = 0; i2 < 8; i2++) { s += shs[i2]; sq += shq[i2]; }
    float m  = s * (1.f / D_);
    float var = sq * (1.f / D_) - m * m;
    float rs = rsqrtf(var + 1e-5f);
#pragma unroll
    for (int k = 0; k < 4; k++) {
        int c = tid + k * 256;
        out[(long)r * D_ + c] = rndf((v[k] - m) * rs * gam[c] + bet[c]);
    }
}

// ------------- combine + LayerNorm3 fused (writes o and h3) -----------------
__global__ __launch_bounds__(256) void cln_k(
    const float* __restrict__ x, const float* __restrict__ gt,
    const float* __restrict__ ao, const float* __restrict__ mc,
    float* __restrict__ o, float* __restrict__ h3,
    const float* __restrict__ gam, const float* __restrict__ bet, int c0)
{
    int r = blockIdx.x;
    int b = r >> 9, i = r & 511;
    int tid = threadIdx.x;
    float v[4], s = 0.f, sq = 0.f;
#pragma unroll
    for (int k = 0; k < 4; k++) {
        int c = tid + k * 256;
        float xv = x[((long)b * S_ + c0 + i) * D_ + c];
        float gv = gt[(long)r * D_ + c];
        float val = xv + gv * ao[(long)r * D_ + c] + (1.f - gv) * mc[(long)r * D_ + c];
        o[(long)r * D_ + c] = val;
        v[k] = val; s += val; sq += val * val;
    }
    __shared__ float shs[8], shq[8];
#pragma unroll
    for (int w = 16; w; w >>= 1) {
        s  += __shfl_xor_sync(0xffffffffu, s,  w);
        sq += __shfl_xor_sync(0xffffffffu, sq, w);
    }
    if ((tid & 31) == 0) { shs[tid >> 5] = s; shq[tid >> 5] = sq; }
    __syncthreads();
    s = 0.f; sq = 0.f;
#pragma unroll
    for (int i2 = 0; i2 < 8; i2++) { s += shs[i2]; sq += shq[i2]; }
    float m  = s * (1.f / D_);
    float var = sq * (1.f / D_) - m * m;
    float rs = rsqrtf(var + 1e-5f);
#pragma unroll
    for (int k = 0; k < 4; k++) {
        int c = tid + k * 256;
        h3[(long)r * D_ + c] = rndf((v[k] - m) * rs * gam[c] + bet[c]);
    }
}

// ----------------- row L2 normalize (strided, tf32-rounded) -----------------
__global__ __launch_bounds__(256) void rownorm_k(float* __restrict__ km, int ld)
{
    int r = blockIdx.x, tid = threadIdx.x;
    float* p = km + (long)r * ld;
    float v[4], sq = 0.f;
#pragma unroll
    for (int k = 0; k < 4; k++) { int c = tid + k * 256; v[k] = p[c]; sq += v[k] * v[k]; }
    __shared__ float shq[8];
#pragma unroll
    for (int o = 16; o; o >>= 1) sq += __shfl_xor_sync(0xffffffffu, sq, o);
    if ((tid & 31) == 0) shq[tid >> 5] = sq;
    __syncthreads();
    sq = 0.f;
#pragma unroll
    for (int i = 0; i < 8; i++) sq += shq[i];
    float rs = rsqrtf(sq + 1e-6f);
#pragma unroll
    for (int k = 0; k < 4; k++) { int c = tid + k * 256; p[c] = rndf(v[k] * rs); }
}

// ------------------------- softmax (row length PCP) -------------------------
__global__ __launch_bounds__(256) void softmax_k(float* __restrict__ sc)
{
    float* row = sc + (long)blockIdx.x * PCP_;
    int tid = threadIdx.x;
    __shared__ float sh[8];
    float mx = -1e30f;
    for (int c = tid; c < PCP_; c += 256) mx = fmaxf(mx, row[c]);
#pragma unroll
    for (int o = 16; o; o >>= 1) mx = fmaxf(mx, __shfl_xor_sync(0xffffffffu, mx, o));
    if ((tid & 31) == 0) sh[tid >> 5] = mx;
    __syncthreads();
    mx = sh[0];
#pragma unroll
    for (int i = 1; i < 8; i++) mx = fmaxf(mx, sh[i]);
    float s = 0.f;
    float ev[3];
    int idx = 0;
    for (int c = tid; c < PCP_; c += 256, idx++) {
        float e = expf(row[c] - mx);
        ev[idx] = e; s += e;
    }
    __syncthreads();
#pragma unroll
    for (int o = 16; o; o >>= 1) s += __shfl_xor_sync(0xffffffffu, s, o);
    if ((tid & 31) == 0) sh[tid >> 5] = s;
    __syncthreads();
    s = 0.f;
#pragma unroll
    for (int i = 0; i < 8; i++) s += sh[i];
    float inv = 1.f / s;
    idx = 0;
    for (int c = tid; c < PCP_; c += 256, idx++)
        row[c] = rndf(ev[idx] * inv);
}

// ------------------------------- elementwise --------------------------------
__global__ void zero3_k(float* __restrict__ a, float* __restrict__ b,
                        float* __restrict__ c)
{
    long i = (long)blockIdx.x * 256 + threadIdx.x;
    a[i] = 0.f; b[i] = 0.f; c[i] = 0.f;
}

__global__ void fillpkv_k(const float* __restrict__ pk, const float* __restrict__ pv,
                          float* __restrict__ attn)
{
    int idx = blockIdx.x * 256 + threadIdx.x;
    int bh = idx >> 10, rem = idx & 1023;
    int p = rem >> 6, d = rem & 63;
    int h = bh & 15;
    float kv = pk[((long)p * H_ + h) * DH_ + d];
    float vv = pv[((long)p * H_ + h) * DH_ + d];
    attn[KB_OFFc + ((long)bh * PCP_ + p) * DH_ + d] = rndf(kv);
    attn[VB_OFFc + ((long)bh * DH_ + d) * PCP_ + p] = rndf(vv);
}

__global__ void cat3_k(const float* __restrict__ a, const float* __restrict__ b,
                       const float* __restrict__ c, float* __restrict__ out,
                       int na, int nb)
{
    int i = blockIdx.x * 256 + threadIdx.x;
    out[i] = (i < na) ? a[i] : (i < na + nb) ? b[i - na] : c[i - na - nb];
}

// ----------- M/S update fused with transposed tf32 tM production ------------
__global__ __launch_bounds__(256) void updtr_k(
    float* __restrict__ M, float* __restrict__ S, const float* __restrict__ grad,
    const float* __restrict__ lr, const float* __restrict__ mom,
    const float* __restrict__ fg, float* __restrict__ tM)
{
    __shared__ float t[32][33];
    int b = blockIdx.z;
    int r0 = blockIdx.y * 32, c0 = blockIdx.x * 32;
    int tx = threadIdx.x & 31, ty = threadIdx.x >> 5;
    float th = 1.f / (1.f + expf(-lr[0]));
    float et = 1.f / (1.f + expf(-mom[0]));
    float al = 1.f / (1.f + expf(-fg[0]));
#pragma unroll
    for (int i = 0; i < 32; i += 8) {
        long idx = ((long)b * D_ + r0 + ty + i) * D_ + c0 + tx;
        float s = et * S[idx] - th * grad[idx];
        S[idx] = s;
        float m = (1.f - al) * M[idx] + s;
        M[idx] = m;
        t[ty + i][tx] = m;
    }
    __syncthreads();
#pragma unroll
    for (int i = 0; i < 32; i += 8)
        tM[((long)b * D_ + c0 + ty + i) * D_ + r0 + tx] = rndf(t[tx][ty + i]);
}

__global__ void silu_mul_k(float* __restrict__ f12)
{
    long idx = (long)blockIdx.x * 256 + threadIdx.x;
    long r = idx >> 12, c = idx & 4095;
    float v = f12[r * 8192 + c];
    f12[r * 8192 + c] = rndf(v / (1.f + expf(-v)) * f12[r * 8192 + 4096 + c]);
}

// --------------------------------- launch -----------------------------------
extern "C" void kernel_launch(void* const* d_in, const int* in_sizes, int n_in,
                              void* d_out, int out_size)
{
    const float* x     = (const float*)d_in[0];
    const float* g1    = (const float*)d_in[1];
    const float* b1    = (const float*)d_in[2];
    const float* g2    = (const float*)d_in[3];
    const float* b2    = (const float*)d_in[4];
    const float* g3    = (const float*)d_in[5];
    const float* b3    = (const float*)d_in[6];
    const float* Wqm   = (const float*)d_in[7];
    const float* Wkm   = (const float*)d_in[8];
    const float* Wvm   = (const float*)d_in[9];
    const float* lr    = (const float*)d_in[10];
    const float* mom   = (const float*)d_in[11];
    const float* fg    = (const float*)d_in[12];
    const float* Wq    = (const float*)d_in[13];
    const float* bq    = (const float*)d_in[14];
    const float* Wk    = (const float*)d_in[15];
    const float* bk    = (const float*)d_in[16];
    const float* Wv    = (const float*)d_in[17];
    const float* bv    = (const float*)d_in[18];
    const float* Wo    = (const float*)d_in[19];
    const float* bo    = (const float*)d_in[20];
    const float* pk    = (const float*)d_in[21];
    const float* pv    = (const float*)d_in[22];
    const float* Wg    = (const float*)d_in[23];
    const float* bg    = (const float*)d_in[24];
    const float* Wgate = (const float*)d_in[25];
    const float* bgate = (const float*)d_in[26];
    const float* Wup   = (const float*)d_in[27];
    const float* bup   = (const float*)d_in[28];
    const float* Wdown = (const float*)d_in[29];
    const float* bdown = (const float*)d_in[30];
    float* outp = (float*)d_out;

    float *h1, *qkvm, *mc, *pr, *grad, *Mm, *Sm, *h2, *attn, *sc, *at, *ao, *gt;
    float *o, *h3, *f12;
    float *wmem, *wqkv, *wo, *wg, *wgu, *wdown;
    float *tM, *tkm, *tpr, *bqkv, *bgu;
    cudaGetSymbolAddress((void**)&h1, g_h1);
    cudaGetSymbolAddress((void**)&qkvm, g_qkvm);
    cudaGetSymbolAddress((void**)&mc, g_mc);
    cudaGetSymbolAddress((void**)&pr, g_pr);
    cudaGetSymbolAddress((void**)&grad, g_grad);
    cudaGetSymbolAddress((void**)&Mm, g_Mst);
    cudaGetSymbolAddress((void**)&Sm, g_Sst);
    cudaGetSymbolAddress((void**)&h2, g_h2);
    cudaGetSymbolAddress((void**)&attn, g_attn);
    cudaGetSymbolAddress((void**)&sc, g_sc);
    cudaGetSymbolAddress((void**)&at, g_at);
    cudaGetSymbolAddress((void**)&ao, g_ao);
    cudaGetSymbolAddress((void**)&gt, g_gt);
    cudaGetSymbolAddress((void**)&o,  g_o);
    cudaGetSymbolAddress((void**)&h3, g_h3);
    cudaGetSymbolAddress((void**)&f12, g_f12);
    cudaGetSymbolAddress((void**)&wmem, w_mem);
    cudaGetSymbolAddress((void**)&wqkv, w_qkv);
    cudaGetSymbolAddress((void**)&wo,  w_o);
    cudaGetSymbolAddress((void**)&wg,  w_g);
    cudaGetSymbolAddress((void**)&wgu, w_gu);
    cudaGetSymbolAddress((void**)&wdown, w_down);
    cudaGetSymbolAddress((void**)&tM,  t_M);
    cudaGetSymbolAddress((void**)&tkm, t_km);
    cudaGetSymbolAddress((void**)&tpr, t_pr);
    cudaGetSymbolAddress((void**)&bqkv, b_qkv);
    cudaGetSymbolAddress((void**)&bgu,  b_gu);

    cudaFuncSetAttribute(tmma_k<0,0>,  cudaFuncAttributeMaxDynamicSharedMemorySize, TM_SMEM);
    cudaFuncSetAttribute(tmma_k<1,0>,  cudaFuncAttributeMaxDynamicSharedMemorySize, TM_SMEM);
    cudaFuncSetAttribute(tmma_k<2,1>,  cudaFuncAttributeMaxDynamicSharedMemorySize, TM_SMEM);
    cudaFuncSetAttribute(tmma_k<4,0>,  cudaFuncAttributeMaxDynamicSharedMemorySize, TM_SMEM);
    cudaFuncSetAttribute(tmma_k<5,0>,  cudaFuncAttributeMaxDynamicSharedMemorySize, TM_SMEM);
    cudaFuncSetAttribute(tmma_k<9,0>,  cudaFuncAttributeMaxDynamicSharedMemorySize, TM_SMEM);
    cudaFuncSetAttribute(tmma_k<10,0>, cudaFuncAttributeMaxDynamicSharedMemorySize, TM_SMEM);
    cudaFuncSetAttribute(attn_sc_k, cudaFuncAttributeMaxDynamicSharedMemorySize, SC_SMEM);
    cudaFuncSetAttribute(attn_av_k, cudaFuncAttributeMaxDynamicSharedMemorySize, AV_SMEM);

    const long ND   = (long)B_ * D_ * D_;
    const long NBF  = (long)BC_ * FF_;
    const long sQK  = (long)C_ * 3 * D_;    // batch stride in qkvm
    const long sDD  = (long)D_ * D_;
    const long sDC  = (long)D_ * C_;
    const long sCD  = (long)C_ * D_;

    zero3_k<<<(unsigned)(ND / 256), 256>>>(Mm, Sm, tM);
    fillpkv_k<<<256, 256>>>(pk, pv, attn);
    cat3_k<<<12, 256>>>(bq, bk, bv, bqkv, D_, D_);
    cat3_k<<<32, 256>>>(bgate, bup, bup, bgu, FF_, FF_);

    dim3 t256(256);
    tconv_k<<<dim3(D_/32,  D_/32, 1), t256>>>(Wqm,   wmem,              D_,  D_,  0, 0);
    tconv_k<<<dim3(D_/32,  D_/32, 1), t256>>>(Wkm,   wmem + sDD,        D_,  D_,  0, 0);
    tconv_k<<<dim3(D_/32,  D_/32, 1), t256>>>(Wvm,   wmem + 2 * sDD,    D_,  D_,  0, 0);
    tconv_k<<<dim3(D_/32,  D_/32, 1), t256>>>(Wq,    wqkv,              D_,  D_,  0, 0);
    tconv_k<<<dim3(D_/32,  D_/32, 1), t256>>>(Wk,    wqkv + sDD,        D_,  D_,  0, 0);
    tconv_k<<<dim3(D_/32,  D_/32, 1), t256>>>(Wv,    wqkv + 2 * sDD,    D_,  D_,  0, 0);
    tconv_k<<<dim3(D_/32,  D_/32, 1), t256>>>(Wo,    wo,                D_,  D_,  0, 0);
    tconv_k<<<dim3(D_/32,  D_/32, 1), t256>>>(Wg,    wg,                D_,  D_,  0, 0);
    tconv_k<<<dim3(FF_/32, D_/32, 1), t256>>>(Wgate, wgu,               D_,  FF_, 0, 0);
    tconv_k<<<dim3(FF_/32, D_/32, 1), t256>>>(Wup,   wgu + (long)FF_*D_, D_, FF_, 0, 0);
    tconv_k<<<dim3(D_/32, FF_/32, 1), t256>>>(Wdown, wdown,             FF_, D_,  0, 0);

    for (int t = 0; t < NC_; t++) {
        int c0 = t * C_;
        // --- neural memory ---
        ln_k<0><<<BC_, 256>>>(x, nullptr, g1, b1, h1, c0);
        tmma_k<9,0><<<dim3(24,16), 256, TM_SMEM>>>(h1, wmem, qkvm, nullptr, nullptr,
            3*D_, D_, D_, 0, 0, 0, 0, 1.f, 0);
        rownorm_k<<<BC_, 256>>>(qkvm + D_, 3*D_);
        tmma_k<0,0><<<dim3(8,4,B_), 256, TM_SMEM>>>(qkvm, tM, mc, nullptr, nullptr,
            D_, D_, 3*D_, 0, sQK, sDD, sCD, 1.f, 0);
        tmma_k<4,0><<<dim3(8,4,B_), 256, TM_SMEM>>>(qkvm + D_, tM, pr, nullptr, qkvm + 2*D_,
            D_, D_, 3*D_, 3*D_, sQK, sDD, sCD, 1.f, 0);
        tconv_k<<<dim3(D_/32, C_/32, B_), t256>>>(qkvm + D_, tkm, C_, 3*D_, sQK, sDC);
        tconv_k<<<dim3(D_/32, C_/32, B_), t256>>>(pr, tpr, C_, D_, sCD, sDC);
        tmma_k<0,0><<<dim3(8,8,B_), 256, TM_SMEM>>>(tkm, tpr, grad, nullptr, nullptr,
            D_, C_, C_, 0, sDC, sDC, sDD, 1.f / C_, 0);
        updtr_k<<<dim3(32,32,B_), 256>>>(Mm, Sm, grad, lr, mom, fg, tM);

        // --- attention with persistent tokens ---
        ln_k<1><<<BC_, 256>>>(x, mc, g2, b2, h2, c0);
        tmma_k<10,0><<<dim3(24,16), 256, TM_SMEM>>>(h2, wqkv, attn, bqkv, nullptr,
            0, D_, D_, 0, 0, 0, 0, 1.f, 0);
        attn_sc_k<<<dim3(PCP_/128, C_/128, BH_), 256, SC_SMEM>>>(attn, attn + KB_OFFc, sc);
        softmax_k<<<BH_ * C_, 256>>>(sc);
        attn_av_k<<<dim3(C_/128, BH_), 256, AV_SMEM>>>(sc, attn + VB_OFFc, at);
        tmma_k<1,0><<<dim3(8,16), 256, TM_SMEM>>>(at, wo, ao, bo, nullptr,
            D_, D_, D_, 0, 0, 0, 0, 1.f, 0);
        tmma_k<2,1><<<dim3(8,16), 256, TM_SMEM>>>(mc, wg, gt, bg, nullptr,
            D_, D_, D_, 0, 0, 0, 0, 1.f, 0);
        cln_k<<<BC_, 256>>>(x, gt, ao, mc, o, h3, g3, b3, c0);

        // --- gated FFN ---
        tmma_k<1,0><<<dim3(64,16), 256, TM_SMEM>>>(h3, wgu, f12, bgu, nullptr,
            2*FF_, D_, D_, 0, 0, 0, 0, 1.f, 0);
        silu_mul_k<<<(unsigned)(NBF / 256), 256>>>(f12);
        tmma_k<5,0><<<dim3(8,16), 256, TM_SMEM>>>(f12, wdown, o, bdown, outp,
            D_, FF_, 2*FF_, 0, 0, 0, 0, 1.f, c0);
    }
}

// round 9
// speedup vs baseline: 5.8894x; 1.2275x over previous
#include <cuda_runtime.h>
#include <cuda_fp16.h>
#include <math.h>
#include <stdint.h>

#define D_  1024
#define H_  16
#define DH_ 64
#define P_  16
#define C_  512
#define B_  4
#define S_  4096
#define FF_ 4096
#define NC_ 8
#define BC_ (B_*C_)      /* 2048 */
#define PCP_ 640         /* padded key length (5*128) */
#define BH_ (B_*H_)      /* 64   */

static constexpr long KB_OFF = (long)BH_ * C_ * DH_;
static constexpr long VB_OFF = KB_OFF + (long)BH_ * PCP_ * DH_;
static constexpr long ATTN_SZ = VB_OFF + (long)BH_ * DH_ * PCP_;

// ------------------------- scratch (device globals) -------------------------
__device__ __align__(16) __half g_h1[BC_*D_];
__device__ __align__(16) __half g_qkvm[(long)BC_*3*D_];   // qm|km|vm (half)
__device__ float g_mc[BC_*D_];
__device__ __align__(16) __half g_mch[BC_*D_];
__device__ float g_pr[BC_*D_];
__device__ float g_grad[B_*D_*D_];
__device__ float g_Mst[B_*D_*D_];
__device__ float g_Sst[B_*D_*D_];
__device__ __align__(16) __half g_h2[BC_*D_];
__device__ __align__(16) __half g_attn[(size_t)ATTN_SZ]; // qb | kb | vbT
__device__ float g_sc[(long)BH_*C_*PCP_];
__device__ __align__(16) __half g_scp[(long)BH_*C_*PCP_];
__device__ __align__(16) __half g_at[BC_*D_];
__device__ float g_ao[BC_*D_];
__device__ float g_gt[BC_*D_];
__device__ float g_o [BC_*D_];
__device__ __align__(16) __half g_h3[BC_*D_];
__device__ float g_f12[(long)BC_*2*FF_];
__device__ __align__(16) __half g_fs[(long)BC_*FF_];

// half operand buffers ([N,K] K-major for mma B operand)
__device__ __align__(16) __half w_mem[(long)3*D_*D_];
__device__ __align__(16) __half w_qkv[(long)3*D_*D_];
__device__ __align__(16) __half w_o [D_*D_];
__device__ __align__(16) __half w_g [D_*D_];
__device__ __align__(16) __half w_gu[(long)2*FF_*D_];
__device__ __align__(16) __half w_down[(long)D_*FF_];
__device__ __align__(16) __half t_M [B_*D_*D_];
__device__ __align__(16) __half t_km[(long)B_*D_*C_];
__device__ __align__(16) __half t_pr[(long)B_*D_*C_];
__device__ float b_qkv[3*D_];
__device__ float b_gu[2*FF_];

// ----------------------------- PTX helpers ----------------------------------
__device__ __forceinline__ uint32_t smem_u32(const void* p) {
    uint32_t a;
    asm("{ .reg .u64 t; cvta.to.shared.u64 t, %1; cvt.u32.u64 %0, t; }"
        : "=r"(a) : "l"(p));
    return a;
}
__device__ __forceinline__ void ldsm4(uint32_t& r0, uint32_t& r1, uint32_t& r2,
                                      uint32_t& r3, uint32_t addr) {
    asm volatile("ldmatrix.sync.aligned.m8n8.x4.shared.b16 {%0,%1,%2,%3}, [%4];"
                 : "=r"(r0), "=r"(r1), "=r"(r2), "=r"(r3) : "r"(addr));
}
#define CP_ASYNC16(dst, src)                                                     \
    asm volatile("cp.async.cg.shared.global [%0], [%1], 16;" :: "r"(dst), "l"(src))
#define CP_COMMIT()  asm volatile("cp.async.commit_group;")
#define CP_WAIT(n)   asm volatile("cp.async.wait_group %0;" :: "n"(n))

#define MMAH(d, a, b0, b1)                                                       \
    asm volatile(                                                                \
        "mma.sync.aligned.m16n8k16.row.col.f32.f16.f16.f32 "                     \
        "{%0,%1,%2,%3}, {%4,%5,%6,%7}, {%8,%9}, {%0,%1,%2,%3};"                  \
        : "+f"((d)[0]), "+f"((d)[1]), "+f"((d)[2]), "+f"((d)[3])                 \
        : "r"((a)[0]), "r"((a)[1]), "r"((a)[2]), "r"((a)[3]), "r"(b0), "r"(b1))

// -------------------- FP16 HMMA GEMM, cp.async 3-stage ----------------------
// C = epi(alpha * A[M,K] @ B[N,K]^T). A,B pre-rounded __half. fp32 accum.
// CTA 128x128, K-step 32, 3-stage. EPI: 0 plain fp32; 1 +bias; 2 sigmoid(+bias);
// 4 acc - half-aux; 5 C+=acc+bias & outp; 9 half store; 10 +bias half qkv-scatter;
// 11 dual fp32 + half.
#define LDH_ 40
#define HT_ (128 * LDH_)
#define TM_SMEM (3 * 2 * HT_ * 2)   /* 61440 B */

template<int EPI>
__global__ __launch_bounds__(256, 2) void hmma_k(
    const __half* __restrict__ A, const __half* __restrict__ Bw,
    float* __restrict__ Cm, const float* __restrict__ bias,
    void* __restrict__ aux, int ldc, int K, int lda, int ldaux,
    long sA, long sB, long sC, float alpha, int c0)
{
    extern __shared__ __half smh[];
    const int bz = blockIdx.z;
    A  += bz * sA;
    Bw += bz * sB;
    Cm += bz * sC;
    const __half* auxh4  = (EPI == 4)  ? (const __half*)aux + bz * sA : nullptr;
    __half*       auxh11 = (EPI == 11) ? (__half*)aux + bz * sC : nullptr;

    const int tid = threadIdx.x, warp = tid >> 5, lane = tid & 31;
    const int n0 = blockIdx.x * 128, m0 = blockIdx.y * 128;
    const int mo = (warp >> 2) * 64, no = (warp & 3) * 32;
    const int grp = lane >> 2, tig = lane & 3;
    const int lrow = lane & 15, lcol = (lane >> 4) << 3;

    const int lr = tid >> 1;
    const int lc = (tid & 1) << 4;   // halves

    float acc[4][4][4] = {};
    const int KT = K >> 5;

#pragma unroll
    for (int s = 0; s < 2; s++) {
        const int k0 = s << 5;
        __half* As = smh + s * 2 * HT_;
        __half* Bs = As + HT_;
#pragma unroll
        for (int j = 0; j < 2; j++) {
            CP_ASYNC16(smem_u32(&As[lr * LDH_ + lc + 8 * j]), A  + (long)(m0 + lr) * lda + k0 + lc + 8 * j);
            CP_ASYNC16(smem_u32(&Bs[lr * LDH_ + lc + 8 * j]), Bw + (long)(n0 + lr) * K + k0 + lc + 8 * j);
        }
        CP_COMMIT();
    }

    for (int kt = 0; kt < KT; kt++) {
        if (kt + 1 < KT) { CP_WAIT(1); } else { CP_WAIT(0); }
        __syncthreads();

        if (kt + 2 < KT) {
            const int s = (kt + 2) % 3;
            const int k0 = (kt + 2) << 5;
            __half* As = smh + s * 2 * HT_;
            __half* Bs = As + HT_;
#pragma unroll
            for (int j = 0; j < 2; j++) {
                CP_ASYNC16(smem_u32(&As[lr * LDH_ + lc + 8 * j]), A  + (long)(m0 + lr) * lda + k0 + lc + 8 * j);
                CP_ASYNC16(smem_u32(&Bs[lr * LDH_ + lc + 8 * j]), Bw + (long)(n0 + lr) * K + k0 + lc + 8 * j);
            }
            CP_COMMIT();
        }

        const __half* As = smh + (kt % 3) * 2 * HT_;
        const __half* Bs = As + HT_;
        const uint32_t uA = smem_u32(As), uB = smem_u32(Bs);
#pragma unroll
        for (int h = 0; h < 2; h++) {
            uint32_t a[4][4], q[8];
#pragma unroll
            for (int mt = 0; mt < 4; mt++) {
                uint32_t ad = uA + (uint32_t)(((mo + mt * 16 + lrow) * LDH_ + h * 16 + lcol) * 2);
                ldsm4(a[mt][0], a[mt][1], a[mt][2], a[mt][3], ad);
            }
#pragma unroll
            for (int g = 0; g < 2; g++) {
                uint32_t bd = smem_u32(&Bs[(no + g * 16 + lrow) * LDH_ + h * 16 + lcol]);
                ldsm4(q[g * 4 + 0], q[g * 4 + 1], q[g * 4 + 2], q[g * 4 + 3], bd);
            }
#pragma unroll
            for (int mt = 0; mt < 4; mt++)
#pragma unroll
                for (int j = 0; j < 4; j++) {
                    uint32_t b0 = q[(j >> 1) * 4 + (j & 1)];
                    uint32_t b1 = q[(j >> 1) * 4 + (j & 1) + 2];
                    MMAH(acc[mt][j], a[mt], b0, b1);
                }
        }
    }

    // ------------------------------ epilogue --------------------------------
#pragma unroll
    for (int mt = 0; mt < 4; mt++) {
#pragma unroll
        for (int j = 0; j < 4; j++) {
            int row = m0 + mo + mt * 16 + grp;
            int col = n0 + no + j * 8 + tig * 2;
#pragma unroll
            for (int hh = 0; hh < 2; hh++) {
                int r = row + hh * 8;
                float v0 = acc[mt][j][hh * 2 + 0] * alpha;
                float v1 = acc[mt][j][hh * 2 + 1] * alpha;
                if (EPI == 1 || EPI == 2 || EPI == 5 || EPI == 10) {
                    float2 bv = *(const float2*)(bias + col);
                    v0 += bv.x; v1 += bv.y;
                }
                if (EPI == 9) {
                    __half* Ch = (__half*)Cm;
                    *(__half2*)(Ch + (long)r * ldc + col) = __floats2half2_rn(v0, v1);
                } else if (EPI == 10) {
                    __half* Ch = (__half*)Cm;
                    int b = r >> 9, i = r & 511;
                    int seg = col >> 10, cl = col & 1023;
                    int h = cl >> 6, d = cl & 63;
                    __half2 o = __floats2half2_rn(v0, v1);
                    if (seg == 0)
                        *(__half2*)(Ch + ((((long)b * H_ + h) * C_ + i) * DH_ + d)) = o;
                    else if (seg == 1)
                        *(__half2*)(Ch + KB_OFF + ((((long)b * H_ + h) * PCP_ + P_ + i) * DH_ + d)) = o;
                    else {
                        Ch[VB_OFF + (((long)b * H_ + h) * DH_ + d)     * PCP_ + P_ + i] = __float2half_rn(v0);
                        Ch[VB_OFF + (((long)b * H_ + h) * DH_ + d + 1) * PCP_ + P_ + i] = __float2half_rn(v1);
                    }
                } else {
                    float* cp = Cm + (long)r * ldc + col;
                    if (EPI == 2) {
                        v0 = 1.f / (1.f + expf(-v0));
                        v1 = 1.f / (1.f + expf(-v1));
                    }
                    if (EPI == 5) {
                        float2 c = *(float2*)cp;
                        v0 += c.x; v1 += c.y;
                    }
                    if (EPI == 4) {
                        float2 av = __half22float2(*(const __half2*)(auxh4 + (long)r * ldaux + col));
                        v0 -= av.x; v1 -= av.y;
                    }
                    float2 o; o.x = v0; o.y = v1;
                    *(float2*)cp = o;
                    if (EPI == 5) {
                        int b = r >> 9, i = r & 511;
                        *(float2*)((float*)aux + ((long)b * S_ + c0 + i) * D_ + col) = o;
                    }
                    if (EPI == 11)
                        *(__half2*)(auxh11 + (long)r * ldc + col) = __floats2half2_rn(v0, v1);
                }
            }
        }
    }
}

// ------------------ attention scores: S = Q @ K^T * 0.125 + mask ------------
#define SC_LD 72
#define SC_SMEM (2 * 128 * SC_LD * 2)   /* 36864 B */
__global__ __launch_bounds__(256, 2) void attn_sc_k(
    const __half* __restrict__ qb, const __half* __restrict__ kb,
    float* __restrict__ sc)
{
    extern __shared__ __half smh[];
    __half* As = smh;
    __half* Bs = smh + 128 * SC_LD;
    const int bh = blockIdx.z;
    const int n0 = blockIdx.x * 128, m0 = blockIdx.y * 128;
    const __half* Aq = qb + (long)bh * C_ * DH_;
    const __half* Bk = kb + (long)bh * PCP_ * DH_;

    const int tid = threadIdx.x, warp = tid >> 5, lane = tid & 31;
    const int mo = (warp >> 2) * 64, no = (warp & 3) * 32;
    const int grp = lane >> 2, tig = lane & 3;
    const int lrow = lane & 15, lcol = (lane >> 4) << 3;
    const int lr = tid >> 1, lc = (tid & 1) << 5;

    float acc[4][4][4] = {};

#pragma unroll
    for (int j = 0; j < 4; j++) {
        CP_ASYNC16(smem_u32(&As[lr * SC_LD + lc + 8 * j]), Aq + (long)(m0 + lr) * DH_ + lc + 8 * j);
        CP_ASYNC16(smem_u32(&Bs[lr * SC_LD + lc + 8 * j]), Bk + (long)(n0 + lr) * DH_ + lc + 8 * j);
    }
    CP_COMMIT();
    CP_WAIT(0);
    __syncthreads();

    const uint32_t uA = smem_u32(As);
#pragma unroll
    for (int h = 0; h < 4; h++) {
        uint32_t a[4][4], q[8];
#pragma unroll
        for (int mt = 0; mt < 4; mt++) {
            uint32_t ad = uA + (uint32_t)(((mo + mt * 16 + lrow) * SC_LD + h * 16 + lcol) * 2);
            ldsm4(a[mt][0], a[mt][1], a[mt][2], a[mt][3], ad);
        }
#pragma unroll
        for (int g = 0; g < 2; g++) {
            uint32_t bd = smem_u32(&Bs[(no + g * 16 + lrow) * SC_LD + h * 16 + lcol]);
            ldsm4(q[g * 4 + 0], q[g * 4 + 1], q[g * 4 + 2], q[g * 4 + 3], bd);
        }
#pragma unroll
        for (int mt = 0; mt < 4; mt++)
#pragma unroll
            for (int j = 0; j < 4; j++) {
                uint32_t b0 = q[(j >> 1) * 4 + (j & 1)];
                uint32_t b1 = q[(j >> 1) * 4 + (j & 1) + 2];
                MMAH(acc[mt][j], a[mt], b0, b1);
            }
    }

#pragma unroll
    for (int mt = 0; mt < 4; mt++) {
#pragma unroll
        for (int j = 0; j < 4; j++) {
            int row = m0 + mo + mt * 16 + grp;
            int col = n0 + no + j * 8 + tig * 2;
#pragma unroll
            for (int hh = 0; hh < 2; hh++) {
                int gi = row + hh * 8;
                float2 o;
                o.x = (col     < P_ || (col     - P_) <= gi) ? acc[mt][j][hh*2+0] * 0.125f : -1e9f;
                o.y = (col + 1 < P_ || (col + 1 - P_) <= gi) ? acc[mt][j][hh*2+1] * 0.125f : -1e9f;
                *(float2*)(sc + ((long)bh * C_ + gi) * PCP_ + col) = o;
            }
        }
    }
}

// ------------------- attention AV: O = P @ V (half) -------------------------
#define AV_AT (128 * LDH_)
#define AV_BT (64 * LDH_)
#define AV_ST (AV_AT + AV_BT)
#define AV_SMEM (3 * AV_ST * 2)
__global__ __launch_bounds__(256, 2) void attn_av_k(
    const __half* __restrict__ scp, const __half* __restrict__ vbT,
    __half* __restrict__ at)
{
    extern __shared__ __half smh[];
    const int bh = blockIdx.y, b = bh >> 4, h = bh & 15;
    const int m0 = blockIdx.x * 128;
    const __half* Ap = scp + ((long)bh * C_ + m0) * PCP_;
    const __half* Bv = vbT + (long)bh * DH_ * PCP_;

    const int tid = threadIdx.x, warp = tid >> 5, lane = tid & 31;
    const int mo = (warp & 3) * 32, no = (warp >> 2) * 32;
    const int grp = lane >> 2, tig = lane & 3;
    const int lrow = lane & 15, lcol = (lane >> 4) << 3;
    const int lra = tid >> 1, lca = (tid & 1) << 4;
    const int lrb = tid >> 2, lcb = (tid & 3) << 3;

    float acc[2][4][4] = {};
    const int KT = PCP_ >> 5;

#pragma unroll
    for (int s = 0; s < 2; s++) {
        const int k0 = s << 5;
        __half* As = smh + s * AV_ST;
        __half* Bs = As + AV_AT;
#pragma unroll
        for (int j = 0; j < 2; j++)
            CP_ASYNC16(smem_u32(&As[lra * LDH_ + lca + 8 * j]), Ap + (long)lra * PCP_ + k0 + lca + 8 * j);
        CP_ASYNC16(smem_u32(&Bs[lrb * LDH_ + lcb]), Bv + (long)lrb * PCP_ + k0 + lcb);
        CP_COMMIT();
    }

    for (int kt = 0; kt < KT; kt++) {
        if (kt + 1 < KT) { CP_WAIT(1); } else { CP_WAIT(0); }
        __syncthreads();
        if (kt + 2 < KT) {
            const int s = (kt + 2) % 3;
            const int k0 = (kt + 2) << 5;
            __half* As = smh + s * AV_ST;
            __half* Bs = As + AV_AT;
#pragma unroll
            for (int j = 0; j < 2; j++)
                CP_ASYNC16(smem_u32(&As[lra * LDH_ + lca + 8 * j]), Ap + (long)lra * PCP_ + k0 + lca + 8 * j);
            CP_ASYNC16(smem_u32(&Bs[lrb * LDH_ + lcb]), Bv + (long)lrb * PCP_ + k0 + lcb);
            CP_COMMIT();
        }

        const __half* As = smh + (kt % 3) * AV_ST;
        const __half* Bs = As + AV_AT;
        const uint32_t uA = smem_u32(As);
#pragma unroll
        for (int h2 = 0; h2 < 2; h2++) {
            uint32_t a[2][4], q[8];
#pragma unroll
            for (int mt = 0; mt < 2; mt++) {
                uint32_t ad = uA + (uint32_t)(((mo + mt * 16 + lrow) * LDH_ + h2 * 16 + lcol) * 2);
                ldsm4(a[mt][0], a[mt][1], a[mt][2], a[mt][3], ad);
            }
#pragma unroll
            for (int g = 0; g < 2; g++) {
                uint32_t bd = smem_u32(&Bs[(no + g * 16 + lrow) * LDH_ + h2 * 16 + lcol]);
                ldsm4(q[g * 4 + 0], q[g * 4 + 1], q[g * 4 + 2], q[g * 4 + 3], bd);
            }
#pragma unroll
            for (int mt = 0; mt < 2; mt++)
#pragma unroll
                for (int j = 0; j < 4; j++) {
                    uint32_t b0 = q[(j >> 1) * 4 + (j & 1)];
                    uint32_t b1 = q[(j >> 1) * 4 + (j & 1) + 2];
                    MMAH(acc[mt][j], a[mt], b0, b1);
                }
        }
    }

#pragma unroll
    for (int mt = 0; mt < 2; mt++) {
#pragma unroll
        for (int j = 0; j < 4; j++) {
            int row = m0 + mo + mt * 16 + grp;
            int col = no + j * 8 + tig * 2;
#pragma unroll
            for (int hh = 0; hh < 2; hh++) {
                int gi = row + hh * 8;
                *(__half2*)(at + ((long)b * C_ + gi) * D_ + h * DH_ + col) =
                    __floats2half2_rn(acc[mt][j][hh * 2 + 0], acc[mt][j][hh * 2 + 1]);
            }
        }
    }
}

// ------------------- transpose converts -------------------------------------
__global__ __launch_bounds__(256) void tconvfh_k(
    const float* __restrict__ in, __half* __restrict__ out,
    int R, int ldin, long sIn, long sOut)
{
    __shared__ float t[32][33];
    in  += (long)blockIdx.z * sIn;
    out += (long)blockIdx.z * sOut;
    int r0 = blockIdx.y * 32, c0 = blockIdx.x * 32;
    int tx = threadIdx.x & 31, ty = threadIdx.x >> 5;
#pragma unroll
    for (int i = 0; i < 32; i += 8)
        t[ty + i][tx] = in[(long)(r0 + ty + i) * ldin + c0 + tx];
    __syncthreads();
#pragma unroll
    for (int i = 0; i < 32; i += 8)
        out[(long)(c0 + ty + i) * R + r0 + tx] = __float2half_rn(t[tx][ty + i]);
}

__global__ __launch_bounds__(256) void tconvhh_k(
    const __half* __restrict__ in, __half* __restrict__ out,
    int R, int ldin, long sIn, long sOut)
{
    __shared__ __half t[32][34];
    in  += (long)blockIdx.z * sIn;
    out += (long)blockIdx.z * sOut;
    int r0 = blockIdx.y * 32, c0 = blockIdx.x * 32;
    int tx = threadIdx.x & 31, ty = threadIdx.x >> 5;
#pragma unroll
    for (int i = 0; i < 32; i += 8)
        t[ty + i][tx] = in[(long)(r0 + ty + i) * ldin + c0 + tx];
    __syncthreads();
#pragma unroll
    for (int i = 0; i < 32; i += 8)
        out[(long)(c0 + ty + i) * R + r0 + tx] = t[tx][ty + i];
}

// --------------------- LayerNorm (half output) ------------------------------
template<int MODE>   // 0: x chunk ; 1: x chunk + residual(fp32)
__global__ __launch_bounds__(256) void ln_k(
    const float* __restrict__ src, const float* __restrict__ res,
    const float* __restrict__ gam, const float* __restrict__ bet,
    __half* __restrict__ out, int c0)
{
    int r = blockIdx.x;
    int b = r >> 9, i = r & 511;
    const float* p = src + ((long)b * S_ + c0 + i) * D_;

    int tid = threadIdx.x;
    float v[4], s = 0.f, sq = 0.f;
#pragma unroll
    for (int k = 0; k < 4; k++) {
        int c = tid + k * 256;
        float xv = p[c];
        if (MODE == 1) xv += res[(long)r * D_ + c];
        v[k] = xv; s += xv; sq += xv * xv;
    }
    __shared__ float shs[8], shq[8];
#pragma unroll
    for (int o = 16; o; o >>= 1) {
        s  += __shfl_xor_sync(0xffffffffu, s,  o);
        sq += __shfl_xor_sync(0xffffffffu, sq, o);
    }
    if ((tid & 31) == 0) { shs[tid >> 5] = s; shq[tid >> 5] = sq; }
    __syncthreads();
    s = 0.f; sq = 0.f;
#pragma unroll
    for (int i2 = 0; i2 < 8; i2++) { s += shs[i2]; sq += shq[i2]; }
    float m  = s * (1.f / D_);
    float var = sq * (1.f / D_) - m * m;
    float rs = rsqrtf(var + 1e-5f);
#pragma unroll
    for (int k = 0; k < 4; k++) {
        int c = tid + k * 256;
        out[(long)r * D_ + c] = __float2half_rn((v[k] - m) * rs * gam[c] + bet[c]);
    }
}

// ------------- combine + LayerNorm3 fused (o fp32, h3 half) -----------------
__global__ __launch_bounds__(256) void cln_k(
    const float* __restrict__ x, const float* __restrict__ gt,
    const float* __restrict__ ao, const float* __restrict__ mc,
    float* __restrict__ o, __half* __restrict__ h3,
    const float* __restrict__ gam, const float* __restrict__ bet, int c0)
{
    int r = blockIdx.x;
    int b = r >> 9, i = r & 511;
    int tid = threadIdx.x;
    float v[4], s = 0.f, sq = 0.f;
#pragma unroll
    for (int k = 0; k < 4; k++) {
        int c = tid + k * 256;
        float xv = x[((long)b * S_ + c0 + i) * D_ + c];
        float gv = gt[(long)r * D_ + c];
        float val = xv + gv * ao[(long)r * D_ + c] + (1.f - gv) * mc[(long)r * D_ + c];
        o[(long)r * D_ + c] = val;
        v[k] = val; s += val; sq += val * val;
    }
    __shared__ float shs[8], shq[8];
#pragma unroll
    for (int w = 16; w; w >>= 1) {
        s  += __shfl_xor_sync(0xffffffffu, s,  w);
        sq += __shfl_xor_sync(0xffffffffu, sq, w);
    }
    if ((tid & 31) == 0) { shs[tid >> 5] = s; shq[tid >> 5] = sq; }
    __syncthreads();
    s = 0.f; sq = 0.f;
#pragma unroll
    for (int i2 = 0; i2 < 8; i2++) { s += shs[i2]; sq += shq[i2]; }
    float m  = s * (1.f / D_);
    float var = sq * (1.f / D_) - m * m;
    float rs = rsqrtf(var + 1e-5f);
#pragma unroll
    for (int k = 0; k < 4; k++) {
        int c = tid + k * 256;
        h3[(long)r * D_ + c] = __float2half_rn((v[k] - m) * rs * gam[c] + bet[c]);
    }
}

// ----------------- row L2 normalize (half, strided) -------------------------
__global__ __launch_bounds__(256) void rownorm_k(__half* __restrict__ km, int ld)
{
    int r = blockIdx.x, tid = threadIdx.x;
    __half* p = km + (long)r * ld;
    float v[4], sq = 0.f;
#pragma unroll
    for (int k = 0; k < 4; k++) {
        int c = tid + k * 256;
        v[k] = __half2float(p[c]); sq += v[k] * v[k];
    }
    __shared__ float shq[8];
#pragma unroll
    for (int o = 16; o; o >>= 1) sq += __shfl_xor_sync(0xffffffffu, sq, o);
    if ((tid & 31) == 0) shq[tid >> 5] = sq;
    __syncthreads();
    sq = 0.f;
#pragma unroll
    for (int i = 0; i < 8; i++) sq += shq[i];
    float rs = rsqrtf(sq + 1e-6f);
#pragma unroll
    for (int k = 0; k < 4; k++) {
        int c = tid + k * 256;
        p[c] = __float2half_rn(v[k] * rs);
    }
}

// ------------------------- softmax (fp32 -> half probs) ---------------------
__global__ __launch_bounds__(256) void softmax_k(
    const float* __restrict__ sc, __half* __restrict__ scp)
{
    const float* row = sc + (long)blockIdx.x * PCP_;
    __half* orow = scp + (long)blockIdx.x * PCP_;
    int tid = threadIdx.x;
    __shared__ float sh[8];
    float mx = -1e30f;
    for (int c = tid; c < PCP_; c += 256) mx = fmaxf(mx, row[c]);
#pragma unroll
    for (int o = 16; o; o >>= 1) mx = fmaxf(mx, __shfl_xor_sync(0xffffffffu, mx, o));
    if ((tid & 31) == 0) sh[tid >> 5] = mx;
    __syncthreads();
    mx = sh[0];
#pragma unroll
    for (int i = 1; i < 8; i++) mx = fmaxf(mx, sh[i]);
    float s = 0.f, ev[3];
    int idx = 0;
    for (int c = tid; c < PCP_; c += 256, idx++) {
        float e = expf(row[c] - mx);
        ev[idx] = e; s += e;
    }
    __syncthreads();
#pragma unroll
    for (int o = 16; o; o >>= 1) s += __shfl_xor_sync(0xffffffffu, s, o);
    if ((tid & 31) == 0) sh[tid >> 5] = s;
    __syncthreads();
    s = 0.f;
#pragma unroll
    for (int i = 0; i < 8; i++) s += sh[i];
    float inv = 1.f / s;
    idx = 0;
    for (int c = tid; c < PCP_; c += 256, idx++)
        orow[c] = __float2half_rn(ev[idx] * inv);
}

// ------------------------------- elementwise --------------------------------
__global__ void zeroinit_k(float* __restrict__ a, float* __restrict__ b,
                           float* __restrict__ tMf, long nd)
{
    long i = (long)blockIdx.x * 256 + threadIdx.x;
    a[i] = 0.f; b[i] = 0.f;
    if (i < nd / 2) tMf[i] = 0.f;
}

__global__ void fillpkv_k(const float* __restrict__ pk, const float* __restrict__ pv,
                          __half* __restrict__ attn)
{
    int idx = blockIdx.x * 256 + threadIdx.x;
    int bh = idx >> 10, rem = idx & 1023;
    int p = rem >> 6, d = rem & 63;
    int h = bh & 15;
    attn[KB_OFF + ((long)bh * PCP_ + p) * DH_ + d] = __float2half_rn(pk[((long)p * H_ + h) * DH_ + d]);
    attn[VB_OFF + ((long)bh * DH_ + d) * PCP_ + p] = __float2half_rn(pv[((long)p * H_ + h) * DH_ + d]);
}

__global__ void cat3_k(const float* __restrict__ a, const float* __restrict__ b,
                       const float* __restrict__ c, float* __restrict__ out,
                       int na, int nb)
{
    int i = blockIdx.x * 256 + threadIdx.x;
    out[i] = (i < na) ? a[i] : (i < na + nb) ? b[i - na] : c[i - na - nb];
}

// ----------- M/S update fused with transposed half tM production ------------
__global__ __launch_bounds__(256) void updtr_k(
    float* __restrict__ M, float* __restrict__ S, const float* __restrict__ grad,
    const float* __restrict__ lr, const float* __restrict__ mom,
    const float* __restrict__ fg, __half* __restrict__ tM)
{
    __shared__ float t[32][33];
    int b = blockIdx.z;
    int r0 = blockIdx.y * 32, c0 = blockIdx.x * 32;
    int tx = threadIdx.x & 31, ty = threadIdx.x >> 5;
    float th = 1.f / (1.f + expf(-lr[0]));
    float et = 1.f / (1.f + expf(-mom[0]));
    float al = 1.f / (1.f + expf(-fg[0]));
#pragma unroll
    for (int i = 0; i < 32; i += 8) {
        long idx = ((long)b * D_ + r0 + ty + i) * D_ + c0 + tx;
        float s = et * S[idx] - th * grad[idx];
        S[idx] = s;
        float m = (1.f - al) * M[idx] + s;
        M[idx] = m;
        t[ty + i][tx] = m;
    }
    __syncthreads();
#pragma unroll
    for (int i = 0; i < 32; i += 8)
        tM[((long)b * D_ + c0 + ty + i) * D_ + r0 + tx] = __float2half_rn(t[tx][ty + i]);
}

__global__ void silu_mul_k(const float* __restrict__ f12, __half* __restrict__ fs)
{
    long idx = (long)blockIdx.x * 256 + threadIdx.x;
    long r = idx >> 12, c = idx & 4095;
    float v = f12[r * 8192 + c];
    fs[r * 4096 + c] = __float2half_rn(v / (1.f + expf(-v)) * f12[r * 8192 + 4096 + c]);
}

// --------------------------------- launch -----------------------------------
extern "C" void kernel_launch(void* const* d_in, const int* in_sizes, int n_in,
                              void* d_out, int out_size)
{
    const float* x     = (const float*)d_in[0];
    const float* g1    = (const float*)d_in[1];
    const float* b1    = (const float*)d_in[2];
    const float* g2    = (const float*)d_in[3];
    const float* b2    = (const float*)d_in[4];
    const float* g3    = (const float*)d_in[5];
    const float* b3    = (const float*)d_in[6];
    const float* Wqm   = (const float*)d_in[7];
    const float* Wkm   = (const float*)d_in[8];
    const float* Wvm   = (const float*)d_in[9];
    const float* lr    = (const float*)d_in[10];
    const float* mom   = (const float*)d_in[11];
    const float* fg    = (const float*)d_in[12];
    const float* Wq    = (const float*)d_in[13];
    const float* bq    = (const float*)d_in[14];
    const float* Wk    = (const float*)d_in[15];
    const float* bk    = (const float*)d_in[16];
    const float* Wv    = (const float*)d_in[17];
    const float* bv    = (const float*)d_in[18];
    const float* Wo    = (const float*)d_in[19];
    const float* bo    = (const float*)d_in[20];
    const float* pk    = (const float*)d_in[21];
    const float* pv    = (const float*)d_in[22];
    const float* Wg    = (const float*)d_in[23];
    const float* bg    = (const float*)d_in[24];
    const float* Wgate = (const float*)d_in[25];
    const float* bgate = (const float*)d_in[26];
    const float* Wup   = (const float*)d_in[27];
    const float* bup   = (const float*)d_in[28];
    const float* Wdown = (const float*)d_in[29];
    const float* bdown = (const float*)d_in[30];
    float* outp = (float*)d_out;

    __half *h1, *qkvm, *mch, *h2, *attn, *scp, *at, *h3, *fs;
    float *mc, *pr, *grad, *Mm, *Sm, *sc, *ao, *gt, *o, *f12;
    __half *wmem, *wqkv, *wo, *wg, *wgu, *wdown;
    __half *tM, *tkm, *tpr;
    float *bqkv, *bgu;
    cudaGetSymbolAddress((void**)&h1, g_h1);
    cudaGetSymbolAddress((void**)&qkvm, g_qkvm);
    cudaGetSymbolAddress((void**)&mc, g_mc);
    cudaGetSymbolAddress((void**)&mch, g_mch);
    cudaGetSymbolAddress((void**)&pr, g_pr);
    cudaGetSymbolAddress((void**)&grad, g_grad);
    cudaGetSymbolAddress((void**)&Mm, g_Mst);
    cudaGetSymbolAddress((void**)&Sm, g_Sst);
    cudaGetSymbolAddress((void**)&h2, g_h2);
    cudaGetSymbolAddress((void**)&attn, g_attn);
    cudaGetSymbolAddress((void**)&sc, g_sc);
    cudaGetSymbolAddress((void**)&scp, g_scp);
    cudaGetSymbolAddress((void**)&at, g_at);
    cudaGetSymbolAddress((void**)&ao, g_ao);
    cudaGetSymbolAddress((void**)&gt, g_gt);
    cudaGetSymbolAddress((void**)&o,  g_o);
    cudaGetSymbolAddress((void**)&h3, g_h3);
    cudaGetSymbolAddress((void**)&f12, g_f12);
    cudaGetSymbolAddress((void**)&fs, g_fs);
    cudaGetSymbolAddress((void**)&wmem, w_mem);
    cudaGetSymbolAddress((void**)&wqkv, w_qkv);
    cudaGetSymbolAddress((void**)&wo,  w_o);
    cudaGetSymbolAddress((void**)&wg,  w_g);
    cudaGetSymbolAddress((void**)&wgu, w_gu);
    cudaGetSymbolAddress((void**)&wdown, w_down);
    cudaGetSymbolAddress((void**)&tM,  t_M);
    cudaGetSymbolAddress((void**)&tkm, t_km);
    cudaGetSymbolAddress((void**)&tpr, t_pr);
    cudaGetSymbolAddress((void**)&bqkv, b_qkv);
    cudaGetSymbolAddress((void**)&bgu,  b_gu);

    cudaFuncSetAttribute(hmma_k<0>,  cudaFuncAttributeMaxDynamicSharedMemorySize, TM_SMEM);
    cudaFuncSetAttribute(hmma_k<1>,  cudaFuncAttributeMaxDynamicSharedMemorySize, TM_SMEM);
    cudaFuncSetAttribute(hmma_k<2>,  cudaFuncAttributeMaxDynamicSharedMemorySize, TM_SMEM);
    cudaFuncSetAttribute(hmma_k<4>,  cudaFuncAttributeMaxDynamicSharedMemorySize, TM_SMEM);
    cudaFuncSetAttribute(hmma_k<5>,  cudaFuncAttributeMaxDynamicSharedMemorySize, TM_SMEM);
    cudaFuncSetAttribute(hmma_k<9>,  cudaFuncAttributeMaxDynamicSharedMemorySize, TM_SMEM);
    cudaFuncSetAttribute(hmma_k<10>, cudaFuncAttributeMaxDynamicSharedMemorySize, TM_SMEM);
    cudaFuncSetAttribute(hmma_k<11>, cudaFuncAttributeMaxDynamicSharedMemorySize, TM_SMEM);
    cudaFuncSetAttribute(attn_sc_k, cudaFuncAttributeMaxDynamicSharedMemorySize, SC_SMEM);
    cudaFuncSetAttribute(attn_av_k, cudaFuncAttributeMaxDynamicSharedMemorySize, AV_SMEM);

    const long ND   = (long)B_ * D_ * D_;
    const long NBF  = (long)BC_ * FF_;
    const long sQK  = (long)C_ * 3 * D_;
    const long sDD  = (long)D_ * D_;
    const long sDC  = (long)D_ * C_;
    const long sCD  = (long)C_ * D_;

    zeroinit_k<<<(unsigned)(ND / 256), 256>>>(Mm, Sm, (float*)tM, ND);
    fillpkv_k<<<256, 256>>>(pk, pv, attn);
    cat3_k<<<12, 256>>>(bq, bk, bv, bqkv, D_, D_);
    cat3_k<<<32, 256>>>(bgate, bup, bup, bgu, FF_, FF_);

    dim3 t256(256);
    tconvfh_k<<<dim3(D_/32,  D_/32, 1), t256>>>(Wqm,   wmem,               D_,  D_,  0, 0);
    tconvfh_k<<<dim3(D_/32,  D_/32, 1), t256>>>(Wkm,   wmem + sDD,         D_,  D_,  0, 0);
    tconvfh_k<<<dim3(D_/32,  D_/32, 1), t256>>>(Wvm,   wmem + 2 * sDD,     D_,  D_,  0, 0);
    tconvfh_k<<<dim3(D_/32,  D_/32, 1), t256>>>(Wq,    wqkv,               D_,  D_,  0, 0);
    tconvfh_k<<<dim3(D_/32,  D_/32, 1), t256>>>(Wk,    wqkv + sDD,         D_,  D_,  0, 0);
    tconvfh_k<<<dim3(D_/32,  D_/32, 1), t256>>>(Wv,    wqkv + 2 * sDD,     D_,  D_,  0, 0);
    tconvfh_k<<<dim3(D_/32,  D_/32, 1), t256>>>(Wo,    wo,                 D_,  D_,  0, 0);
    tconvfh_k<<<dim3(D_/32,  D_/32, 1), t256>>>(Wg,    wg,                 D_,  D_,  0, 0);
    tconvfh_k<<<dim3(FF_/32, D_/32, 1), t256>>>(Wgate, wgu,                D_,  FF_, 0, 0);
    tconvfh_k<<<dim3(FF_/32, D_/32, 1), t256>>>(Wup,   wgu + (long)FF_*D_, D_,  FF_, 0, 0);
    tconvfh_k<<<dim3(D_/32, FF_/32, 1), t256>>>(Wdown, wdown,              FF_, D_,  0, 0);

    for (int t = 0; t < NC_; t++) {
        int c0 = t * C_;
        // --- neural memory ---
        ln_k<0><<<BC_, 256>>>(x, nullptr, g1, b1, h1, c0);
        hmma_k<9><<<dim3(24,16), 256, TM_SMEM>>>(h1, wmem, (float*)qkvm, nullptr, nullptr,
            3*D_, D_, D_, 0, 0, 0, 0, 1.f, 0);
        rownorm_k<<<BC_, 256>>>(qkvm + D_, 3*D_);
        hmma_k<11><<<dim3(8,4,B_), 256, TM_SMEM>>>(qkvm, tM, mc, nullptr, mch,
            D_, D_, 3*D_, 0, sQK, sDD, sCD, 1.f, 0);
        hmma_k<4><<<dim3(8,4,B_), 256, TM_SMEM>>>(qkvm + D_, tM, pr, nullptr, qkvm + 2*D_,
            D_, D_, 3*D_, 3*D_, sQK, sDD, sCD, 1.f, 0);
        tconvhh_k<<<dim3(D_/32, C_/32, B_), t256>>>(qkvm + D_, tkm, C_, 3*D_, sQK, sDC);
        tconvfh_k<<<dim3(D_/32, C_/32, B_), t256>>>(pr, tpr, C_, D_, sCD, sDC);
        hmma_k<0><<<dim3(8,8,B_), 256, TM_SMEM>>>(tkm, tpr, grad, nullptr, nullptr,
            D_, C_, C_, 0, sDC, sDC, sDD, 1.f / C_, 0);
        updtr_k<<<dim3(32,32,B_), 256>>>(Mm, Sm, grad, lr, mom, fg, tM);

        // --- attention with persistent tokens ---
        ln_k<1><<<BC_, 256>>>(x, mc, g2, b2, h2, c0);
        hmma_k<10><<<dim3(24,16), 256, TM_SMEM>>>(h2, wqkv, (float*)attn, bqkv, nullptr,
            0, D_, D_, 0, 0, 0, 0, 1.f, 0);
        attn_sc_k<<<dim3(PCP_/128, C_/128, BH_), 256, SC_SMEM>>>(attn, attn + KB_OFF, sc);
        softmax_k<<<BH_ * C_, 256>>>(sc, scp);
        attn_av_k<<<dim3(C_/128, BH_), 256, AV_SMEM>>>(scp, attn + VB_OFF, at);
        hmma_k<1><<<dim3(8,16), 256, TM_SMEM>>>(at, wo, ao, bo, nullptr,
            D_, D_, D_, 0, 0, 0, 0, 1.f, 0);
        hmma_k<2><<<dim3(8,16), 256, TM_SMEM>>>(mch, wg, gt, bg, nullptr,
            D_, D_, D_, 0, 0, 0, 0, 1.f, 0);
        cln_k<<<BC_, 256>>>(x, gt, ao, mc, o, h3, g3, b3, c0);

        // --- gated FFN ---
        hmma_k<1><<<dim3(64,16), 256, TM_SMEM>>>(h3, wgu, f12, bgu, nullptr,
            2*FF_, D_, D_, 0, 0, 0, 0, 1.f, 0);
        silu_mul_k<<<(unsigned)(NBF / 256), 256>>>(f12, fs);
        hmma_k<5><<<dim3(8,16), 256, TM_SMEM>>>(fs, wdown, o, bdown, outp,
            D_, FF_, FF_, 0, 0, 0, 0, 1.f, c0);
    }
}